// round 4
// baseline (speedup 1.0000x reference)
#include <cuda_runtime.h>
#include <cstdint>
#include <cstddef>

#define B_    2
#define S_    2048
#define D_    4096
#define H_    32
#define KVH_  8
#define DH_   128
#define KVD_  (KVH_*DH_)          // 1024
#define QKVN  (D_ + 2*KVD_)       // 6144
#define EPS_  1e-6f
#define SCALING_ 0.08838834764831845f  // 128^-0.5

// ---------------- scratch (device globals; no runtime allocation) ----------------
__device__ float g_qkv[(size_t)B_*S_*QKVN];        // 4096 x 6144
__device__ float g_q[(size_t)B_*H_*S_*DH_];        // (b,h,s,d)
__device__ float g_k[(size_t)B_*KVH_*S_*DH_];
__device__ float g_v[(size_t)B_*KVH_*S_*DH_];
__device__ float g_attn[(size_t)B_*S_*H_*DH_];     // (b,s, h*dh)

// ---------------- SGEMM: C[M,N] = A[M,K] @ B[K,N], row-major, 128x128x8 ----------------
__global__ __launch_bounds__(256) void sgemm128(const float* __restrict__ A,
                                                const float* __restrict__ B,
                                                float* __restrict__ C,
                                                int M, int N, int K) {
    __shared__ float As[8][128];
    __shared__ float Bs[8][128];
    const int tid = threadIdx.x;
    const int tx = tid & 15;      // 0..15 -> N
    const int ty = tid >> 4;      // 0..15 -> M
    const int row0 = blockIdx.y * 128;
    const int col0 = blockIdx.x * 128;

    float acc[8][8];
    #pragma unroll
    for (int m = 0; m < 8; m++)
        #pragma unroll
        for (int n = 0; n < 8; n++) acc[m][n] = 0.f;

    const int ar = tid >> 1;           // 0..127
    const int ac = (tid & 1) * 4;      // 0 or 4
    const int br = tid >> 5;           // 0..7
    const int bc = (tid & 31) * 4;     // 0..124

    for (int k0 = 0; k0 < K; k0 += 8) {
        float4 av = *(const float4*)(A + (size_t)(row0 + ar) * K + k0 + ac);
        As[ac + 0][ar] = av.x; As[ac + 1][ar] = av.y;
        As[ac + 2][ar] = av.z; As[ac + 3][ar] = av.w;
        float4 bv = *(const float4*)(B + (size_t)(k0 + br) * N + col0 + bc);
        *(float4*)&Bs[br][bc] = bv;
        __syncthreads();

        #pragma unroll
        for (int kk = 0; kk < 8; kk++) {
            float4 a0 = *(const float4*)&As[kk][ty * 8];
            float4 a1 = *(const float4*)&As[kk][ty * 8 + 4];
            float4 b0 = *(const float4*)&Bs[kk][tx * 8];
            float4 b1 = *(const float4*)&Bs[kk][tx * 8 + 4];
            float a[8] = {a0.x,a0.y,a0.z,a0.w,a1.x,a1.y,a1.z,a1.w};
            float b[8] = {b0.x,b0.y,b0.z,b0.w,b1.x,b1.y,b1.z,b1.w};
            #pragma unroll
            for (int m = 0; m < 8; m++)
                #pragma unroll
                for (int n = 0; n < 8; n++) acc[m][n] += a[m] * b[n];
        }
        __syncthreads();
    }

    #pragma unroll
    for (int m = 0; m < 8; m++) {
        float* cp = C + (size_t)(row0 + ty * 8 + m) * N + col0 + tx * 8;
        *(float4*)(cp    ) = make_float4(acc[m][0], acc[m][1], acc[m][2], acc[m][3]);
        *(float4*)(cp + 4) = make_float4(acc[m][4], acc[m][5], acc[m][6], acc[m][7]);
    }
}

// ---------------- RMSNorm + RoPE + scatter to (b,h,s,d) ----------------
__global__ __launch_bounds__(256) void norm_rope_kernel(const float* __restrict__ q_scale,
                                                        const float* __restrict__ k_scale,
                                                        const float* __restrict__ cosc,
                                                        const float* __restrict__ sinc) {
    const int bs = blockIdx.x;           // 0..B*S-1
    const int b = bs / S_;
    const int s = bs % S_;
    const float* row = g_qkv + (size_t)bs * QKVN;
    const int tid = threadIdx.x;
    __shared__ float red[256];
    __shared__ float s_qinv, s_kinv;

    // q rms over D_=4096
    float ss = 0.f;
    for (int i = tid; i < D_; i += 256) { float v = row[i]; ss += v * v; }
    red[tid] = ss; __syncthreads();
    for (int st = 128; st > 0; st >>= 1) { if (tid < st) red[tid] += red[tid + st]; __syncthreads(); }
    if (tid == 0) s_qinv = rsqrtf(red[0] / (float)D_ + EPS_);
    __syncthreads();

    // k rms over KVD_=1024
    ss = 0.f;
    for (int i = tid; i < KVD_; i += 256) { float v = row[D_ + i]; ss += v * v; }
    red[tid] = ss; __syncthreads();
    for (int st = 128; st > 0; st >>= 1) { if (tid < st) red[tid] += red[tid + st]; __syncthreads(); }
    if (tid == 0) s_kinv = rsqrtf(red[0] / (float)KVD_ + EPS_);
    __syncthreads();

    const float qinv = s_qinv, kinv = s_kinv;
    const float* cs = cosc + (size_t)bs * DH_;
    const float* sn = sinc + (size_t)bs * DH_;

    // q: norm + scale + rope -> g_q (b,h,s,d)
    for (int i = tid; i < D_; i += 256) {
        int h = i >> 7, dd = i & 127;
        float xn = row[i] * qinv * q_scale[i];
        int rj = (dd < 64) ? (i + 64) : (i - 64);
        float xr = row[rj] * qinv * q_scale[rj];
        float rot = (dd < 64) ? -xr : xr;
        g_q[(((size_t)b * H_ + h) * S_ + s) * DH_ + dd] = xn * cs[dd] + rot * sn[dd];
    }
    // k
    for (int i = tid; i < KVD_; i += 256) {
        int h = i >> 7, dd = i & 127;
        float xn = row[D_ + i] * kinv * k_scale[i];
        int rj = (dd < 64) ? (i + 64) : (i - 64);
        float xr = row[D_ + rj] * kinv * k_scale[rj];
        float rot = (dd < 64) ? -xr : xr;
        g_k[(((size_t)b * KVH_ + h) * S_ + s) * DH_ + dd] = xn * cs[dd] + rot * sn[dd];
    }
    // v: plain scatter
    for (int i = tid; i < KVD_; i += 256) {
        int h = i >> 7, dd = i & 127;
        g_v[(((size_t)b * KVH_ + h) * S_ + s) * DH_ + dd] = row[D_ + KVD_ + i];
    }
}

// ---------------- Flash attention (causal), BM=BN=64, 256 threads ----------------
__global__ __launch_bounds__(256) void flash_attn_kernel() {
    const int bh = blockIdx.x;            // 0..B*H-1
    const int b = bh / H_;
    const int h = bh % H_;
    const int kvh = h / (H_ / KVH_);
    const int qb = blockIdx.y;            // 0..S/64-1
    const int tid = threadIdx.x;
    const int tx = tid & 15;              // key cols (4 each)
    const int ty = tid >> 4;              // query rows (4 each)

    __shared__ float sP[64][64];
    __shared__ float red[64][17];
    __shared__ __align__(16) float sU[2 * 64 * 33];      // union: {sQ,sK} chunks OR sV
    float (*sQ)[33] = (float(*)[33])sU;
    float (*sK)[33] = (float(*)[33])(sU + 64 * 33);
    float (*sV)[128] = (float(*)[128])sU;

    const float* Qb = g_q + (((size_t)b * H_ + h) * S_ + (size_t)qb * 64) * DH_;
    const float* Kb = g_k + (((size_t)b * KVH_ + kvh) * S_) * DH_;
    const float* Vb = g_v + (((size_t)b * KVH_ + kvh) * S_) * DH_;

    float oacc[4][8];
    float mrow[4], lrow[4];
    #pragma unroll
    for (int m = 0; m < 4; m++) {
        mrow[m] = -1e30f; lrow[m] = 0.f;
        #pragma unroll
        for (int n = 0; n < 8; n++) oacc[m][n] = 0.f;
    }

    for (int jt = 0; jt <= qb; jt++) {
        float sacc[4][4];
        #pragma unroll
        for (int m = 0; m < 4; m++)
            #pragma unroll
            for (int n = 0; n < 4; n++) sacc[m][n] = 0.f;

        // ---- scores: Q(64x128) @ K^T, streamed in d-chunks of 32 ----
        for (int dc = 0; dc < DH_; dc += 32) {
            #pragma unroll
            for (int j = 0; j < 2; j++) {
                int idx = tid + j * 256;              // 0..511
                int r = idx >> 3, c4 = (idx & 7) << 2;
                float4 qa = *(const float4*)(Qb + (size_t)r * DH_ + dc + c4);
                sQ[r][c4+0]=qa.x; sQ[r][c4+1]=qa.y; sQ[r][c4+2]=qa.z; sQ[r][c4+3]=qa.w;
                float4 ka = *(const float4*)(Kb + ((size_t)jt*64 + r) * DH_ + dc + c4);
                sK[r][c4+0]=ka.x; sK[r][c4+1]=ka.y; sK[r][c4+2]=ka.z; sK[r][c4+3]=ka.w;
            }
            __syncthreads();
            #pragma unroll
            for (int dd = 0; dd < 32; dd++) {
                float a[4], bb[4];
                #pragma unroll
                for (int m = 0; m < 4; m++) a[m] = sQ[ty*4+m][dd];
                #pragma unroll
                for (int n = 0; n < 4; n++) bb[n] = sK[tx*4+n][dd];
                #pragma unroll
                for (int m = 0; m < 4; m++)
                    #pragma unroll
                    for (int n = 0; n < 4; n++) sacc[m][n] += a[m] * bb[n];
            }
            __syncthreads();
        }

        // ---- scale + causal mask ----
        const int qi0 = qb * 64 + ty * 4;
        const int kj0 = jt * 64 + tx * 4;
        #pragma unroll
        for (int m = 0; m < 4; m++)
            #pragma unroll
            for (int n = 0; n < 4; n++) {
                float sv = sacc[m][n] * SCALING_;
                if (kj0 + n > qi0 + m) sv = -1e30f;
                sacc[m][n] = sv;
            }

        // ---- row max across tile ----
        #pragma unroll
        for (int m = 0; m < 4; m++) {
            float v = sacc[m][0];
            v = fmaxf(v, sacc[m][1]); v = fmaxf(v, sacc[m][2]); v = fmaxf(v, sacc[m][3]);
            red[ty*4+m][tx] = v;
        }
        __syncthreads();
        float tmax[4];
        #pragma unroll
        for (int m = 0; m < 4; m++) {
            float v = -1e30f;
            #pragma unroll
            for (int t = 0; t < 16; t++) v = fmaxf(v, red[ty*4+m][t]);
            tmax[m] = v;
        }
        __syncthreads();

        // ---- online softmax: p, correction, partial sums ----
        #pragma unroll
        for (int m = 0; m < 4; m++) {
            float mn = fmaxf(mrow[m], tmax[m]);
            float corr = __expf(mrow[m] - mn);
            mrow[m] = mn;
            lrow[m] *= corr;
            #pragma unroll
            for (int n = 0; n < 8; n++) oacc[m][n] *= corr;
            float s = 0.f;
            #pragma unroll
            for (int n = 0; n < 4; n++) {
                float p = __expf(sacc[m][n] - mn);
                sP[ty*4+m][tx*4+n] = p;
                s += p;
            }
            red[ty*4+m][tx] = s;
        }
        __syncthreads();
        #pragma unroll
        for (int m = 0; m < 4; m++) {
            float s = 0.f;
            #pragma unroll
            for (int t = 0; t < 16; t++) s += red[ty*4+m][t];
            lrow[m] += s;
        }
        __syncthreads();   // red/sP stable; safe to overwrite sQ/sK with sV

        // ---- O += P @ V, keys streamed in chunks of 32 ----
        for (int cc = 0; cc < 64; cc += 32) {
            #pragma unroll
            for (int j = 0; j < 4; j++) {
                int idx = tid + j * 256;               // 0..1023
                int r = idx >> 5, c4 = (idx & 31) << 2;
                *(float4*)&sV[r][c4] =
                    *(const float4*)(Vb + ((size_t)jt*64 + cc + r) * DH_ + c4);
            }
            __syncthreads();
            #pragma unroll
            for (int c = 0; c < 32; c++) {
                float p[4];
                #pragma unroll
                for (int m = 0; m < 4; m++) p[m] = sP[ty*4+m][cc + c];
                float4 v0 = *(const float4*)&sV[c][tx*8];
                float4 v1 = *(const float4*)&sV[c][tx*8+4];
                #pragma unroll
                for (int m = 0; m < 4; m++) {
                    oacc[m][0] += p[m]*v0.x; oacc[m][1] += p[m]*v0.y;
                    oacc[m][2] += p[m]*v0.z; oacc[m][3] += p[m]*v0.w;
                    oacc[m][4] += p[m]*v1.x; oacc[m][5] += p[m]*v1.y;
                    oacc[m][6] += p[m]*v1.z; oacc[m][7] += p[m]*v1.w;
                }
            }
            __syncthreads();
        }
    }

    // ---- epilogue: normalize, write (b, s, h*128 + d) ----
    #pragma unroll
    for (int m = 0; m < 4; m++) {
        float inv = 1.0f / lrow[m];
        int sg = qb * 64 + ty * 4 + m;
        float* op = g_attn + ((size_t)b * S_ + sg) * (H_ * DH_) + h * DH_ + tx * 8;
        *(float4*)(op    ) = make_float4(oacc[m][0]*inv, oacc[m][1]*inv, oacc[m][2]*inv, oacc[m][3]*inv);
        *(float4*)(op + 4) = make_float4(oacc[m][4]*inv, oacc[m][5]*inv, oacc[m][6]*inv, oacc[m][7]*inv);
    }
}

// ---------------- launch ----------------
extern "C" void kernel_launch(void* const* d_in, const int* in_sizes, int n_in,
                              void* d_out, int out_size) {
    const float* hidden  = (const float*)d_in[0];
    const float* w_qkv   = (const float*)d_in[1];
    const float* w_out   = (const float*)d_in[2];
    const float* q_scale = (const float*)d_in[3];
    const float* k_scale = (const float*)d_in[4];
    const float* cosc    = (const float*)d_in[5];
    const float* sinc    = (const float*)d_in[6];
    // d_in[7] = attention_mask (causal; recomputed analytically)
    float* out = (float*)d_out;

    float *p_qkv, *p_attn;
    cudaGetSymbolAddress((void**)&p_qkv,  g_qkv);
    cudaGetSymbolAddress((void**)&p_attn, g_attn);

    // 1) QKV projection: [4096,4096] @ [4096,6144]
    {
        dim3 grid(QKVN / 128, (B_ * S_) / 128);
        sgemm128<<<grid, 256>>>(hidden, w_qkv, p_qkv, B_ * S_, QKVN, D_);
    }
    // 2) RMSNorm + RoPE + scatter
    norm_rope_kernel<<<B_ * S_, 256>>>(q_scale, k_scale, cosc, sinc);
    // 3) causal flash attention
    {
        dim3 grid(B_ * H_, S_ / 64);
        flash_attn_kernel<<<grid, 256>>>();
    }
    // 4) output projection: [4096,4096] @ [4096,4096]
    {
        dim3 grid(D_ / 128, (B_ * S_) / 128);
        sgemm128<<<grid, 256>>>(p_attn, w_out, out, B_ * S_, D_, D_);
    }
}

// round 7
// speedup vs baseline: 2.1684x; 2.1684x over previous
#include <cuda_runtime.h>
#include <cuda_bf16.h>
#include <cstdint>
#include <cstddef>

#define B_    2
#define S_    2048
#define D_    4096
#define H_    32
#define KVH_  8
#define DH_   128
#define KVD_  (KVH_*DH_)          // 1024
#define QKVN  (D_ + 2*KVD_)       // 6144
#define MROWS (B_*S_)             // 4096
#define EPS_  1e-6f
#define SCALING_ 0.08838834764831845f  // 128^-0.5

// ---------------- scratch (device globals; no runtime allocation) ----------------
__device__ float g_qkv[(size_t)MROWS*QKVN];
__device__ float g_q[(size_t)B_*H_*S_*DH_];
__device__ float g_k[(size_t)B_*KVH_*S_*DH_];
__device__ float g_v[(size_t)B_*KVH_*S_*DH_];
__device__ float g_attn[(size_t)B_*S_*H_*DH_];
__device__ __nv_bfloat16 g_ah[(size_t)MROWS*D_];     // activation hi
__device__ __nv_bfloat16 g_al[(size_t)MROWS*D_];     // activation lo
__device__ __nv_bfloat16 g_wth[(size_t)QKVN*D_];     // W^T hi  [N,K]
__device__ __nv_bfloat16 g_wtl[(size_t)QKVN*D_];     // W^T lo  [N,K]

// ---------------- ptx helpers ----------------
__device__ __forceinline__ uint32_t smem_u32(const void* p) {
    uint32_t a;
    asm("{ .reg .u64 t; cvta.to.shared.u64 t, %1; cvt.u32.u64 %0, t; }" : "=r"(a) : "l"(p));
    return a;
}
#define CP_ASYNC16(dst, src) \
    asm volatile("cp.async.cg.shared.global [%0], [%1], 16;" :: "r"(dst), "l"(src))
#define CP_COMMIT() asm volatile("cp.async.commit_group;" ::: "memory")
#define CP_WAIT(n)  asm volatile("cp.async.wait_group %0;" :: "n"(n) : "memory")

__device__ __forceinline__ void ldsm_x4(uint32_t* r, uint32_t addr) {
    asm volatile("ldmatrix.sync.aligned.m8n8.x4.shared.b16 {%0,%1,%2,%3}, [%4];"
        : "=r"(r[0]), "=r"(r[1]), "=r"(r[2]), "=r"(r[3]) : "r"(addr));
}
__device__ __forceinline__ void mma16816(float* c, const uint32_t* a, const uint32_t* b) {
    asm volatile(
        "mma.sync.aligned.m16n8k16.row.col.f32.bf16.bf16.f32 "
        "{%0,%1,%2,%3}, {%4,%5,%6,%7}, {%8,%9}, {%0,%1,%2,%3};"
        : "+f"(c[0]), "+f"(c[1]), "+f"(c[2]), "+f"(c[3])
        : "r"(a[0]), "r"(a[1]), "r"(a[2]), "r"(a[3]), "r"(b[0]), "r"(b[1]));
}

// swizzled byte offset within a 64B-row tile: 4 chunks of 16B per row
__device__ __forceinline__ uint32_t swz(int row, int chunk) {
    return (uint32_t)row * 64u + (uint32_t)((chunk ^ ((row >> 1) & 3)) * 16);
}

// ---------------- elementwise split fp32 -> (hi,lo) bf16 ----------------
__global__ __launch_bounds__(256) void split_bf16(const float* __restrict__ x,
                                                  __nv_bfloat16* __restrict__ hi,
                                                  __nv_bfloat16* __restrict__ lo) {
    size_t i = ((size_t)blockIdx.x * 256 + threadIdx.x) * 4;
    float4 v = *(const float4*)(x + i);
    __nv_bfloat16 h0 = __float2bfloat16(v.x), h1 = __float2bfloat16(v.y);
    __nv_bfloat16 h2 = __float2bfloat16(v.z), h3 = __float2bfloat16(v.w);
    __nv_bfloat162 hh0; hh0.x = h0; hh0.y = h1;
    __nv_bfloat162 hh1; hh1.x = h2; hh1.y = h3;
    __nv_bfloat162 ll0, ll1;
    ll0.x = __float2bfloat16(v.x - __bfloat162float(h0));
    ll0.y = __float2bfloat16(v.y - __bfloat162float(h1));
    ll1.x = __float2bfloat16(v.z - __bfloat162float(h2));
    ll1.y = __float2bfloat16(v.w - __bfloat162float(h3));
    *(__nv_bfloat162*)(hi + i)     = hh0;
    *(__nv_bfloat162*)(hi + i + 2) = hh1;
    *(__nv_bfloat162*)(lo + i)     = ll0;
    *(__nv_bfloat162*)(lo + i + 2) = ll1;
}

// ---------------- transpose + split: W[K,N] -> T[N,K] hi/lo bf16 ----------------
__global__ __launch_bounds__(256) void transpose_split(const float* __restrict__ W,
                                                       __nv_bfloat16* __restrict__ Th,
                                                       __nv_bfloat16* __restrict__ Tl,
                                                       int K, int N) {
    __shared__ float t[32][33];
    const int n0 = blockIdx.x * 32, k0 = blockIdx.y * 32;
    const int tx = threadIdx.x, ty = threadIdx.y;   // 32 x 8
    #pragma unroll
    for (int i = 0; i < 32; i += 8)
        t[ty + i][tx] = W[(size_t)(k0 + ty + i) * N + n0 + tx];
    __syncthreads();
    #pragma unroll
    for (int i = 0; i < 32; i += 8) {
        float v = t[tx][ty + i];                    // W[k0+tx][n0+ty+i]
        __nv_bfloat16 h = __float2bfloat16(v);
        size_t o = (size_t)(n0 + ty + i) * K + k0 + tx;
        Th[o] = h;
        Tl[o] = __float2bfloat16(v - __bfloat162float(h));
    }
}

// ---------------- mma.sync GEMM: C[M,N] = A[M,K] @ T[N,K]^T (split-bf16, 3xMMA) ----------------
// block tile 128x256, BK=32, 256 thr (8 warps 2x4, warp tile 64x64)
#define A_TILE_B 8192                    // 128 rows x 64B
#define B_TILE_B 16384                   // 256 rows x 64B
#define GBUF_B   (2*A_TILE_B + 2*B_TILE_B)   // Ah, Al, Bh, Bl = 48KB
#define GSMEM_SZ (2*GBUF_B + 1024)

__global__ __launch_bounds__(256, 1) void gemm_mma(const __nv_bfloat16* __restrict__ Ah,
                                                   const __nv_bfloat16* __restrict__ Al,
                                                   const __nv_bfloat16* __restrict__ Bh,
                                                   const __nv_bfloat16* __restrict__ Bl,
                                                   float* __restrict__ C, int N, int K) {
    extern __shared__ char dsmem[];
    const int tid  = threadIdx.x;
    const int lane = tid & 31;
    const int wid  = tid >> 5;
    const int wm   = (wid >> 2) * 64;           // warp M offset in tile
    const int wn   = (wid & 3) * 64;            // warp N offset in tile
    const int row0 = blockIdx.y * 128;
    const int col0 = blockIdx.x * 256;

    uint32_t db = smem_u32(dsmem);
    uint32_t sbase = (db + 127u) & ~127u;       // 128B align for bank pattern

    float acc[4][8][4];
    #pragma unroll
    for (int mt = 0; mt < 4; mt++)
        #pragma unroll
        for (int nt = 0; nt < 8; nt++)
            #pragma unroll
            for (int j = 0; j < 4; j++) acc[mt][nt][j] = 0.f;

    const int NK = K / 32;

    // ---- async tile loader ----
    auto load_tiles = [&](int buf, int kt) {
        const uint32_t bb = sbase + (uint32_t)buf * GBUF_B;
        const int k0 = kt * 32;
        #pragma unroll
        for (int i = 0; i < 2; i++) {                 // A: 512 x 16B
            int idx = tid + i * 256;
            int row = idx >> 2, ch = idx & 3;
            uint32_t sw = swz(row, ch);
            size_t g = (size_t)(row0 + row) * K + k0 + ch * 8;
            CP_ASYNC16(bb + sw,            Ah + g);
            CP_ASYNC16(bb + A_TILE_B + sw, Al + g);
        }
        #pragma unroll
        for (int i = 0; i < 4; i++) {                 // B: 1024 x 16B
            int idx = tid + i * 256;
            int row = idx >> 2, ch = idx & 3;
            uint32_t sw = swz(row, ch);
            size_t g = (size_t)(col0 + row) * K + k0 + ch * 8;
            CP_ASYNC16(bb + 2*A_TILE_B + sw,            Bh + g);
            CP_ASYNC16(bb + 2*A_TILE_B + B_TILE_B + sw, Bl + g);
        }
    };

    load_tiles(0, 0);
    CP_COMMIT();

    const int mat = lane >> 3;       // ldmatrix sub-matrix id
    const int wi  = lane & 7;

    for (int kt = 0; kt < NK; kt++) {
        const int buf = kt & 1;
        if (kt + 1 < NK) { load_tiles(buf ^ 1, kt + 1); CP_COMMIT(); }
        if (kt + 1 < NK) CP_WAIT(1); else CP_WAIT(0);
        __syncthreads();

        const uint32_t bb  = sbase + (uint32_t)buf * GBUF_B;
        const uint32_t aH = bb, aL = bb + A_TILE_B;
        const uint32_t bH = bb + 2*A_TILE_B, bL = bH + B_TILE_B;

        #pragma unroll
        for (int kh = 0; kh < 2; kh++) {
            uint32_t ah[4][4], al[4][4], bh[4][4], bl[4][4];
            // A fragments: mat0: rows 0-7 k0-7 | mat1: rows 8-15 k0-7 | mat2/3: k8-15
            #pragma unroll
            for (int mt = 0; mt < 4; mt++) {
                int row = wm + mt * 16 + wi + (mat & 1) * 8;
                int ch  = kh * 2 + (mat >> 1);
                uint32_t sw = swz(row, ch);
                ldsm_x4(ah[mt], aH + sw);
                ldsm_x4(al[mt], aL + sw);
            }
            // B fragments: mat0: n0-7 k0-7 | mat1: n0-7 k8-15 | mat2/3: n8-15
            #pragma unroll
            for (int np = 0; np < 4; np++) {
                int row = wn + np * 16 + wi + (mat >> 1) * 8;
                int ch  = kh * 2 + (mat & 1);
                uint32_t sw = swz(row, ch);
                ldsm_x4(bh[np], bH + sw);
                ldsm_x4(bl[np], bL + sw);
            }
            #pragma unroll
            for (int mt = 0; mt < 4; mt++)
                #pragma unroll
                for (int np = 0; np < 4; np++)
                    #pragma unroll
                    for (int s = 0; s < 2; s++) {
                        float* a = acc[mt][np * 2 + s];
                        mma16816(a, ah[mt], &bh[np][s * 2]);
                        mma16816(a, ah[mt], &bl[np][s * 2]);
                        mma16816(a, al[mt], &bh[np][s * 2]);
                    }
        }
        __syncthreads();
    }

    // ---- epilogue: fp32 accumulators -> C ----
    #pragma unroll
    for (int mt = 0; mt < 4; mt++)
        #pragma unroll
        for (int nt = 0; nt < 8; nt++) {
            int m = row0 + wm + mt * 16 + (lane >> 2);
            int n = col0 + wn + nt * 8 + (lane & 3) * 2;
            float* a = acc[mt][nt];
            *(float2*)(C + (size_t)m * N + n)       = make_float2(a[0], a[1]);
            *(float2*)(C + (size_t)(m + 8) * N + n) = make_float2(a[2], a[3]);
        }
}

// ---------------- RMSNorm + RoPE + scatter to (b,h,s,d) ----------------
__global__ __launch_bounds__(256) void norm_rope_kernel(const float* __restrict__ q_scale,
                                                        const float* __restrict__ k_scale,
                                                        const float* __restrict__ cosc,
                                                        const float* __restrict__ sinc) {
    const int bs = blockIdx.x;
    const int b = bs / S_;
    const int s = bs % S_;
    const float* row = g_qkv + (size_t)bs * QKVN;
    const int tid = threadIdx.x;
    __shared__ float red[256];
    __shared__ float s_qinv, s_kinv;

    float ss = 0.f;
    for (int i = tid; i < D_; i += 256) { float v = row[i]; ss += v * v; }
    red[tid] = ss; __syncthreads();
    for (int st = 128; st > 0; st >>= 1) { if (tid < st) red[tid] += red[tid + st]; __syncthreads(); }
    if (tid == 0) s_qinv = rsqrtf(red[0] / (float)D_ + EPS_);
    __syncthreads();

    ss = 0.f;
    for (int i = tid; i < KVD_; i += 256) { float v = row[D_ + i]; ss += v * v; }
    red[tid] = ss; __syncthreads();
    for (int st = 128; st > 0; st >>= 1) { if (tid < st) red[tid] += red[tid + st]; __syncthreads(); }
    if (tid == 0) s_kinv = rsqrtf(red[0] / (float)KVD_ + EPS_);
    __syncthreads();

    const float qinv = s_qinv, kinv = s_kinv;
    const float* cs = cosc + (size_t)bs * DH_;
    const float* sn = sinc + (size_t)bs * DH_;

    for (int i = tid; i < D_; i += 256) {
        int h = i >> 7, dd = i & 127;
        float xn = row[i] * qinv * q_scale[i];
        int rj = (dd < 64) ? (i + 64) : (i - 64);
        float xr = row[rj] * qinv * q_scale[rj];
        float rot = (dd < 64) ? -xr : xr;
        g_q[(((size_t)b * H_ + h) * S_ + s) * DH_ + dd] = xn * cs[dd] + rot * sn[dd];
    }
    for (int i = tid; i < KVD_; i += 256) {
        int h = i >> 7, dd = i & 127;
        float xn = row[D_ + i] * kinv * k_scale[i];
        int rj = (dd < 64) ? (i + 64) : (i - 64);
        float xr = row[D_ + rj] * kinv * k_scale[rj];
        float rot = (dd < 64) ? -xr : xr;
        g_k[(((size_t)b * KVH_ + h) * S_ + s) * DH_ + dd] = xn * cs[dd] + rot * sn[dd];
    }
    for (int i = tid; i < KVD_; i += 256) {
        int h = i >> 7, dd = i & 127;
        g_v[(((size_t)b * KVH_ + h) * S_ + s) * DH_ + dd] = row[D_ + KVD_ + i];
    }
}

// ---------------- Flash attention (causal), BM=BN=64, 256 threads ----------------
__global__ __launch_bounds__(256) void flash_attn_kernel() {
    const int bh = blockIdx.x;
    const int b = bh / H_;
    const int h = bh % H_;
    const int kvh = h / (H_ / KVH_);
    const int qb = blockIdx.y;
    const int tid = threadIdx.x;
    const int tx = tid & 15;
    const int ty = tid >> 4;

    __shared__ float sP[64][64];
    __shared__ float red[64][17];
    __shared__ __align__(16) float sU[2 * 64 * 33];
    float (*sQ)[33] = (float(*)[33])sU;
    float (*sK)[33] = (float(*)[33])(sU + 64 * 33);
    float (*sV)[128] = (float(*)[128])sU;

    const float* Qb = g_q + (((size_t)b * H_ + h) * S_ + (size_t)qb * 64) * DH_;
    const float* Kb = g_k + (((size_t)b * KVH_ + kvh) * S_) * DH_;
    const float* Vb = g_v + (((size_t)b * KVH_ + kvh) * S_) * DH_;

    float oacc[4][8];
    float mrow[4], lrow[4];
    #pragma unroll
    for (int m = 0; m < 4; m++) {
        mrow[m] = -1e30f; lrow[m] = 0.f;
        #pragma unroll
        for (int n = 0; n < 8; n++) oacc[m][n] = 0.f;
    }

    for (int jt = 0; jt <= qb; jt++) {
        float sacc[4][4];
        #pragma unroll
        for (int m = 0; m < 4; m++)
            #pragma unroll
            for (int n = 0; n < 4; n++) sacc[m][n] = 0.f;

        for (int dc = 0; dc < DH_; dc += 32) {
            #pragma unroll
            for (int j = 0; j < 2; j++) {
                int idx = tid + j * 256;
                int rr = idx >> 3, c4 = (idx & 7) << 2;
                float4 qa = *(const float4*)(Qb + (size_t)rr * DH_ + dc + c4);
                sQ[rr][c4+0]=qa.x; sQ[rr][c4+1]=qa.y; sQ[rr][c4+2]=qa.z; sQ[rr][c4+3]=qa.w;
                float4 ka = *(const float4*)(Kb + ((size_t)jt*64 + rr) * DH_ + dc + c4);
                sK[rr][c4+0]=ka.x; sK[rr][c4+1]=ka.y; sK[rr][c4+2]=ka.z; sK[rr][c4+3]=ka.w;
            }
            __syncthreads();
            #pragma unroll
            for (int dd = 0; dd < 32; dd++) {
                float a[4], bb[4];
                #pragma unroll
                for (int m = 0; m < 4; m++) a[m] = sQ[ty*4+m][dd];
                #pragma unroll
                for (int n = 0; n < 4; n++) bb[n] = sK[tx*4+n][dd];
                #pragma unroll
                for (int m = 0; m < 4; m++)
                    #pragma unroll
                    for (int n = 0; n < 4; n++) sacc[m][n] += a[m] * bb[n];
            }
            __syncthreads();
        }

        const int qi0 = qb * 64 + ty * 4;
        const int kj0 = jt * 64 + tx * 4;
        #pragma unroll
        for (int m = 0; m < 4; m++)
            #pragma unroll
            for (int n = 0; n < 4; n++) {
                float sv = sacc[m][n] * SCALING_;
                if (kj0 + n > qi0 + m) sv = -1e30f;
                sacc[m][n] = sv;
            }

        #pragma unroll
        for (int m = 0; m < 4; m++) {
            float v = sacc[m][0];
            v = fmaxf(v, sacc[m][1]); v = fmaxf(v, sacc[m][2]); v = fmaxf(v, sacc[m][3]);
            red[ty*4+m][tx] = v;
        }
        __syncthreads();
        float tmax[4];
        #pragma unroll
        for (int m = 0; m < 4; m++) {
            float v = -1e30f;
            #pragma unroll
            for (int t = 0; t < 16; t++) v = fmaxf(v, red[ty*4+m][t]);
            tmax[m] = v;
        }
        __syncthreads();

        #pragma unroll
        for (int m = 0; m < 4; m++) {
            float mn = fmaxf(mrow[m], tmax[m]);
            float corr = __expf(mrow[m] - mn);
            mrow[m] = mn;
            lrow[m] *= corr;
            #pragma unroll
            for (int n = 0; n < 8; n++) oacc[m][n] *= corr;
            float s = 0.f;
            #pragma unroll
            for (int n = 0; n < 4; n++) {
                float p = __expf(sacc[m][n] - mn);
                sP[ty*4+m][tx*4+n] = p;
                s += p;
            }
            red[ty*4+m][tx] = s;
        }
        __syncthreads();
        #pragma unroll
        for (int m = 0; m < 4; m++) {
            float s = 0.f;
            #pragma unroll
            for (int t = 0; t < 16; t++) s += red[ty*4+m][t];
            lrow[m] += s;
        }
        __syncthreads();

        for (int cc = 0; cc < 64; cc += 32) {
            #pragma unroll
            for (int j = 0; j < 4; j++) {
                int idx = tid + j * 256;
                int rr = idx >> 5, c4 = (idx & 31) << 2;
                *(float4*)&sV[rr][c4] =
                    *(const float4*)(Vb + ((size_t)jt*64 + cc + rr) * DH_ + c4);
            }
            __syncthreads();
            #pragma unroll
            for (int c = 0; c < 32; c++) {
                float p[4];
                #pragma unroll
                for (int m = 0; m < 4; m++) p[m] = sP[ty*4+m][cc + c];
                float4 v0 = *(const float4*)&sV[c][tx*8];
                float4 v1 = *(const float4*)&sV[c][tx*8+4];
                #pragma unroll
                for (int m = 0; m < 4; m++) {
                    oacc[m][0] += p[m]*v0.x; oacc[m][1] += p[m]*v0.y;
                    oacc[m][2] += p[m]*v0.z; oacc[m][3] += p[m]*v0.w;
                    oacc[m][4] += p[m]*v1.x; oacc[m][5] += p[m]*v1.y;
                    oacc[m][6] += p[m]*v1.z; oacc[m][7] += p[m]*v1.w;
                }
            }
            __syncthreads();
        }
    }

    #pragma unroll
    for (int m = 0; m < 4; m++) {
        float inv = 1.0f / lrow[m];
        int sg = qb * 64 + ty * 4 + m;
        float* op = g_attn + ((size_t)b * S_ + sg) * (H_ * DH_) + h * DH_ + tx * 8;
        *(float4*)(op    ) = make_float4(oacc[m][0]*inv, oacc[m][1]*inv, oacc[m][2]*inv, oacc[m][3]*inv);
        *(float4*)(op + 4) = make_float4(oacc[m][4]*inv, oacc[m][5]*inv, oacc[m][6]*inv, oacc[m][7]*inv);
    }
}

// ---------------- launch ----------------
extern "C" void kernel_launch(void* const* d_in, const int* in_sizes, int n_in,
                              void* d_out, int out_size) {
    const float* hidden  = (const float*)d_in[0];
    const float* w_qkv   = (const float*)d_in[1];
    const float* w_out   = (const float*)d_in[2];
    const float* q_scale = (const float*)d_in[3];
    const float* k_scale = (const float*)d_in[4];
    const float* cosc    = (const float*)d_in[5];
    const float* sinc    = (const float*)d_in[6];
    float* out = (float*)d_out;

    float *p_qkv, *p_attn;
    __nv_bfloat16 *p_ah, *p_al, *p_wth, *p_wtl;
    cudaGetSymbolAddress((void**)&p_qkv,  g_qkv);
    cudaGetSymbolAddress((void**)&p_attn, g_attn);
    cudaGetSymbolAddress((void**)&p_ah,   g_ah);
    cudaGetSymbolAddress((void**)&p_al,   g_al);
    cudaGetSymbolAddress((void**)&p_wth,  g_wth);
    cudaGetSymbolAddress((void**)&p_wtl,  g_wtl);

    cudaFuncSetAttribute(gemm_mma, cudaFuncAttributeMaxDynamicSharedMemorySize, GSMEM_SZ);

    // 1) split hidden -> bf16 hi/lo ; transpose+split w_qkv -> [QKVN, D]
    split_bf16<<<(MROWS * (size_t)D_) / (256 * 4), 256>>>(hidden, p_ah, p_al);
    {
        dim3 g(QKVN / 32, D_ / 32);
        transpose_split<<<g, dim3(32, 8)>>>(w_qkv, p_wth, p_wtl, D_, QKVN);
    }
    // 2) QKV projection via mma.sync (HMMA)
    {
        dim3 g(QKVN / 256, MROWS / 128);
        gemm_mma<<<g, 256, GSMEM_SZ>>>(p_ah, p_al, p_wth, p_wtl, p_qkv, QKVN, D_);
    }
    // 3) RMSNorm + RoPE + scatter
    norm_rope_kernel<<<B_ * S_, 256>>>(q_scale, k_scale, cosc, sinc);
    // 4) causal flash attention
    {
        dim3 g(B_ * H_, S_ / 64);
        flash_attn_kernel<<<g, 256>>>();
    }
    // 5) split attn output ; transpose+split w_out
    split_bf16<<<(MROWS * (size_t)D_) / (256 * 4), 256>>>(p_attn, p_ah, p_al);
    {
        dim3 g(D_ / 32, D_ / 32);
        transpose_split<<<g, dim3(32, 8)>>>(w_out, p_wth, p_wtl, D_, D_);
    }
    // 6) output projection via mma.sync
    {
        dim3 g(D_ / 256, MROWS / 128);
        gemm_mma<<<g, 256, GSMEM_SZ>>>(p_ah, p_al, p_wth, p_wtl, out, D_, D_);
    }
}

// round 8
// speedup vs baseline: 3.1925x; 1.4723x over previous
#include <cuda_runtime.h>
#include <cuda_bf16.h>
#include <cstdint>
#include <cstddef>

#define B_    2
#define S_    2048
#define D_    4096
#define H_    32
#define KVH_  8
#define DH_   128
#define KVD_  (KVH_*DH_)          // 1024
#define QKVN  (D_ + 2*KVD_)       // 6144
#define MROWS (B_*S_)             // 4096
#define EPS_  1e-6f
#define SCALING_ 0.08838834764831845f  // 128^-0.5

// ---------------- scratch (device globals; no runtime allocation) ----------------
__device__ float g_qkv[(size_t)MROWS*QKVN];
__device__ __nv_bfloat16 g_qh[(size_t)B_*H_*S_*DH_];
__device__ __nv_bfloat16 g_ql[(size_t)B_*H_*S_*DH_];
__device__ __nv_bfloat16 g_kh[(size_t)B_*KVH_*S_*DH_];
__device__ __nv_bfloat16 g_kl[(size_t)B_*KVH_*S_*DH_];
__device__ __nv_bfloat16 g_vh[(size_t)B_*KVH_*S_*DH_];
__device__ __nv_bfloat16 g_vl[(size_t)B_*KVH_*S_*DH_];
__device__ __nv_bfloat16 g_ah[(size_t)MROWS*D_];     // activation hi
__device__ __nv_bfloat16 g_al[(size_t)MROWS*D_];     // activation lo
__device__ __nv_bfloat16 g_wth[(size_t)QKVN*D_];     // W^T hi  [N,K]
__device__ __nv_bfloat16 g_wtl[(size_t)QKVN*D_];     // W^T lo  [N,K]

// ---------------- ptx helpers ----------------
__device__ __forceinline__ uint32_t smem_u32(const void* p) {
    uint32_t a;
    asm("{ .reg .u64 t; cvta.to.shared.u64 t, %1; cvt.u32.u64 %0, t; }" : "=r"(a) : "l"(p));
    return a;
}
#define CP_ASYNC16(dst, src) \
    asm volatile("cp.async.cg.shared.global [%0], [%1], 16;" :: "r"(dst), "l"(src))
#define CP_COMMIT() asm volatile("cp.async.commit_group;" ::: "memory")
#define CP_WAIT(n)  asm volatile("cp.async.wait_group %0;" :: "n"(n) : "memory")

__device__ __forceinline__ void ldsm_x4(uint32_t* r, uint32_t addr) {
    asm volatile("ldmatrix.sync.aligned.m8n8.x4.shared.b16 {%0,%1,%2,%3}, [%4];"
        : "=r"(r[0]), "=r"(r[1]), "=r"(r[2]), "=r"(r[3]) : "r"(addr));
}
__device__ __forceinline__ void ldsm_x4_t(uint32_t* r, uint32_t addr) {
    asm volatile("ldmatrix.sync.aligned.m8n8.x4.trans.shared.b16 {%0,%1,%2,%3}, [%4];"
        : "=r"(r[0]), "=r"(r[1]), "=r"(r[2]), "=r"(r[3]) : "r"(addr));
}
__device__ __forceinline__ void mma16816(float* c, const uint32_t* a, const uint32_t* b) {
    asm volatile(
        "mma.sync.aligned.m16n8k16.row.col.f32.bf16.bf16.f32 "
        "{%0,%1,%2,%3}, {%4,%5,%6,%7}, {%8,%9}, {%0,%1,%2,%3};"
        : "+f"(c[0]), "+f"(c[1]), "+f"(c[2]), "+f"(c[3])
        : "r"(a[0]), "r"(a[1]), "r"(a[2]), "r"(a[3]), "r"(b[0]), "r"(b[1]));
}

// swizzle for 64B-row tiles (GEMM): 4 chunks of 16B per row
__device__ __forceinline__ uint32_t swz(int row, int chunk) {
    return (uint32_t)row * 64u + (uint32_t)((chunk ^ ((row >> 1) & 3)) * 16);
}
// swizzle for 256B-row tiles (attention, 128 bf16/row): 16 chunks of 16B
__device__ __forceinline__ uint32_t swz256(int row, int chunk) {
    return (uint32_t)row * 256u + (uint32_t)((chunk ^ (row & 7)) * 16);
}
// split fp32 -> packed bf16x2 hi with lo out-param
__device__ __forceinline__ uint32_t packsplit(float a, float b, uint32_t& lo) {
    __nv_bfloat16 ha = __float2bfloat16(a), hb = __float2bfloat16(b);
    __nv_bfloat16 la = __float2bfloat16(a - __bfloat162float(ha));
    __nv_bfloat16 lb = __float2bfloat16(b - __bfloat162float(hb));
    uint16_t uha = *(uint16_t*)&ha, uhb = *(uint16_t*)&hb;
    uint16_t ula = *(uint16_t*)&la, ulb = *(uint16_t*)&lb;
    lo = (uint32_t)ula | ((uint32_t)ulb << 16);
    return (uint32_t)uha | ((uint32_t)uhb << 16);
}
__device__ __forceinline__ void store_split(__nv_bfloat16* hi, __nv_bfloat16* lo,
                                            size_t idx, float v) {
    __nv_bfloat16 h = __float2bfloat16(v);
    hi[idx] = h;
    lo[idx] = __float2bfloat16(v - __bfloat162float(h));
}

// ---------------- elementwise split fp32 -> (hi,lo) bf16 ----------------
__global__ __launch_bounds__(256) void split_bf16(const float* __restrict__ x,
                                                  __nv_bfloat16* __restrict__ hi,
                                                  __nv_bfloat16* __restrict__ lo) {
    size_t i = ((size_t)blockIdx.x * 256 + threadIdx.x) * 4;
    float4 v = *(const float4*)(x + i);
    __nv_bfloat16 h0 = __float2bfloat16(v.x), h1 = __float2bfloat16(v.y);
    __nv_bfloat16 h2 = __float2bfloat16(v.z), h3 = __float2bfloat16(v.w);
    __nv_bfloat162 hh0; hh0.x = h0; hh0.y = h1;
    __nv_bfloat162 hh1; hh1.x = h2; hh1.y = h3;
    __nv_bfloat162 ll0, ll1;
    ll0.x = __float2bfloat16(v.x - __bfloat162float(h0));
    ll0.y = __float2bfloat16(v.y - __bfloat162float(h1));
    ll1.x = __float2bfloat16(v.z - __bfloat162float(h2));
    ll1.y = __float2bfloat16(v.w - __bfloat162float(h3));
    *(__nv_bfloat162*)(hi + i)     = hh0;
    *(__nv_bfloat162*)(hi + i + 2) = hh1;
    *(__nv_bfloat162*)(lo + i)     = ll0;
    *(__nv_bfloat162*)(lo + i + 2) = ll1;
}

// ---------------- transpose + split: W[K,N] -> T[N,K] hi/lo bf16 ----------------
__global__ __launch_bounds__(256) void transpose_split(const float* __restrict__ W,
                                                       __nv_bfloat16* __restrict__ Th,
                                                       __nv_bfloat16* __restrict__ Tl,
                                                       int K, int N) {
    __shared__ float t[32][33];
    const int n0 = blockIdx.x * 32, k0 = blockIdx.y * 32;
    const int tx = threadIdx.x, ty = threadIdx.y;   // 32 x 8
    #pragma unroll
    for (int i = 0; i < 32; i += 8)
        t[ty + i][tx] = W[(size_t)(k0 + ty + i) * N + n0 + tx];
    __syncthreads();
    #pragma unroll
    for (int i = 0; i < 32; i += 8) {
        float v = t[tx][ty + i];
        __nv_bfloat16 h = __float2bfloat16(v);
        size_t o = (size_t)(n0 + ty + i) * K + k0 + tx;
        Th[o] = h;
        Tl[o] = __float2bfloat16(v - __bfloat162float(h));
    }
}

// ---------------- mma.sync GEMM (unchanged from R7, proven) ----------------
#define A_TILE_B 8192
#define B_TILE_B 16384
#define GBUF_B   (2*A_TILE_B + 2*B_TILE_B)
#define GSMEM_SZ (2*GBUF_B + 1024)

__global__ __launch_bounds__(256, 1) void gemm_mma(const __nv_bfloat16* __restrict__ Ah,
                                                   const __nv_bfloat16* __restrict__ Al,
                                                   const __nv_bfloat16* __restrict__ Bh,
                                                   const __nv_bfloat16* __restrict__ Bl,
                                                   float* __restrict__ C, int N, int K) {
    extern __shared__ char dsmem[];
    const int tid  = threadIdx.x;
    const int lane = tid & 31;
    const int wid  = tid >> 5;
    const int wm   = (wid >> 2) * 64;
    const int wn   = (wid & 3) * 64;
    const int row0 = blockIdx.y * 128;
    const int col0 = blockIdx.x * 256;

    uint32_t db = smem_u32(dsmem);
    uint32_t sbase = (db + 127u) & ~127u;

    float acc[4][8][4];
    #pragma unroll
    for (int mt = 0; mt < 4; mt++)
        #pragma unroll
        for (int nt = 0; nt < 8; nt++)
            #pragma unroll
            for (int j = 0; j < 4; j++) acc[mt][nt][j] = 0.f;

    const int NK = K / 32;

    auto load_tiles = [&](int buf, int kt) {
        const uint32_t bb = sbase + (uint32_t)buf * GBUF_B;
        const int k0 = kt * 32;
        #pragma unroll
        for (int i = 0; i < 2; i++) {
            int idx = tid + i * 256;
            int row = idx >> 2, ch = idx & 3;
            uint32_t sw = swz(row, ch);
            size_t g = (size_t)(row0 + row) * K + k0 + ch * 8;
            CP_ASYNC16(bb + sw,            Ah + g);
            CP_ASYNC16(bb + A_TILE_B + sw, Al + g);
        }
        #pragma unroll
        for (int i = 0; i < 4; i++) {
            int idx = tid + i * 256;
            int row = idx >> 2, ch = idx & 3;
            uint32_t sw = swz(row, ch);
            size_t g = (size_t)(col0 + row) * K + k0 + ch * 8;
            CP_ASYNC16(bb + 2*A_TILE_B + sw,            Bh + g);
            CP_ASYNC16(bb + 2*A_TILE_B + B_TILE_B + sw, Bl + g);
        }
    };

    load_tiles(0, 0);
    CP_COMMIT();

    const int mat = lane >> 3;
    const int wi  = lane & 7;

    for (int kt = 0; kt < NK; kt++) {
        const int buf = kt & 1;
        if (kt + 1 < NK) { load_tiles(buf ^ 1, kt + 1); CP_COMMIT(); }
        if (kt + 1 < NK) CP_WAIT(1); else CP_WAIT(0);
        __syncthreads();

        const uint32_t bb  = sbase + (uint32_t)buf * GBUF_B;
        const uint32_t aH = bb, aL = bb + A_TILE_B;
        const uint32_t bH = bb + 2*A_TILE_B, bL = bH + B_TILE_B;

        #pragma unroll
        for (int kh = 0; kh < 2; kh++) {
            uint32_t ah[4][4], al[4][4], bh[4][4], bl[4][4];
            #pragma unroll
            for (int mt = 0; mt < 4; mt++) {
                int row = wm + mt * 16 + wi + (mat & 1) * 8;
                int ch  = kh * 2 + (mat >> 1);
                uint32_t sw = swz(row, ch);
                ldsm_x4(ah[mt], aH + sw);
                ldsm_x4(al[mt], aL + sw);
            }
            #pragma unroll
            for (int np = 0; np < 4; np++) {
                int row = wn + np * 16 + wi + (mat >> 1) * 8;
                int ch  = kh * 2 + (mat & 1);
                uint32_t sw = swz(row, ch);
                ldsm_x4(bh[np], bH + sw);
                ldsm_x4(bl[np], bL + sw);
            }
            #pragma unroll
            for (int mt = 0; mt < 4; mt++)
                #pragma unroll
                for (int np = 0; np < 4; np++)
                    #pragma unroll
                    for (int s = 0; s < 2; s++) {
                        float* a = acc[mt][np * 2 + s];
                        mma16816(a, ah[mt], &bh[np][s * 2]);
                        mma16816(a, ah[mt], &bl[np][s * 2]);
                        mma16816(a, al[mt], &bh[np][s * 2]);
                    }
        }
        __syncthreads();
    }

    #pragma unroll
    for (int mt = 0; mt < 4; mt++)
        #pragma unroll
        for (int nt = 0; nt < 8; nt++) {
            int m = row0 + wm + mt * 16 + (lane >> 2);
            int n = col0 + wn + nt * 8 + (lane & 3) * 2;
            float* a = acc[mt][nt];
            *(float2*)(C + (size_t)m * N + n)       = make_float2(a[0], a[1]);
            *(float2*)(C + (size_t)(m + 8) * N + n) = make_float2(a[2], a[3]);
        }
}

// ---------------- RMSNorm + RoPE + split-bf16 scatter to (b,h,s,d) ----------------
__global__ __launch_bounds__(256) void norm_rope_kernel(const float* __restrict__ q_scale,
                                                        const float* __restrict__ k_scale,
                                                        const float* __restrict__ cosc,
                                                        const float* __restrict__ sinc) {
    const int bs = blockIdx.x;
    const int b = bs / S_;
    const int s = bs % S_;
    const float* row = g_qkv + (size_t)bs * QKVN;
    const int tid = threadIdx.x;
    __shared__ float red[256];
    __shared__ float s_qinv, s_kinv;

    float ss = 0.f;
    for (int i = tid; i < D_; i += 256) { float v = row[i]; ss += v * v; }
    red[tid] = ss; __syncthreads();
    for (int st = 128; st > 0; st >>= 1) { if (tid < st) red[tid] += red[tid + st]; __syncthreads(); }
    if (tid == 0) s_qinv = rsqrtf(red[0] / (float)D_ + EPS_);
    __syncthreads();

    ss = 0.f;
    for (int i = tid; i < KVD_; i += 256) { float v = row[D_ + i]; ss += v * v; }
    red[tid] = ss; __syncthreads();
    for (int st = 128; st > 0; st >>= 1) { if (tid < st) red[tid] += red[tid + st]; __syncthreads(); }
    if (tid == 0) s_kinv = rsqrtf(red[0] / (float)KVD_ + EPS_);
    __syncthreads();

    const float qinv = s_qinv, kinv = s_kinv;
    const float* cs = cosc + (size_t)bs * DH_;
    const float* sn = sinc + (size_t)bs * DH_;

    for (int i = tid; i < D_; i += 256) {
        int h = i >> 7, dd = i & 127;
        float xn = row[i] * qinv * q_scale[i];
        int rj = (dd < 64) ? (i + 64) : (i - 64);
        float xr = row[rj] * qinv * q_scale[rj];
        float rot = (dd < 64) ? -xr : xr;
        size_t o = (((size_t)b * H_ + h) * S_ + s) * DH_ + dd;
        store_split(g_qh, g_ql, o, xn * cs[dd] + rot * sn[dd]);
    }
    for (int i = tid; i < KVD_; i += 256) {
        int h = i >> 7, dd = i & 127;
        float xn = row[D_ + i] * kinv * k_scale[i];
        int rj = (dd < 64) ? (i + 64) : (i - 64);
        float xr = row[D_ + rj] * kinv * k_scale[rj];
        float rot = (dd < 64) ? -xr : xr;
        size_t o = (((size_t)b * KVH_ + h) * S_ + s) * DH_ + dd;
        store_split(g_kh, g_kl, o, xn * cs[dd] + rot * sn[dd]);
    }
    for (int i = tid; i < KVD_; i += 256) {
        int h = i >> 7, dd = i & 127;
        size_t o = (((size_t)b * KVH_ + h) * S_ + s) * DH_ + dd;
        store_split(g_vh, g_vl, o, row[D_ + KVD_ + i]);
    }
}

// ---------------- tensor-core flash attention (causal, split-bf16 3xMMA) ----------------
// BM=64, BN=64, DH=128; 256 threads = 8 warps (4 M x 2 N)
// smem layout (bytes from aligned base):
#define AT_QH   0
#define AT_QL   16384
#define AT_KV   32768          // stage base; stride 65536: KH 0 | KL 16384 | VH 32768 | VL 49152
#define AKV_STG 65536
#define AT_SO   (AT_KV + 2*AKV_STG)      // 163840: fp32 [64][132]
#define SO_STRIDE 132
#define AT_RED  (AT_SO + 64*SO_STRIDE*4) // 197632: red_m [2][64], red_l [2][64]
#define ATT_SMEM (AT_RED + 1024 + 128)

__global__ __launch_bounds__(256, 1) void attn_mma() {
    extern __shared__ char dsmem[];
    const int bh = blockIdx.x;
    const int b = bh / H_;
    const int h = bh % H_;
    const int kvh = h / (H_ / KVH_);
    const int qb = blockIdx.y;
    const int tid = threadIdx.x;
    const int lane = tid & 31;
    const int wid = tid >> 5;
    const int warp_m = wid >> 1;          // 0..3 -> 16 q rows
    const int warp_n = wid & 1;           // 0..1 -> 32 keys / key-slice for PV

    uint32_t db = smem_u32(dsmem);
    uint32_t sbase = (db + 127u) & ~127u;
    float* sO   = (float*)(dsmem + (sbase - db) + AT_SO);
    float* redm = (float*)(dsmem + (sbase - db) + AT_RED);
    float* redl = redm + 128;

    const __nv_bfloat16* QhG = g_qh + (((size_t)b * H_ + h) * S_ + (size_t)qb * 64) * DH_;
    const __nv_bfloat16* QlG = g_ql + (((size_t)b * H_ + h) * S_ + (size_t)qb * 64) * DH_;
    const __nv_bfloat16* KhB = g_kh + ((size_t)b * KVH_ + kvh) * S_ * DH_;
    const __nv_bfloat16* KlB = g_kl + ((size_t)b * KVH_ + kvh) * S_ * DH_;
    const __nv_bfloat16* VhB = g_vh + ((size_t)b * KVH_ + kvh) * S_ * DH_;
    const __nv_bfloat16* VlB = g_vl + ((size_t)b * KVH_ + kvh) * S_ * DH_;

    // ---- load Q (once) ----
    #pragma unroll
    for (int i = 0; i < 4; i++) {
        int idx = tid + i * 256;               // 0..1023
        int row = idx >> 4, ch = idx & 15;
        uint32_t sw = swz256(row, ch);
        size_t g = (size_t)row * DH_ + ch * 8;
        CP_ASYNC16(sbase + AT_QH + sw, QhG + g);
        CP_ASYNC16(sbase + AT_QL + sw, QlG + g);
    }
    auto load_kv = [&](int buf, int jt) {
        uint32_t sb = sbase + AT_KV + (uint32_t)buf * AKV_STG;
        size_t gb = (size_t)jt * 64 * DH_;
        #pragma unroll
        for (int i = 0; i < 4; i++) {
            int idx = tid + i * 256;
            int row = idx >> 4, ch = idx & 15;
            uint32_t sw = swz256(row, ch);
            size_t g = gb + (size_t)row * DH_ + ch * 8;
            CP_ASYNC16(sb +         sw, KhB + g);
            CP_ASYNC16(sb + 16384 + sw, KlB + g);
            CP_ASYNC16(sb + 32768 + sw, VhB + g);
            CP_ASYNC16(sb + 49152 + sw, VlB + g);
        }
    };
    load_kv(0, 0);
    CP_COMMIT();

    float oacc[16][4];
    #pragma unroll
    for (int nt = 0; nt < 16; nt++)
        #pragma unroll
        for (int j = 0; j < 4; j++) oacc[nt][j] = 0.f;
    float m0 = -1e30f, m1 = -1e30f, l0 = 0.f, l1 = 0.f;

    const int gr  = lane >> 2;            // 0..7
    const int rI0 = warp_m * 16 + gr;     // tile-local row (and +8)
    const int nj = qb + 1;

    for (int jt = 0; jt < nj; jt++) {
        const int buf = jt & 1;
        if (jt + 1 < nj) { load_kv(buf ^ 1, jt + 1); CP_COMMIT(); CP_WAIT(1); }
        else             { CP_WAIT(0); }
        __syncthreads();

        const uint32_t sQH = sbase + AT_QH, sQL = sbase + AT_QL;
        const uint32_t kb = sbase + AT_KV + (uint32_t)buf * AKV_STG;
        const uint32_t sKH = kb, sKL = kb + 16384, sVH = kb + 32768, sVL = kb + 49152;

        // ---- scores S = Q K^T (split-bf16 3xMMA) ----
        float sacc[4][4];
        #pragma unroll
        for (int nt = 0; nt < 4; nt++)
            #pragma unroll
            for (int j = 0; j < 4; j++) sacc[nt][j] = 0.f;

        #pragma unroll
        for (int kt = 0; kt < 8; kt++) {
            uint32_t qh4[4], ql4[4], kbh[2][4], kbl[2][4];
            int qrow = warp_m * 16 + (lane & 15);
            int qch  = kt * 2 + (lane >> 4);
            ldsm_x4(qh4, sQH + swz256(qrow, qch));
            ldsm_x4(ql4, sQL + swz256(qrow, qch));
            #pragma unroll
            for (int ng = 0; ng < 2; ng++) {
                int krow = warp_n * 32 + ng * 16 + (lane & 7) + (lane >> 4) * 8;
                int kch  = kt * 2 + ((lane >> 3) & 1);
                ldsm_x4(kbh[ng], sKH + swz256(krow, kch));
                ldsm_x4(kbl[ng], sKL + swz256(krow, kch));
            }
            #pragma unroll
            for (int ng = 0; ng < 2; ng++)
                #pragma unroll
                for (int s = 0; s < 2; s++) {
                    float* a = sacc[ng * 2 + s];
                    mma16816(a, qh4, &kbh[ng][s * 2]);
                    mma16816(a, qh4, &kbl[ng][s * 2]);
                    mma16816(a, ql4, &kbh[ng][s * 2]);
                }
        }

        // ---- scale + causal mask (only diagonal tile) ----
        #pragma unroll
        for (int nt = 0; nt < 4; nt++)
            #pragma unroll
            for (int j = 0; j < 4; j++) sacc[nt][j] *= SCALING_;
        if (jt == qb) {
            int r0g = qb * 64 + rI0;
            #pragma unroll
            for (int nt = 0; nt < 4; nt++) {
                int c = jt * 64 + warp_n * 32 + nt * 8 + (lane & 3) * 2;
                if (c     > r0g)     sacc[nt][0] = -1e30f;
                if (c + 1 > r0g)     sacc[nt][1] = -1e30f;
                if (c     > r0g + 8) sacc[nt][2] = -1e30f;
                if (c + 1 > r0g + 8) sacc[nt][3] = -1e30f;
            }
        }

        // ---- row max (intra-warp shfl, cross-warp via smem) ----
        float pm0 = -1e30f, pm1 = -1e30f;
        #pragma unroll
        for (int nt = 0; nt < 4; nt++) {
            pm0 = fmaxf(pm0, fmaxf(sacc[nt][0], sacc[nt][1]));
            pm1 = fmaxf(pm1, fmaxf(sacc[nt][2], sacc[nt][3]));
        }
        pm0 = fmaxf(pm0, __shfl_xor_sync(0xFFFFFFFFu, pm0, 1));
        pm0 = fmaxf(pm0, __shfl_xor_sync(0xFFFFFFFFu, pm0, 2));
        pm1 = fmaxf(pm1, __shfl_xor_sync(0xFFFFFFFFu, pm1, 1));
        pm1 = fmaxf(pm1, __shfl_xor_sync(0xFFFFFFFFu, pm1, 2));
        if ((lane & 3) == 0) {
            redm[warp_n * 64 + rI0]     = pm0;
            redm[warp_n * 64 + rI0 + 8] = pm1;
        }
        __syncthreads();
        float mt0 = fmaxf(redm[rI0],     redm[64 + rI0]);
        float mt1 = fmaxf(redm[rI0 + 8], redm[64 + rI0 + 8]);

        float mn0 = fmaxf(m0, mt0), mn1 = fmaxf(m1, mt1);
        float c0 = __expf(m0 - mn0), c1 = __expf(m1 - mn1);

        // ---- p = exp(s - m), partial row sums ----
        float ps0 = 0.f, ps1 = 0.f;
        #pragma unroll
        for (int nt = 0; nt < 4; nt++) {
            sacc[nt][0] = __expf(sacc[nt][0] - mn0);
            sacc[nt][1] = __expf(sacc[nt][1] - mn0);
            sacc[nt][2] = __expf(sacc[nt][2] - mn1);
            sacc[nt][3] = __expf(sacc[nt][3] - mn1);
            ps0 += sacc[nt][0] + sacc[nt][1];
            ps1 += sacc[nt][2] + sacc[nt][3];
        }
        ps0 += __shfl_xor_sync(0xFFFFFFFFu, ps0, 1);
        ps0 += __shfl_xor_sync(0xFFFFFFFFu, ps0, 2);
        ps1 += __shfl_xor_sync(0xFFFFFFFFu, ps1, 1);
        ps1 += __shfl_xor_sync(0xFFFFFFFFu, ps1, 2);
        if ((lane & 3) == 0) {
            redl[warp_n * 64 + rI0]     = ps0;
            redl[warp_n * 64 + rI0 + 8] = ps1;
        }
        __syncthreads();
        l0 = l0 * c0 + redl[rI0]     + redl[64 + rI0];
        l1 = l1 * c1 + redl[rI0 + 8] + redl[64 + rI0 + 8];
        m0 = mn0; m1 = mn1;

        // ---- rescale O ----
        #pragma unroll
        for (int nt = 0; nt < 16; nt++) {
            oacc[nt][0] *= c0; oacc[nt][1] *= c0;
            oacc[nt][2] *= c1; oacc[nt][3] *= c1;
        }

        // ---- P (in-register split to A-fragments) ----
        uint32_t pah[2][4], pal[2][4];
        #pragma unroll
        for (int kt = 0; kt < 2; kt++) {
            pah[kt][0] = packsplit(sacc[2*kt][0],   sacc[2*kt][1],   pal[kt][0]);
            pah[kt][1] = packsplit(sacc[2*kt][2],   sacc[2*kt][3],   pal[kt][1]);
            pah[kt][2] = packsplit(sacc[2*kt+1][0], sacc[2*kt+1][1], pal[kt][2]);
            pah[kt][3] = packsplit(sacc[2*kt+1][2], sacc[2*kt+1][3], pal[kt][3]);
        }

        // ---- O += P V (split-bf16 3xMMA); each warp covers its 32-key slice, full d ----
        #pragma unroll
        for (int ndg = 0; ndg < 8; ndg++) {
            #pragma unroll
            for (int kt = 0; kt < 2; kt++) {
                uint32_t vh4[4], vl4[4];
                int vrow = warp_n * 32 + kt * 16 + (lane & 15);
                int vch  = ndg * 2 + (lane >> 4);
                ldsm_x4_t(vh4, sVH + swz256(vrow, vch));
                ldsm_x4_t(vl4, sVL + swz256(vrow, vch));
                #pragma unroll
                for (int hf = 0; hf < 2; hf++) {
                    float* o = oacc[ndg * 2 + hf];
                    mma16816(o, pah[kt], &vh4[hf * 2]);
                    mma16816(o, pah[kt], &vl4[hf * 2]);
                    mma16816(o, pal[kt], &vh4[hf * 2]);
                }
            }
        }
        __syncthreads();   // protect K/V buffer + red arrays for next iter
    }

    // ---- epilogue: cross-warp (key-slice) sum via smem, normalize, split-bf16 out ----
    if (warp_n == 0) {
        #pragma unroll
        for (int nt = 0; nt < 16; nt++) {
            int d = nt * 8 + (lane & 3) * 2;
            *(float2*)&sO[(size_t)rI0 * SO_STRIDE + d]       = make_float2(oacc[nt][0], oacc[nt][1]);
            *(float2*)&sO[(size_t)(rI0 + 8) * SO_STRIDE + d] = make_float2(oacc[nt][2], oacc[nt][3]);
        }
    }
    __syncthreads();
    if (warp_n == 1) {
        float inv0 = 1.0f / l0, inv1 = 1.0f / l1;
        size_t row0g = (size_t)b * S_ + qb * 64 + rI0;
        size_t row1g = row0g + 8;
        #pragma unroll
        for (int nt = 0; nt < 16; nt++) {
            int d = nt * 8 + (lane & 3) * 2;
            float2 t0 = *(float2*)&sO[(size_t)rI0 * SO_STRIDE + d];
            float2 t1 = *(float2*)&sO[(size_t)(rI0 + 8) * SO_STRIDE + d];
            float v00 = (t0.x + oacc[nt][0]) * inv0;
            float v01 = (t0.y + oacc[nt][1]) * inv0;
            float v10 = (t1.x + oacc[nt][2]) * inv1;
            float v11 = (t1.y + oacc[nt][3]) * inv1;
            size_t o0 = row0g * D_ + h * DH_ + d;
            size_t o1 = row1g * D_ + h * DH_ + d;
            uint32_t lo0, lo1;
            uint32_t hi0 = packsplit(v00, v01, lo0);
            uint32_t hi1 = packsplit(v10, v11, lo1);
            *(uint32_t*)(g_ah + o0) = hi0;
            *(uint32_t*)(g_al + o0) = lo0;
            *(uint32_t*)(g_ah + o1) = hi1;
            *(uint32_t*)(g_al + o1) = lo1;
        }
    }
}

// ---------------- launch ----------------
extern "C" void kernel_launch(void* const* d_in, const int* in_sizes, int n_in,
                              void* d_out, int out_size) {
    const float* hidden  = (const float*)d_in[0];
    const float* w_qkv   = (const float*)d_in[1];
    const float* w_out   = (const float*)d_in[2];
    const float* q_scale = (const float*)d_in[3];
    const float* k_scale = (const float*)d_in[4];
    const float* cosc    = (const float*)d_in[5];
    const float* sinc    = (const float*)d_in[6];
    float* out = (float*)d_out;

    float* p_qkv;
    __nv_bfloat16 *p_ah, *p_al, *p_wth, *p_wtl;
    cudaGetSymbolAddress((void**)&p_qkv,  g_qkv);
    cudaGetSymbolAddress((void**)&p_ah,   g_ah);
    cudaGetSymbolAddress((void**)&p_al,   g_al);
    cudaGetSymbolAddress((void**)&p_wth,  g_wth);
    cudaGetSymbolAddress((void**)&p_wtl,  g_wtl);

    cudaFuncSetAttribute(gemm_mma, cudaFuncAttributeMaxDynamicSharedMemorySize, GSMEM_SZ);
    cudaFuncSetAttribute(attn_mma, cudaFuncAttributeMaxDynamicSharedMemorySize, ATT_SMEM);

    // 1) split hidden -> bf16 hi/lo ; transpose+split w_qkv
    split_bf16<<<(MROWS * (size_t)D_) / (256 * 4), 256>>>(hidden, p_ah, p_al);
    {
        dim3 g(QKVN / 32, D_ / 32);
        transpose_split<<<g, dim3(32, 8)>>>(w_qkv, p_wth, p_wtl, D_, QKVN);
    }
    // 2) QKV projection
    {
        dim3 g(QKVN / 256, MROWS / 128);
        gemm_mma<<<g, 256, GSMEM_SZ>>>(p_ah, p_al, p_wth, p_wtl, p_qkv, QKVN, D_);
    }
    // 3) RMSNorm + RoPE -> split-bf16 q/k/v
    norm_rope_kernel<<<B_ * S_, 256>>>(q_scale, k_scale, cosc, sinc);
    // 4) tensor-core flash attention -> writes g_ah/g_al directly
    {
        dim3 g(B_ * H_, S_ / 64);
        attn_mma<<<g, 256, ATT_SMEM>>>();
    }
    // 5) transpose+split w_out ; output projection
    {
        dim3 g(D_ / 32, D_ / 32);
        transpose_split<<<g, dim3(32, 8)>>>(w_out, p_wth, p_wtl, D_, D_);
    }
    {
        dim3 g(D_ / 256, MROWS / 128);
        gemm_mma<<<g, 256, GSMEM_SZ>>>(p_ah, p_al, p_wth, p_wtl, out, D_, D_);
    }
}

// round 9
// speedup vs baseline: 3.2772x; 1.0265x over previous
#include <cuda_runtime.h>
#include <cuda_bf16.h>
#include <cstdint>
#include <cstddef>

#define B_    2
#define S_    2048
#define D_    4096
#define H_    32
#define KVH_  8
#define DH_   128
#define KVD_  (KVH_*DH_)          // 1024
#define QKVN  (D_ + 2*KVD_)       // 6144
#define MROWS (B_*S_)             // 4096
#define EPS_  1e-6f
#define SCALING_ 0.08838834764831845f  // 128^-0.5

// ---------------- scratch (device globals; no runtime allocation) ----------------
__device__ float g_qkv[(size_t)MROWS*QKVN];
__device__ __nv_bfloat16 g_qh[(size_t)B_*H_*S_*DH_];
__device__ __nv_bfloat16 g_ql[(size_t)B_*H_*S_*DH_];
__device__ __nv_bfloat16 g_kh[(size_t)B_*KVH_*S_*DH_];
__device__ __nv_bfloat16 g_kl[(size_t)B_*KVH_*S_*DH_];
__device__ __nv_bfloat16 g_vh[(size_t)B_*KVH_*S_*DH_];
__device__ __nv_bfloat16 g_vl[(size_t)B_*KVH_*S_*DH_];
__device__ __nv_bfloat16 g_ah[(size_t)MROWS*D_];     // activation hi
__device__ __nv_bfloat16 g_al[(size_t)MROWS*D_];     // activation lo
__device__ __nv_bfloat16 g_wth[(size_t)QKVN*D_];     // W^T hi  [N,K]
__device__ __nv_bfloat16 g_wtl[(size_t)QKVN*D_];     // W^T lo  [N,K]

// ---------------- ptx helpers ----------------
__device__ __forceinline__ uint32_t smem_u32(const void* p) {
    uint32_t a;
    asm("{ .reg .u64 t; cvta.to.shared.u64 t, %1; cvt.u32.u64 %0, t; }" : "=r"(a) : "l"(p));
    return a;
}
#define CP_ASYNC16(dst, src) \
    asm volatile("cp.async.cg.shared.global [%0], [%1], 16;" :: "r"(dst), "l"(src))
#define CP_COMMIT() asm volatile("cp.async.commit_group;" ::: "memory")
#define CP_WAIT(n)  asm volatile("cp.async.wait_group %0;" :: "n"(n) : "memory")

__device__ __forceinline__ void ldsm_x4(uint32_t* r, uint32_t addr) {
    asm volatile("ldmatrix.sync.aligned.m8n8.x4.shared.b16 {%0,%1,%2,%3}, [%4];"
        : "=r"(r[0]), "=r"(r[1]), "=r"(r[2]), "=r"(r[3]) : "r"(addr));
}
__device__ __forceinline__ void ldsm_x4_t(uint32_t* r, uint32_t addr) {
    asm volatile("ldmatrix.sync.aligned.m8n8.x4.trans.shared.b16 {%0,%1,%2,%3}, [%4];"
        : "=r"(r[0]), "=r"(r[1]), "=r"(r[2]), "=r"(r[3]) : "r"(addr));
}
__device__ __forceinline__ void mma16816(float* c, const uint32_t* a, const uint32_t* b) {
    asm volatile(
        "mma.sync.aligned.m16n8k16.row.col.f32.bf16.bf16.f32 "
        "{%0,%1,%2,%3}, {%4,%5,%6,%7}, {%8,%9}, {%0,%1,%2,%3};"
        : "+f"(c[0]), "+f"(c[1]), "+f"(c[2]), "+f"(c[3])
        : "r"(a[0]), "r"(a[1]), "r"(a[2]), "r"(a[3]), "r"(b[0]), "r"(b[1]));
}

// swizzle for 64B-row tiles (GEMM): 4 chunks of 16B per row
__device__ __forceinline__ uint32_t swz(int row, int chunk) {
    return (uint32_t)row * 64u + (uint32_t)((chunk ^ ((row >> 1) & 3)) * 16);
}
// swizzle for 256B-row tiles (attention, 128 bf16/row): 16 chunks of 16B
__device__ __forceinline__ uint32_t swz256(int row, int chunk) {
    return (uint32_t)row * 256u + (uint32_t)((chunk ^ (row & 7)) * 16);
}
// split fp32 -> packed bf16x2 hi with lo out-param
__device__ __forceinline__ uint32_t packsplit(float a, float b, uint32_t& lo) {
    __nv_bfloat16 ha = __float2bfloat16(a), hb = __float2bfloat16(b);
    __nv_bfloat16 la = __float2bfloat16(a - __bfloat162float(ha));
    __nv_bfloat16 lb = __float2bfloat16(b - __bfloat162float(hb));
    uint16_t uha = *(uint16_t*)&ha, uhb = *(uint16_t*)&hb;
    uint16_t ula = *(uint16_t*)&la, ulb = *(uint16_t*)&lb;
    lo = (uint32_t)ula | ((uint32_t)ulb << 16);
    return (uint32_t)uha | ((uint32_t)uhb << 16);
}

// ---------------- elementwise split fp32 -> (hi,lo) bf16 ----------------
__global__ __launch_bounds__(256) void split_bf16(const float* __restrict__ x,
                                                  __nv_bfloat16* __restrict__ hi,
                                                  __nv_bfloat16* __restrict__ lo) {
    size_t i = ((size_t)blockIdx.x * 256 + threadIdx.x) * 4;
    float4 v = *(const float4*)(x + i);
    uint32_t lo0, lo1;
    uint32_t hi0 = packsplit(v.x, v.y, lo0);
    uint32_t hi1 = packsplit(v.z, v.w, lo1);
    *(uint32_t*)(hi + i)     = hi0;
    *(uint32_t*)(hi + i + 2) = hi1;
    *(uint32_t*)(lo + i)     = lo0;
    *(uint32_t*)(lo + i + 2) = lo1;
}

// ---------------- transpose + split: W[K,N] -> T[N,K] hi/lo bf16 ----------------
__global__ __launch_bounds__(256) void transpose_split(const float* __restrict__ W,
                                                       __nv_bfloat16* __restrict__ Th,
                                                       __nv_bfloat16* __restrict__ Tl,
                                                       int K, int N) {
    __shared__ float t[32][33];
    const int n0 = blockIdx.x * 32, k0 = blockIdx.y * 32;
    const int tx = threadIdx.x, ty = threadIdx.y;   // 32 x 8
    #pragma unroll
    for (int i = 0; i < 32; i += 8)
        t[ty + i][tx] = W[(size_t)(k0 + ty + i) * N + n0 + tx];
    __syncthreads();
    #pragma unroll
    for (int i = 0; i < 32; i += 8) {
        float v = t[tx][ty + i];
        __nv_bfloat16 h = __float2bfloat16(v);
        size_t o = (size_t)(n0 + ty + i) * K + k0 + tx;
        Th[o] = h;
        Tl[o] = __float2bfloat16(v - __bfloat162float(h));
    }
}

// ---------------- mma.sync GEMM, 4-stage cp.async, single barrier/iter ----------------
#define A_TILE_B 8192
#define B_TILE_B 16384
#define GBUF_B   (2*A_TILE_B + 2*B_TILE_B)     // 48KB / stage
#define NSTAGE   4
#define GSMEM_SZ (NSTAGE*GBUF_B + 1024)

__global__ __launch_bounds__(256, 1) void gemm_mma(const __nv_bfloat16* __restrict__ Ah,
                                                   const __nv_bfloat16* __restrict__ Al,
                                                   const __nv_bfloat16* __restrict__ Bh,
                                                   const __nv_bfloat16* __restrict__ Bl,
                                                   float* __restrict__ C, int N, int K) {
    extern __shared__ char dsmem[];
    const int tid  = threadIdx.x;
    const int lane = tid & 31;
    const int wid  = tid >> 5;
    const int wm   = (wid >> 2) * 64;
    const int wn   = (wid & 3) * 64;
    const int row0 = blockIdx.y * 128;
    const int col0 = blockIdx.x * 256;

    uint32_t db = smem_u32(dsmem);
    uint32_t sbase = (db + 127u) & ~127u;

    float acc[4][8][4];
    #pragma unroll
    for (int mt = 0; mt < 4; mt++)
        #pragma unroll
        for (int nt = 0; nt < 8; nt++)
            #pragma unroll
            for (int j = 0; j < 4; j++) acc[mt][nt][j] = 0.f;

    const int NK = K / 32;

    auto load_tiles = [&](int buf, int kt) {
        const uint32_t bb = sbase + (uint32_t)buf * GBUF_B;
        const int k0 = kt * 32;
        #pragma unroll
        for (int i = 0; i < 2; i++) {
            int idx = tid + i * 256;
            int row = idx >> 2, ch = idx & 3;
            uint32_t sw = swz(row, ch);
            size_t g = (size_t)(row0 + row) * K + k0 + ch * 8;
            CP_ASYNC16(bb + sw,            Ah + g);
            CP_ASYNC16(bb + A_TILE_B + sw, Al + g);
        }
        #pragma unroll
        for (int i = 0; i < 4; i++) {
            int idx = tid + i * 256;
            int row = idx >> 2, ch = idx & 3;
            uint32_t sw = swz(row, ch);
            size_t g = (size_t)(col0 + row) * K + k0 + ch * 8;
            CP_ASYNC16(bb + 2*A_TILE_B + sw,            Bh + g);
            CP_ASYNC16(bb + 2*A_TILE_B + B_TILE_B + sw, Bl + g);
        }
    };

    // prologue: fill NSTAGE-1 stages
    #pragma unroll
    for (int s = 0; s < NSTAGE - 1; s++) { load_tiles(s, s); CP_COMMIT(); }

    const int mat = lane >> 3;
    const int wi  = lane & 7;

    for (int kt = 0; kt < NK; kt++) {
        CP_WAIT(NSTAGE - 2);          // stage kt resident
        __syncthreads();              // publishes stage kt; proves stage kt-1 reads done
        {
            int pf = kt + NSTAGE - 1;
            if (pf < NK) load_tiles(pf & (NSTAGE - 1), pf);
            CP_COMMIT();              // empty groups near tail keep accounting aligned
        }

        const uint32_t bb = sbase + (uint32_t)(kt & (NSTAGE - 1)) * GBUF_B;
        const uint32_t aH = bb, aL = bb + A_TILE_B;
        const uint32_t bH = bb + 2*A_TILE_B, bL = bH + B_TILE_B;

        #pragma unroll
        for (int kh = 0; kh < 2; kh++) {
            uint32_t ah[4][4], al[4][4], bh[4][4], bl[4][4];
            #pragma unroll
            for (int mt = 0; mt < 4; mt++) {
                int row = wm + mt * 16 + wi + (mat & 1) * 8;
                int ch  = kh * 2 + (mat >> 1);
                uint32_t sw = swz(row, ch);
                ldsm_x4(ah[mt], aH + sw);
                ldsm_x4(al[mt], aL + sw);
            }
            #pragma unroll
            for (int np = 0; np < 4; np++) {
                int row = wn + np * 16 + wi + (mat >> 1) * 8;
                int ch  = kh * 2 + (mat & 1);
                uint32_t sw = swz(row, ch);
                ldsm_x4(bh[np], bH + sw);
                ldsm_x4(bl[np], bL + sw);
            }
            #pragma unroll
            for (int mt = 0; mt < 4; mt++)
                #pragma unroll
                for (int np = 0; np < 4; np++)
                    #pragma unroll
                    for (int s = 0; s < 2; s++) {
                        float* a = acc[mt][np * 2 + s];
                        mma16816(a, ah[mt], &bh[np][s * 2]);
                        mma16816(a, ah[mt], &bl[np][s * 2]);
                        mma16816(a, al[mt], &bh[np][s * 2]);
                    }
        }
        // no trailing barrier: next iteration's top barrier protects the ring
    }

    #pragma unroll
    for (int mt = 0; mt < 4; mt++)
        #pragma unroll
        for (int nt = 0; nt < 8; nt++) {
            int m = row0 + wm + mt * 16 + (lane >> 2);
            int n = col0 + wn + nt * 8 + (lane & 3) * 2;
            float* a = acc[mt][nt];
            *(float2*)(C + (size_t)m * N + n)       = make_float2(a[0], a[1]);
            *(float2*)(C + (size_t)(m + 8) * N + n) = make_float2(a[2], a[3]);
        }
}

// ---------------- RMSNorm + RoPE + split-bf16 scatter (vectorized) ----------------
__global__ __launch_bounds__(256) void norm_rope_kernel(const float* __restrict__ q_scale,
                                                        const float* __restrict__ k_scale,
                                                        const float* __restrict__ cosc,
                                                        const float* __restrict__ sinc) {
    const int bs = blockIdx.x;
    const int b = bs / S_;
    const int s = bs % S_;
    const float* row = g_qkv + (size_t)bs * QKVN;
    const int tid = threadIdx.x;
    __shared__ float red[256];
    __shared__ float s_qinv, s_kinv;

    float ss = 0.f;
    for (int i = tid * 4; i < D_; i += 1024) {
        float4 v = *(const float4*)(row + i);
        ss += v.x*v.x + v.y*v.y + v.z*v.z + v.w*v.w;
    }
    red[tid] = ss; __syncthreads();
    for (int st = 128; st > 0; st >>= 1) { if (tid < st) red[tid] += red[tid + st]; __syncthreads(); }
    if (tid == 0) s_qinv = rsqrtf(red[0] / (float)D_ + EPS_);
    __syncthreads();

    ss = 0.f;
    for (int i = tid * 4; i < KVD_; i += 1024) {
        float4 v = *(const float4*)(row + D_ + i);
        ss += v.x*v.x + v.y*v.y + v.z*v.z + v.w*v.w;
    }
    red[tid] = ss; __syncthreads();
    for (int st = 128; st > 0; st >>= 1) { if (tid < st) red[tid] += red[tid + st]; __syncthreads(); }
    if (tid == 0) s_kinv = rsqrtf(red[0] / (float)KVD_ + EPS_);
    __syncthreads();

    const float qinv = s_qinv, kinv = s_kinv;
    const float* cs = cosc + (size_t)bs * DH_;
    const float* sn = sinc + (size_t)bs * DH_;

    // q: pairs (2i, 2i+1) never straddle the rotate-half boundary (half=64, even-aligned)
    for (int i2 = tid; i2 < D_ / 2; i2 += 256) {
        int i = i2 * 2;
        int h = i >> 7, dd = i & 127;
        int rj = (dd < 64) ? (i + 64) : (i - 64);
        float sgn = (dd < 64) ? -1.f : 1.f;
        float x0 = row[i]   * qinv * q_scale[i];
        float x1 = row[i+1] * qinv * q_scale[i+1];
        float r0 = row[rj]   * qinv * q_scale[rj]   * sgn;
        float r1 = row[rj+1] * qinv * q_scale[rj+1] * sgn;
        float v0 = x0 * cs[dd]   + r0 * sn[dd];
        float v1 = x1 * cs[dd+1] + r1 * sn[dd+1];
        size_t o = (((size_t)b * H_ + h) * S_ + s) * DH_ + dd;
        uint32_t lo, hi = packsplit(v0, v1, lo);
        *(uint32_t*)(g_qh + o) = hi;
        *(uint32_t*)(g_ql + o) = lo;
    }
    for (int i2 = tid; i2 < KVD_ / 2; i2 += 256) {
        int i = i2 * 2;
        int h = i >> 7, dd = i & 127;
        int rj = (dd < 64) ? (i + 64) : (i - 64);
        float sgn = (dd < 64) ? -1.f : 1.f;
        float x0 = row[D_ + i]   * kinv * k_scale[i];
        float x1 = row[D_ + i+1] * kinv * k_scale[i+1];
        float r0 = row[D_ + rj]   * kinv * k_scale[rj]   * sgn;
        float r1 = row[D_ + rj+1] * kinv * k_scale[rj+1] * sgn;
        float v0 = x0 * cs[dd]   + r0 * sn[dd];
        float v1 = x1 * cs[dd+1] + r1 * sn[dd+1];
        size_t o = (((size_t)b * KVH_ + h) * S_ + s) * DH_ + dd;
        uint32_t lo, hi = packsplit(v0, v1, lo);
        *(uint32_t*)(g_kh + o) = hi;
        *(uint32_t*)(g_kl + o) = lo;
    }
    for (int i2 = tid; i2 < KVD_ / 2; i2 += 256) {
        int i = i2 * 2;
        int h = i >> 7, dd = i & 127;
        size_t o = (((size_t)b * KVH_ + h) * S_ + s) * DH_ + dd;
        uint32_t lo, hi = packsplit(row[D_ + KVD_ + i], row[D_ + KVD_ + i + 1], lo);
        *(uint32_t*)(g_vh + o) = hi;
        *(uint32_t*)(g_vl + o) = lo;
    }
}

// ---------------- tensor-core flash attention (causal, split-bf16 3xMMA) ----------------
#define AT_QH   0
#define AT_QL   16384
#define AT_KV   32768
#define AKV_STG 65536
#define AT_SO   (AT_KV + 2*AKV_STG)      // fp32 [64][132]
#define SO_STRIDE 132
#define AT_RED  (AT_SO + 64*SO_STRIDE*4)
#define ATT_SMEM (AT_RED + 1024 + 128)

__global__ __launch_bounds__(256, 1) void attn_mma() {
    extern __shared__ char dsmem[];
    const int bh = blockIdx.x;
    const int b = bh / H_;
    const int h = bh % H_;
    const int kvh = h / (H_ / KVH_);
    const int qb = blockIdx.y;
    const int tid = threadIdx.x;
    const int lane = tid & 31;
    const int wid = tid >> 5;
    const int warp_m = wid >> 1;
    const int warp_n = wid & 1;

    uint32_t db = smem_u32(dsmem);
    uint32_t sbase = (db + 127u) & ~127u;
    float* sO   = (float*)(dsmem + (sbase - db) + AT_SO);
    float* redm = (float*)(dsmem + (sbase - db) + AT_RED);
    float* redl = redm + 128;

    const __nv_bfloat16* QhG = g_qh + (((size_t)b * H_ + h) * S_ + (size_t)qb * 64) * DH_;
    const __nv_bfloat16* QlG = g_ql + (((size_t)b * H_ + h) * S_ + (size_t)qb * 64) * DH_;
    const __nv_bfloat16* KhB = g_kh + ((size_t)b * KVH_ + kvh) * S_ * DH_;
    const __nv_bfloat16* KlB = g_kl + ((size_t)b * KVH_ + kvh) * S_ * DH_;
    const __nv_bfloat16* VhB = g_vh + ((size_t)b * KVH_ + kvh) * S_ * DH_;
    const __nv_bfloat16* VlB = g_vl + ((size_t)b * KVH_ + kvh) * S_ * DH_;

    #pragma unroll
    for (int i = 0; i < 4; i++) {
        int idx = tid + i * 256;
        int row = idx >> 4, ch = idx & 15;
        uint32_t sw = swz256(row, ch);
        size_t g = (size_t)row * DH_ + ch * 8;
        CP_ASYNC16(sbase + AT_QH + sw, QhG + g);
        CP_ASYNC16(sbase + AT_QL + sw, QlG + g);
    }
    auto load_kv = [&](int buf, int jt) {
        uint32_t sb = sbase + AT_KV + (uint32_t)buf * AKV_STG;
        size_t gb = (size_t)jt * 64 * DH_;
        #pragma unroll
        for (int i = 0; i < 4; i++) {
            int idx = tid + i * 256;
            int row = idx >> 4, ch = idx & 15;
            uint32_t sw = swz256(row, ch);
            size_t g = gb + (size_t)row * DH_ + ch * 8;
            CP_ASYNC16(sb +         sw, KhB + g);
            CP_ASYNC16(sb + 16384 + sw, KlB + g);
            CP_ASYNC16(sb + 32768 + sw, VhB + g);
            CP_ASYNC16(sb + 49152 + sw, VlB + g);
        }
    };
    load_kv(0, 0);
    CP_COMMIT();

    float oacc[16][4];
    #pragma unroll
    for (int nt = 0; nt < 16; nt++)
        #pragma unroll
        for (int j = 0; j < 4; j++) oacc[nt][j] = 0.f;
    float m0 = -1e30f, m1 = -1e30f, l0 = 0.f, l1 = 0.f;

    const int gr  = lane >> 2;
    const int rI0 = warp_m * 16 + gr;
    const int nj = qb + 1;

    for (int jt = 0; jt < nj; jt++) {
        const int buf = jt & 1;
        CP_WAIT(0);
        __syncthreads();              // publish stage jt; prior-iter reads of buf^1 done
        if (jt + 1 < nj) { load_kv(buf ^ 1, jt + 1); CP_COMMIT(); }

        const uint32_t sQH = sbase + AT_QH, sQL = sbase + AT_QL;
        const uint32_t kb = sbase + AT_KV + (uint32_t)buf * AKV_STG;
        const uint32_t sKH = kb, sKL = kb + 16384, sVH = kb + 32768, sVL = kb + 49152;

        float sacc[4][4];
        #pragma unroll
        for (int nt = 0; nt < 4; nt++)
            #pragma unroll
            for (int j = 0; j < 4; j++) sacc[nt][j] = 0.f;

        #pragma unroll
        for (int kt = 0; kt < 8; kt++) {
            uint32_t qh4[4], ql4[4], kbh[2][4], kbl[2][4];
            int qrow = warp_m * 16 + (lane & 15);
            int qch  = kt * 2 + (lane >> 4);
            ldsm_x4(qh4, sQH + swz256(qrow, qch));
            ldsm_x4(ql4, sQL + swz256(qrow, qch));
            #pragma unroll
            for (int ng = 0; ng < 2; ng++) {
                int krow = warp_n * 32 + ng * 16 + (lane & 7) + (lane >> 4) * 8;
                int kch  = kt * 2 + ((lane >> 3) & 1);
                ldsm_x4(kbh[ng], sKH + swz256(krow, kch));
                ldsm_x4(kbl[ng], sKL + swz256(krow, kch));
            }
            #pragma unroll
            for (int ng = 0; ng < 2; ng++)
                #pragma unroll
                for (int s = 0; s < 2; s++) {
                    float* a = sacc[ng * 2 + s];
                    mma16816(a, qh4, &kbh[ng][s * 2]);
                    mma16816(a, qh4, &kbl[ng][s * 2]);
                    mma16816(a, ql4, &kbh[ng][s * 2]);
                }
        }

        #pragma unroll
        for (int nt = 0; nt < 4; nt++)
            #pragma unroll
            for (int j = 0; j < 4; j++) sacc[nt][j] *= SCALING_;
        if (jt == qb) {
            int r0g = qb * 64 + rI0;
            #pragma unroll
            for (int nt = 0; nt < 4; nt++) {
                int c = jt * 64 + warp_n * 32 + nt * 8 + (lane & 3) * 2;
                if (c     > r0g)     sacc[nt][0] = -1e30f;
                if (c + 1 > r0g)     sacc[nt][1] = -1e30f;
                if (c     > r0g + 8) sacc[nt][2] = -1e30f;
                if (c + 1 > r0g + 8) sacc[nt][3] = -1e30f;
            }
        }

        float pm0 = -1e30f, pm1 = -1e30f;
        #pragma unroll
        for (int nt = 0; nt < 4; nt++) {
            pm0 = fmaxf(pm0, fmaxf(sacc[nt][0], sacc[nt][1]));
            pm1 = fmaxf(pm1, fmaxf(sacc[nt][2], sacc[nt][3]));
        }
        pm0 = fmaxf(pm0, __shfl_xor_sync(0xFFFFFFFFu, pm0, 1));
        pm0 = fmaxf(pm0, __shfl_xor_sync(0xFFFFFFFFu, pm0, 2));
        pm1 = fmaxf(pm1, __shfl_xor_sync(0xFFFFFFFFu, pm1, 1));
        pm1 = fmaxf(pm1, __shfl_xor_sync(0xFFFFFFFFu, pm1, 2));
        if ((lane & 3) == 0) {
            redm[warp_n * 64 + rI0]     = pm0;
            redm[warp_n * 64 + rI0 + 8] = pm1;
        }
        __syncthreads();
        float mt0 = fmaxf(redm[rI0],     redm[64 + rI0]);
        float mt1 = fmaxf(redm[rI0 + 8], redm[64 + rI0 + 8]);

        float mn0 = fmaxf(m0, mt0), mn1 = fmaxf(m1, mt1);
        float c0 = __expf(m0 - mn0), c1 = __expf(m1 - mn1);

        float ps0 = 0.f, ps1 = 0.f;
        #pragma unroll
        for (int nt = 0; nt < 4; nt++) {
            sacc[nt][0] = __expf(sacc[nt][0] - mn0);
            sacc[nt][1] = __expf(sacc[nt][1] - mn0);
            sacc[nt][2] = __expf(sacc[nt][2] - mn1);
            sacc[nt][3] = __expf(sacc[nt][3] - mn1);
            ps0 += sacc[nt][0] + sacc[nt][1];
            ps1 += sacc[nt][2] + sacc[nt][3];
        }
        ps0 += __shfl_xor_sync(0xFFFFFFFFu, ps0, 1);
        ps0 += __shfl_xor_sync(0xFFFFFFFFu, ps0, 2);
        ps1 += __shfl_xor_sync(0xFFFFFFFFu, ps1, 1);
        ps1 += __shfl_xor_sync(0xFFFFFFFFu, ps1, 2);
        if ((lane & 3) == 0) {
            redl[warp_n * 64 + rI0]     = ps0;
            redl[warp_n * 64 + rI0 + 8] = ps1;
        }
        __syncthreads();
        l0 = l0 * c0 + redl[rI0]     + redl[64 + rI0];
        l1 = l1 * c1 + redl[rI0 + 8] + redl[64 + rI0 + 8];
        m0 = mn0; m1 = mn1;

        #pragma unroll
        for (int nt = 0; nt < 16; nt++) {
            oacc[nt][0] *= c0; oacc[nt][1] *= c0;
            oacc[nt][2] *= c1; oacc[nt][3] *= c1;
        }

        uint32_t pah[2][4], pal[2][4];
        #pragma unroll
        for (int kt = 0; kt < 2; kt++) {
            pah[kt][0] = packsplit(sacc[2*kt][0],   sacc[2*kt][1],   pal[kt][0]);
            pah[kt][1] = packsplit(sacc[2*kt][2],   sacc[2*kt][3],   pal[kt][1]);
            pah[kt][2] = packsplit(sacc[2*kt+1][0], sacc[2*kt+1][1], pal[kt][2]);
            pah[kt][3] = packsplit(sacc[2*kt+1][2], sacc[2*kt+1][3], pal[kt][3]);
        }

        #pragma unroll
        for (int ndg = 0; ndg < 8; ndg++) {
            #pragma unroll
            for (int kt = 0; kt < 2; kt++) {
                uint32_t vh4[4], vl4[4];
                int vrow = warp_n * 32 + kt * 16 + (lane & 15);
                int vch  = ndg * 2 + (lane >> 4);
                ldsm_x4_t(vh4, sVH + swz256(vrow, vch));
                ldsm_x4_t(vl4, sVL + swz256(vrow, vch));
                #pragma unroll
                for (int hf = 0; hf < 2; hf++) {
                    float* o = oacc[ndg * 2 + hf];
                    mma16816(o, pah[kt], &vh4[hf * 2]);
                    mma16816(o, pah[kt], &vl4[hf * 2]);
                    mma16816(o, pal[kt], &vh4[hf * 2]);
                }
            }
        }
        // no trailing barrier: next iteration's top barrier protects KV ring + red arrays
    }

    __syncthreads();
    if (warp_n == 0) {
        #pragma unroll
        for (int nt = 0; nt < 16; nt++) {
            int d = nt * 8 + (lane & 3) * 2;
            *(float2*)&sO[(size_t)rI0 * SO_STRIDE + d]       = make_float2(oacc[nt][0], oacc[nt][1]);
            *(float2*)&sO[(size_t)(rI0 + 8) * SO_STRIDE + d] = make_float2(oacc[nt][2], oacc[nt][3]);
        }
    }
    __syncthreads();
    if (warp_n == 1) {
        float inv0 = 1.0f / l0, inv1 = 1.0f / l1;
        size_t row0g = (size_t)b * S_ + qb * 64 + rI0;
        size_t row1g = row0g + 8;
        #pragma unroll
        for (int nt = 0; nt < 16; nt++) {
            int d = nt * 8 + (lane & 3) * 2;
            float2 t0 = *(float2*)&sO[(size_t)rI0 * SO_STRIDE + d];
            float2 t1 = *(float2*)&sO[(size_t)(rI0 + 8) * SO_STRIDE + d];
            float v00 = (t0.x + oacc[nt][0]) * inv0;
            float v01 = (t0.y + oacc[nt][1]) * inv0;
            float v10 = (t1.x + oacc[nt][2]) * inv1;
            float v11 = (t1.y + oacc[nt][3]) * inv1;
            size_t o0 = row0g * D_ + h * DH_ + d;
            size_t o1 = row1g * D_ + h * DH_ + d;
            uint32_t lo0, lo1;
            uint32_t hi0 = packsplit(v00, v01, lo0);
            uint32_t hi1 = packsplit(v10, v11, lo1);
            *(uint32_t*)(g_ah + o0) = hi0;
            *(uint32_t*)(g_al + o0) = lo0;
            *(uint32_t*)(g_ah + o1) = hi1;
            *(uint32_t*)(g_al + o1) = lo1;
        }
    }
}

// ---------------- launch ----------------
extern "C" void kernel_launch(void* const* d_in, const int* in_sizes, int n_in,
                              void* d_out, int out_size) {
    const float* hidden  = (const float*)d_in[0];
    const float* w_qkv   = (const float*)d_in[1];
    const float* w_out   = (const float*)d_in[2];
    const float* q_scale = (const float*)d_in[3];
    const float* k_scale = (const float*)d_in[4];
    const float* cosc    = (const float*)d_in[5];
    const float* sinc    = (const float*)d_in[6];
    float* out = (float*)d_out;

    float* p_qkv;
    __nv_bfloat16 *p_ah, *p_al, *p_wth, *p_wtl;
    cudaGetSymbolAddress((void**)&p_qkv,  g_qkv);
    cudaGetSymbolAddress((void**)&p_ah,   g_ah);
    cudaGetSymbolAddress((void**)&p_al,   g_al);
    cudaGetSymbolAddress((void**)&p_wth,  g_wth);
    cudaGetSymbolAddress((void**)&p_wtl,  g_wtl);

    cudaFuncSetAttribute(gemm_mma, cudaFuncAttributeMaxDynamicSharedMemorySize, GSMEM_SZ);
    cudaFuncSetAttribute(attn_mma, cudaFuncAttributeMaxDynamicSharedMemorySize, ATT_SMEM);

    split_bf16<<<(MROWS * (size_t)D_) / (256 * 4), 256>>>(hidden, p_ah, p_al);
    {
        dim3 g(QKVN / 32, D_ / 32);
        transpose_split<<<g, dim3(32, 8)>>>(w_qkv, p_wth, p_wtl, D_, QKVN);
    }
    {
        dim3 g(QKVN / 256, MROWS / 128);
        gemm_mma<<<g, 256, GSMEM_SZ>>>(p_ah, p_al, p_wth, p_wtl, p_qkv, QKVN, D_);
    }
    norm_rope_kernel<<<B_ * S_, 256>>>(q_scale, k_scale, cosc, sinc);
    {
        dim3 g(B_ * H_, S_ / 64);
        attn_mma<<<g, 256, ATT_SMEM>>>();
    }
    {
        dim3 g(D_ / 32, D_ / 32);
        transpose_split<<<g, dim3(32, 8)>>>(w_out, p_wth, p_wtl, D_, D_);
    }
    {
        dim3 g(D_ / 256, MROWS / 128);
        gemm_mma<<<g, 256, GSMEM_SZ>>>(p_ah, p_al, p_wth, p_wtl, out, D_, D_);
    }
}

// round 10
// speedup vs baseline: 3.5180x; 1.0735x over previous
#include <cuda_runtime.h>
#include <cuda_bf16.h>
#include <cstdint>
#include <cstddef>

#define B_    2
#define S_    2048
#define D_    4096
#define H_    32
#define KVH_  8
#define DH_   128
#define KVD_  (KVH_*DH_)          // 1024
#define QKVN  (D_ + 2*KVD_)       // 6144
#define MROWS (B_*S_)             // 4096
#define EPS_  1e-6f
#define SCALING_ 0.08838834764831845f  // 128^-0.5

// ---------------- scratch (device globals; no runtime allocation) ----------------
__device__ float g_part[(size_t)2*MROWS*QKVN];       // split-K partials (reused for both GEMMs)
__device__ __nv_bfloat16 g_qh[(size_t)B_*H_*S_*DH_];
__device__ __nv_bfloat16 g_ql[(size_t)B_*H_*S_*DH_];
__device__ __nv_bfloat16 g_kh[(size_t)B_*KVH_*S_*DH_];
__device__ __nv_bfloat16 g_kl[(size_t)B_*KVH_*S_*DH_];
__device__ __nv_bfloat16 g_vh[(size_t)B_*KVH_*S_*DH_];
__device__ __nv_bfloat16 g_vl[(size_t)B_*KVH_*S_*DH_];
__device__ __nv_bfloat16 g_ah[(size_t)MROWS*D_];     // activation hi
__device__ __nv_bfloat16 g_al[(size_t)MROWS*D_];     // activation lo
__device__ __nv_bfloat16 g_wth[(size_t)QKVN*D_];     // W^T hi  [N,K]
__device__ __nv_bfloat16 g_wtl[(size_t)QKVN*D_];     // W^T lo  [N,K]

// ---------------- ptx helpers ----------------
__device__ __forceinline__ uint32_t smem_u32(const void* p) {
    uint32_t a;
    asm("{ .reg .u64 t; cvta.to.shared.u64 t, %1; cvt.u32.u64 %0, t; }" : "=r"(a) : "l"(p));
    return a;
}
#define CP_ASYNC16(dst, src) \
    asm volatile("cp.async.cg.shared.global [%0], [%1], 16;" :: "r"(dst), "l"(src))
#define CP_COMMIT() asm volatile("cp.async.commit_group;" ::: "memory")
#define CP_WAIT(n)  asm volatile("cp.async.wait_group %0;" :: "n"(n) : "memory")

__device__ __forceinline__ void ldsm_x4(uint32_t* r, uint32_t addr) {
    asm volatile("ldmatrix.sync.aligned.m8n8.x4.shared.b16 {%0,%1,%2,%3}, [%4];"
        : "=r"(r[0]), "=r"(r[1]), "=r"(r[2]), "=r"(r[3]) : "r"(addr));
}
__device__ __forceinline__ void ldsm_x4_t(uint32_t* r, uint32_t addr) {
    asm volatile("ldmatrix.sync.aligned.m8n8.x4.trans.shared.b16 {%0,%1,%2,%3}, [%4];"
        : "=r"(r[0]), "=r"(r[1]), "=r"(r[2]), "=r"(r[3]) : "r"(addr));
}
__device__ __forceinline__ void mma16816(float* c, const uint32_t* a, const uint32_t* b) {
    asm volatile(
        "mma.sync.aligned.m16n8k16.row.col.f32.bf16.bf16.f32 "
        "{%0,%1,%2,%3}, {%4,%5,%6,%7}, {%8,%9}, {%0,%1,%2,%3};"
        : "+f"(c[0]), "+f"(c[1]), "+f"(c[2]), "+f"(c[3])
        : "r"(a[0]), "r"(a[1]), "r"(a[2]), "r"(a[3]), "r"(b[0]), "r"(b[1]));
}

// swizzle for 64B-row tiles (GEMM): 4 chunks of 16B per row
__device__ __forceinline__ uint32_t swz(int row, int chunk) {
    return (uint32_t)row * 64u + (uint32_t)((chunk ^ ((row >> 1) & 3)) * 16);
}
// swizzle for 256B-row tiles (attention, 128 bf16/row): 16 chunks of 16B
__device__ __forceinline__ uint32_t swz256(int row, int chunk) {
    return (uint32_t)row * 256u + (uint32_t)((chunk ^ (row & 7)) * 16);
}
// split fp32 -> packed bf16x2 hi with lo out-param
__device__ __forceinline__ uint32_t packsplit(float a, float b, uint32_t& lo) {
    __nv_bfloat16 ha = __float2bfloat16(a), hb = __float2bfloat16(b);
    __nv_bfloat16 la = __float2bfloat16(a - __bfloat162float(ha));
    __nv_bfloat16 lb = __float2bfloat16(b - __bfloat162float(hb));
    uint16_t uha = *(uint16_t*)&ha, uhb = *(uint16_t*)&hb;
    uint16_t ula = *(uint16_t*)&la, ulb = *(uint16_t*)&lb;
    lo = (uint32_t)ula | ((uint32_t)ulb << 16);
    return (uint32_t)uha | ((uint32_t)uhb << 16);
}

// ---------------- elementwise split fp32 -> (hi,lo) bf16 ----------------
__global__ __launch_bounds__(256) void split_bf16(const float* __restrict__ x,
                                                  __nv_bfloat16* __restrict__ hi,
                                                  __nv_bfloat16* __restrict__ lo) {
    size_t i = ((size_t)blockIdx.x * 256 + threadIdx.x) * 4;
    float4 v = *(const float4*)(x + i);
    uint32_t lo0, lo1;
    uint32_t hi0 = packsplit(v.x, v.y, lo0);
    uint32_t hi1 = packsplit(v.z, v.w, lo1);
    *(uint32_t*)(hi + i)     = hi0;
    *(uint32_t*)(hi + i + 2) = hi1;
    *(uint32_t*)(lo + i)     = lo0;
    *(uint32_t*)(lo + i + 2) = lo1;
}

// ---------------- final reduce for split-K out-projection ----------------
__global__ __launch_bounds__(256) void reduce_add(const float* __restrict__ p,
                                                  float* __restrict__ out, size_t n) {
    size_t i = ((size_t)blockIdx.x * 256 + threadIdx.x) * 4;
    float4 a = *(const float4*)(p + i);
    float4 b = *(const float4*)(p + n + i);
    *(float4*)(out + i) = make_float4(a.x + b.x, a.y + b.y, a.z + b.z, a.w + b.w);
}

// ---------------- transpose + split: W[K,N] -> T[N,K] hi/lo bf16 ----------------
__global__ __launch_bounds__(256) void transpose_split(const float* __restrict__ W,
                                                       __nv_bfloat16* __restrict__ Th,
                                                       __nv_bfloat16* __restrict__ Tl,
                                                       int K, int N) {
    __shared__ float t[32][33];
    const int n0 = blockIdx.x * 32, k0 = blockIdx.y * 32;
    const int tx = threadIdx.x, ty = threadIdx.y;   // 32 x 8
    #pragma unroll
    for (int i = 0; i < 32; i += 8)
        t[ty + i][tx] = W[(size_t)(k0 + ty + i) * N + n0 + tx];
    __syncthreads();
    #pragma unroll
    for (int i = 0; i < 32; i += 8) {
        float v = t[tx][ty + i];
        __nv_bfloat16 h = __float2bfloat16(v);
        size_t o = (size_t)(n0 + ty + i) * K + k0 + tx;
        Th[o] = h;
        Tl[o] = __float2bfloat16(v - __bfloat162float(h));
    }
}

// ---------------- mma.sync GEMM, 4-stage cp.async, split-K=2 ----------------
#define A_TILE_B 8192
#define B_TILE_B 16384
#define GBUF_B   (2*A_TILE_B + 2*B_TILE_B)     // 48KB / stage
#define NSTAGE   4
#define GSMEM_SZ (NSTAGE*GBUF_B + 1024)

__global__ __launch_bounds__(256, 1) void gemm_mma(const __nv_bfloat16* __restrict__ Ah,
                                                   const __nv_bfloat16* __restrict__ Al,
                                                   const __nv_bfloat16* __restrict__ Bh,
                                                   const __nv_bfloat16* __restrict__ Bl,
                                                   float* __restrict__ C, int N, int K) {
    extern __shared__ char dsmem[];
    const int tid  = threadIdx.x;
    const int lane = tid & 31;
    const int wid  = tid >> 5;
    const int wm   = (wid >> 2) * 64;
    const int wn   = (wid & 3) * 64;
    const int row0 = blockIdx.y * 128;
    const int col0 = blockIdx.x * 256;

    // split-K slice: columns [ks*K/2, (ks+1)*K/2), partial C slab per slice
    const int Khalf = K >> 1;
    const size_t koff = (size_t)blockIdx.z * Khalf;
    Ah += koff; Al += koff; Bh += koff; Bl += koff;
    C  += (size_t)blockIdx.z * (size_t)MROWS * N;

    uint32_t db = smem_u32(dsmem);
    uint32_t sbase = (db + 127u) & ~127u;

    float acc[4][8][4];
    #pragma unroll
    for (int mt = 0; mt < 4; mt++)
        #pragma unroll
        for (int nt = 0; nt < 8; nt++)
            #pragma unroll
            for (int j = 0; j < 4; j++) acc[mt][nt][j] = 0.f;

    const int NK = Khalf / 32;

    auto load_tiles = [&](int buf, int kt) {
        const uint32_t bb = sbase + (uint32_t)buf * GBUF_B;
        const int k0 = kt * 32;
        #pragma unroll
        for (int i = 0; i < 2; i++) {
            int idx = tid + i * 256;
            int row = idx >> 2, ch = idx & 3;
            uint32_t sw = swz(row, ch);
            size_t g = (size_t)(row0 + row) * K + k0 + ch * 8;
            CP_ASYNC16(bb + sw,            Ah + g);
            CP_ASYNC16(bb + A_TILE_B + sw, Al + g);
        }
        #pragma unroll
        for (int i = 0; i < 4; i++) {
            int idx = tid + i * 256;
            int row = idx >> 2, ch = idx & 3;
            uint32_t sw = swz(row, ch);
            size_t g = (size_t)(col0 + row) * K + k0 + ch * 8;
            CP_ASYNC16(bb + 2*A_TILE_B + sw,            Bh + g);
            CP_ASYNC16(bb + 2*A_TILE_B + B_TILE_B + sw, Bl + g);
        }
    };

    #pragma unroll
    for (int s = 0; s < NSTAGE - 1; s++) { load_tiles(s, s); CP_COMMIT(); }

    const int mat = lane >> 3;
    const int wi  = lane & 7;

    for (int kt = 0; kt < NK; kt++) {
        CP_WAIT(NSTAGE - 2);
        __syncthreads();
        {
            int pf = kt + NSTAGE - 1;
            if (pf < NK) load_tiles(pf & (NSTAGE - 1), pf);
            CP_COMMIT();
        }

        const uint32_t bb = sbase + (uint32_t)(kt & (NSTAGE - 1)) * GBUF_B;
        const uint32_t aH = bb, aL = bb + A_TILE_B;
        const uint32_t bH = bb + 2*A_TILE_B, bL = bH + B_TILE_B;

        #pragma unroll
        for (int kh = 0; kh < 2; kh++) {
            uint32_t ah[4][4], al[4][4], bh[4][4], bl[4][4];
            #pragma unroll
            for (int mt = 0; mt < 4; mt++) {
                int row = wm + mt * 16 + wi + (mat & 1) * 8;
                int ch  = kh * 2 + (mat >> 1);
                uint32_t sw = swz(row, ch);
                ldsm_x4(ah[mt], aH + sw);
                ldsm_x4(al[mt], aL + sw);
            }
            #pragma unroll
            for (int np = 0; np < 4; np++) {
                int row = wn + np * 16 + wi + (mat >> 1) * 8;
                int ch  = kh * 2 + (mat & 1);
                uint32_t sw = swz(row, ch);
                ldsm_x4(bh[np], bH + sw);
                ldsm_x4(bl[np], bL + sw);
            }
            #pragma unroll
            for (int mt = 0; mt < 4; mt++)
                #pragma unroll
                for (int np = 0; np < 4; np++)
                    #pragma unroll
                    for (int s = 0; s < 2; s++) {
                        float* a = acc[mt][np * 2 + s];
                        mma16816(a, ah[mt], &bh[np][s * 2]);
                        mma16816(a, ah[mt], &bl[np][s * 2]);
                        mma16816(a, al[mt], &bh[np][s * 2]);
                    }
        }
    }

    #pragma unroll
    for (int mt = 0; mt < 4; mt++)
        #pragma unroll
        for (int nt = 0; nt < 8; nt++) {
            int m = row0 + wm + mt * 16 + (lane >> 2);
            int n = col0 + wn + nt * 8 + (lane & 3) * 2;
            float* a = acc[mt][nt];
            *(float2*)(C + (size_t)m * N + n)       = make_float2(a[0], a[1]);
            *(float2*)(C + (size_t)(m + 8) * N + n) = make_float2(a[2], a[3]);
        }
}

// ---------------- fused split-K reduce + RMSNorm + RoPE + split-bf16 scatter ----------------
__global__ __launch_bounds__(256) void norm_rope_kernel(const float* __restrict__ part,
                                                        const float* __restrict__ q_scale,
                                                        const float* __restrict__ k_scale,
                                                        const float* __restrict__ cosc,
                                                        const float* __restrict__ sinc) {
    __shared__ float srow[QKVN];          // 24KB: reduced qkv row
    __shared__ float red[256];
    __shared__ float s_qinv, s_kinv;
    const int bs = blockIdx.x;
    const int b = bs / S_;
    const int s = bs % S_;
    const int tid = threadIdx.x;
    const float* p0 = part + (size_t)bs * QKVN;
    const float* p1 = part + (size_t)MROWS * QKVN + (size_t)bs * QKVN;

    // reduce the two split-K partials into smem (single gmem pass)
    for (int i = tid * 4; i < QKVN; i += 1024) {
        float4 a = *(const float4*)(p0 + i);
        float4 c = *(const float4*)(p1 + i);
        *(float4*)(srow + i) = make_float4(a.x + c.x, a.y + c.y, a.z + c.z, a.w + c.w);
    }
    __syncthreads();

    float ss = 0.f;
    for (int i = tid * 4; i < D_; i += 1024) {
        float4 v = *(const float4*)(srow + i);
        ss += v.x*v.x + v.y*v.y + v.z*v.z + v.w*v.w;
    }
    red[tid] = ss; __syncthreads();
    for (int st = 128; st > 0; st >>= 1) { if (tid < st) red[tid] += red[tid + st]; __syncthreads(); }
    if (tid == 0) s_qinv = rsqrtf(red[0] / (float)D_ + EPS_);
    __syncthreads();

    ss = 0.f;
    for (int i = tid * 4; i < KVD_; i += 1024) {
        float4 v = *(const float4*)(srow + D_ + i);
        ss += v.x*v.x + v.y*v.y + v.z*v.z + v.w*v.w;
    }
    red[tid] = ss; __syncthreads();
    for (int st = 128; st > 0; st >>= 1) { if (tid < st) red[tid] += red[tid + st]; __syncthreads(); }
    if (tid == 0) s_kinv = rsqrtf(red[0] / (float)KVD_ + EPS_);
    __syncthreads();

    const float qinv = s_qinv, kinv = s_kinv;
    const float* cs = cosc + (size_t)bs * DH_;
    const float* sn = sinc + (size_t)bs * DH_;

    for (int i2 = tid; i2 < D_ / 2; i2 += 256) {
        int i = i2 * 2;
        int h = i >> 7, dd = i & 127;
        int rj = (dd < 64) ? (i + 64) : (i - 64);
        float sgn = (dd < 64) ? -1.f : 1.f;
        float x0 = srow[i]   * qinv * q_scale[i];
        float x1 = srow[i+1] * qinv * q_scale[i+1];
        float r0 = srow[rj]   * qinv * q_scale[rj]   * sgn;
        float r1 = srow[rj+1] * qinv * q_scale[rj+1] * sgn;
        float v0 = x0 * cs[dd]   + r0 * sn[dd];
        float v1 = x1 * cs[dd+1] + r1 * sn[dd+1];
        size_t o = (((size_t)b * H_ + h) * S_ + s) * DH_ + dd;
        uint32_t lo, hi = packsplit(v0, v1, lo);
        *(uint32_t*)(g_qh + o) = hi;
        *(uint32_t*)(g_ql + o) = lo;
    }
    for (int i2 = tid; i2 < KVD_ / 2; i2 += 256) {
        int i = i2 * 2;
        int h = i >> 7, dd = i & 127;
        int rj = (dd < 64) ? (i + 64) : (i - 64);
        float sgn = (dd < 64) ? -1.f : 1.f;
        float x0 = srow[D_ + i]   * kinv * k_scale[i];
        float x1 = srow[D_ + i+1] * kinv * k_scale[i+1];
        float r0 = srow[D_ + rj]   * kinv * k_scale[rj]   * sgn;
        float r1 = srow[D_ + rj+1] * kinv * k_scale[rj+1] * sgn;
        float v0 = x0 * cs[dd]   + r0 * sn[dd];
        float v1 = x1 * cs[dd+1] + r1 * sn[dd+1];
        size_t o = (((size_t)b * KVH_ + h) * S_ + s) * DH_ + dd;
        uint32_t lo, hi = packsplit(v0, v1, lo);
        *(uint32_t*)(g_kh + o) = hi;
        *(uint32_t*)(g_kl + o) = lo;
    }
    for (int i2 = tid; i2 < KVD_ / 2; i2 += 256) {
        int i = i2 * 2;
        int h = i >> 7, dd = i & 127;
        size_t o = (((size_t)b * KVH_ + h) * S_ + s) * DH_ + dd;
        uint32_t lo, hi = packsplit(srow[D_ + KVD_ + i], srow[D_ + KVD_ + i + 1], lo);
        *(uint32_t*)(g_vh + o) = hi;
        *(uint32_t*)(g_vl + o) = lo;
    }
}

// ---------------- tensor-core flash attention (causal, split-bf16 3xMMA) ----------------
#define AT_QH   0
#define AT_QL   16384
#define AT_KV   32768
#define AKV_STG 65536
#define AT_SO   (AT_KV + 2*AKV_STG)      // fp32 [64][132]
#define SO_STRIDE 132
#define AT_RED  (AT_SO + 64*SO_STRIDE*4)
#define ATT_SMEM (AT_RED + 1024 + 128)

__global__ __launch_bounds__(256, 1) void attn_mma() {
    extern __shared__ char dsmem[];
    const int bh = blockIdx.x;
    const int b = bh / H_;
    const int h = bh % H_;
    const int kvh = h / (H_ / KVH_);
    const int qb = (S_ / 64 - 1) - blockIdx.y;   // heavy blocks first
    const int tid = threadIdx.x;
    const int lane = tid & 31;
    const int wid = tid >> 5;
    const int warp_m = wid >> 1;
    const int warp_n = wid & 1;

    uint32_t db = smem_u32(dsmem);
    uint32_t sbase = (db + 127u) & ~127u;
    float* sO   = (float*)(dsmem + (sbase - db) + AT_SO);
    float* redm = (float*)(dsmem + (sbase - db) + AT_RED);
    float* redl = redm + 128;

    const __nv_bfloat16* QhG = g_qh + (((size_t)b * H_ + h) * S_ + (size_t)qb * 64) * DH_;
    const __nv_bfloat16* QlG = g_ql + (((size_t)b * H_ + h) * S_ + (size_t)qb * 64) * DH_;
    const __nv_bfloat16* KhB = g_kh + ((size_t)b * KVH_ + kvh) * S_ * DH_;
    const __nv_bfloat16* KlB = g_kl + ((size_t)b * KVH_ + kvh) * S_ * DH_;
    const __nv_bfloat16* VhB = g_vh + ((size_t)b * KVH_ + kvh) * S_ * DH_;
    const __nv_bfloat16* VlB = g_vl + ((size_t)b * KVH_ + kvh) * S_ * DH_;

    #pragma unroll
    for (int i = 0; i < 4; i++) {
        int idx = tid + i * 256;
        int row = idx >> 4, ch = idx & 15;
        uint32_t sw = swz256(row, ch);
        size_t g = (size_t)row * DH_ + ch * 8;
        CP_ASYNC16(sbase + AT_QH + sw, QhG + g);
        CP_ASYNC16(sbase + AT_QL + sw, QlG + g);
    }
    auto load_kv = [&](int buf, int jt) {
        uint32_t sb = sbase + AT_KV + (uint32_t)buf * AKV_STG;
        size_t gb = (size_t)jt * 64 * DH_;
        #pragma unroll
        for (int i = 0; i < 4; i++) {
            int idx = tid + i * 256;
            int row = idx >> 4, ch = idx & 15;
            uint32_t sw = swz256(row, ch);
            size_t g = gb + (size_t)row * DH_ + ch * 8;
            CP_ASYNC16(sb +         sw, KhB + g);
            CP_ASYNC16(sb + 16384 + sw, KlB + g);
            CP_ASYNC16(sb + 32768 + sw, VhB + g);
            CP_ASYNC16(sb + 49152 + sw, VlB + g);
        }
    };
    load_kv(0, 0);
    CP_COMMIT();

    float oacc[16][4];
    #pragma unroll
    for (int nt = 0; nt < 16; nt++)
        #pragma unroll
        for (int j = 0; j < 4; j++) oacc[nt][j] = 0.f;
    float m0 = -1e30f, m1 = -1e30f, l0 = 0.f, l1 = 0.f;

    const int gr  = lane >> 2;
    const int rI0 = warp_m * 16 + gr;
    const int nj = qb + 1;

    for (int jt = 0; jt < nj; jt++) {
        const int buf = jt & 1;
        CP_WAIT(0);
        __syncthreads();
        if (jt + 1 < nj) { load_kv(buf ^ 1, jt + 1); CP_COMMIT(); }

        const uint32_t sQH = sbase + AT_QH, sQL = sbase + AT_QL;
        const uint32_t kb = sbase + AT_KV + (uint32_t)buf * AKV_STG;
        const uint32_t sKH = kb, sKL = kb + 16384, sVH = kb + 32768, sVL = kb + 49152;

        float sacc[4][4];
        #pragma unroll
        for (int nt = 0; nt < 4; nt++)
            #pragma unroll
            for (int j = 0; j < 4; j++) sacc[nt][j] = 0.f;

        #pragma unroll
        for (int kt = 0; kt < 8; kt++) {
            uint32_t qh4[4], ql4[4], kbh[2][4], kbl[2][4];
            int qrow = warp_m * 16 + (lane & 15);
            int qch  = kt * 2 + (lane >> 4);
            ldsm_x4(qh4, sQH + swz256(qrow, qch));
            ldsm_x4(ql4, sQL + swz256(qrow, qch));
            #pragma unroll
            for (int ng = 0; ng < 2; ng++) {
                int krow = warp_n * 32 + ng * 16 + (lane & 7) + (lane >> 4) * 8;
                int kch  = kt * 2 + ((lane >> 3) & 1);
                ldsm_x4(kbh[ng], sKH + swz256(krow, kch));
                ldsm_x4(kbl[ng], sKL + swz256(krow, kch));
            }
            #pragma unroll
            for (int ng = 0; ng < 2; ng++)
                #pragma unroll
                for (int s = 0; s < 2; s++) {
                    float* a = sacc[ng * 2 + s];
                    mma16816(a, qh4, &kbh[ng][s * 2]);
                    mma16816(a, qh4, &kbl[ng][s * 2]);
                    mma16816(a, ql4, &kbh[ng][s * 2]);
                }
        }

        #pragma unroll
        for (int nt = 0; nt < 4; nt++)
            #pragma unroll
            for (int j = 0; j < 4; j++) sacc[nt][j] *= SCALING_;
        if (jt == qb) {
            int r0g = qb * 64 + rI0;
            #pragma unroll
            for (int nt = 0; nt < 4; nt++) {
                int c = jt * 64 + warp_n * 32 + nt * 8 + (lane & 3) * 2;
                if (c     > r0g)     sacc[nt][0] = -1e30f;
                if (c + 1 > r0g)     sacc[nt][1] = -1e30f;
                if (c     > r0g + 8) sacc[nt][2] = -1e30f;
                if (c + 1 > r0g + 8) sacc[nt][3] = -1e30f;
            }
        }

        float pm0 = -1e30f, pm1 = -1e30f;
        #pragma unroll
        for (int nt = 0; nt < 4; nt++) {
            pm0 = fmaxf(pm0, fmaxf(sacc[nt][0], sacc[nt][1]));
            pm1 = fmaxf(pm1, fmaxf(sacc[nt][2], sacc[nt][3]));
        }
        pm0 = fmaxf(pm0, __shfl_xor_sync(0xFFFFFFFFu, pm0, 1));
        pm0 = fmaxf(pm0, __shfl_xor_sync(0xFFFFFFFFu, pm0, 2));
        pm1 = fmaxf(pm1, __shfl_xor_sync(0xFFFFFFFFu, pm1, 1));
        pm1 = fmaxf(pm1, __shfl_xor_sync(0xFFFFFFFFu, pm1, 2));
        if ((lane & 3) == 0) {
            redm[warp_n * 64 + rI0]     = pm0;
            redm[warp_n * 64 + rI0 + 8] = pm1;
        }
        __syncthreads();
        float mt0 = fmaxf(redm[rI0],     redm[64 + rI0]);
        float mt1 = fmaxf(redm[rI0 + 8], redm[64 + rI0 + 8]);

        float mn0 = fmaxf(m0, mt0), mn1 = fmaxf(m1, mt1);
        float c0 = __expf(m0 - mn0), c1 = __expf(m1 - mn1);

        float ps0 = 0.f, ps1 = 0.f;
        #pragma unroll
        for (int nt = 0; nt < 4; nt++) {
            sacc[nt][0] = __expf(sacc[nt][0] - mn0);
            sacc[nt][1] = __expf(sacc[nt][1] - mn0);
            sacc[nt][2] = __expf(sacc[nt][2] - mn1);
            sacc[nt][3] = __expf(sacc[nt][3] - mn1);
            ps0 += sacc[nt][0] + sacc[nt][1];
            ps1 += sacc[nt][2] + sacc[nt][3];
        }
        ps0 += __shfl_xor_sync(0xFFFFFFFFu, ps0, 1);
        ps0 += __shfl_xor_sync(0xFFFFFFFFu, ps0, 2);
        ps1 += __shfl_xor_sync(0xFFFFFFFFu, ps1, 1);
        ps1 += __shfl_xor_sync(0xFFFFFFFFu, ps1, 2);
        if ((lane & 3) == 0) {
            redl[warp_n * 64 + rI0]     = ps0;
            redl[warp_n * 64 + rI0 + 8] = ps1;
        }
        __syncthreads();
        l0 = l0 * c0 + redl[rI0]     + redl[64 + rI0];
        l1 = l1 * c1 + redl[rI0 + 8] + redl[64 + rI0 + 8];
        m0 = mn0; m1 = mn1;

        #pragma unroll
        for (int nt = 0; nt < 16; nt++) {
            oacc[nt][0] *= c0; oacc[nt][1] *= c0;
            oacc[nt][2] *= c1; oacc[nt][3] *= c1;
        }

        uint32_t pah[2][4], pal[2][4];
        #pragma unroll
        for (int kt = 0; kt < 2; kt++) {
            pah[kt][0] = packsplit(sacc[2*kt][0],   sacc[2*kt][1],   pal[kt][0]);
            pah[kt][1] = packsplit(sacc[2*kt][2],   sacc[2*kt][3],   pal[kt][1]);
            pah[kt][2] = packsplit(sacc[2*kt+1][0], sacc[2*kt+1][1], pal[kt][2]);
            pah[kt][3] = packsplit(sacc[2*kt+1][2], sacc[2*kt+1][3], pal[kt][3]);
        }

        #pragma unroll
        for (int ndg = 0; ndg < 8; ndg++) {
            #pragma unroll
            for (int kt = 0; kt < 2; kt++) {
                uint32_t vh4[4], vl4[4];
                int vrow = warp_n * 32 + kt * 16 + (lane & 15);
                int vch  = ndg * 2 + (lane >> 4);
                ldsm_x4_t(vh4, sVH + swz256(vrow, vch));
                ldsm_x4_t(vl4, sVL + swz256(vrow, vch));
                #pragma unroll
                for (int hf = 0; hf < 2; hf++) {
                    float* o = oacc[ndg * 2 + hf];
                    mma16816(o, pah[kt], &vh4[hf * 2]);
                    mma16816(o, pah[kt], &vl4[hf * 2]);
                    mma16816(o, pal[kt], &vh4[hf * 2]);
                }
            }
        }
    }

    __syncthreads();
    if (warp_n == 0) {
        #pragma unroll
        for (int nt = 0; nt < 16; nt++) {
            int d = nt * 8 + (lane & 3) * 2;
            *(float2*)&sO[(size_t)rI0 * SO_STRIDE + d]       = make_float2(oacc[nt][0], oacc[nt][1]);
            *(float2*)&sO[(size_t)(rI0 + 8) * SO_STRIDE + d] = make_float2(oacc[nt][2], oacc[nt][3]);
        }
    }
    __syncthreads();
    if (warp_n == 1) {
        float inv0 = 1.0f / l0, inv1 = 1.0f / l1;
        size_t row0g = (size_t)b * S_ + qb * 64 + rI0;
        size_t row1g = row0g + 8;
        #pragma unroll
        for (int nt = 0; nt < 16; nt++) {
            int d = nt * 8 + (lane & 3) * 2;
            float2 t0 = *(float2*)&sO[(size_t)rI0 * SO_STRIDE + d];
            float2 t1 = *(float2*)&sO[(size_t)(rI0 + 8) * SO_STRIDE + d];
            float v00 = (t0.x + oacc[nt][0]) * inv0;
            float v01 = (t0.y + oacc[nt][1]) * inv0;
            float v10 = (t1.x + oacc[nt][2]) * inv1;
            float v11 = (t1.y + oacc[nt][3]) * inv1;
            size_t o0 = row0g * D_ + h * DH_ + d;
            size_t o1 = row1g * D_ + h * DH_ + d;
            uint32_t lo0, lo1;
            uint32_t hi0 = packsplit(v00, v01, lo0);
            uint32_t hi1 = packsplit(v10, v11, lo1);
            *(uint32_t*)(g_ah + o0) = hi0;
            *(uint32_t*)(g_al + o0) = lo0;
            *(uint32_t*)(g_ah + o1) = hi1;
            *(uint32_t*)(g_al + o1) = lo1;
        }
    }
}

// ---------------- launch ----------------
extern "C" void kernel_launch(void* const* d_in, const int* in_sizes, int n_in,
                              void* d_out, int out_size) {
    const float* hidden  = (const float*)d_in[0];
    const float* w_qkv   = (const float*)d_in[1];
    const float* w_out   = (const float*)d_in[2];
    const float* q_scale = (const float*)d_in[3];
    const float* k_scale = (const float*)d_in[4];
    const float* cosc    = (const float*)d_in[5];
    const float* sinc    = (const float*)d_in[6];
    float* out = (float*)d_out;

    float* p_part;
    __nv_bfloat16 *p_ah, *p_al, *p_wth, *p_wtl;
    cudaGetSymbolAddress((void**)&p_part, g_part);
    cudaGetSymbolAddress((void**)&p_ah,   g_ah);
    cudaGetSymbolAddress((void**)&p_al,   g_al);
    cudaGetSymbolAddress((void**)&p_wth,  g_wth);
    cudaGetSymbolAddress((void**)&p_wtl,  g_wtl);

    cudaFuncSetAttribute(gemm_mma, cudaFuncAttributeMaxDynamicSharedMemorySize, GSMEM_SZ);
    cudaFuncSetAttribute(attn_mma, cudaFuncAttributeMaxDynamicSharedMemorySize, ATT_SMEM);

    // 1) split hidden ; transpose+split w_qkv
    split_bf16<<<(MROWS * (size_t)D_) / (256 * 4), 256>>>(hidden, p_ah, p_al);
    {
        dim3 g(QKVN / 32, D_ / 32);
        transpose_split<<<g, dim3(32, 8)>>>(w_qkv, p_wth, p_wtl, D_, QKVN);
    }
    // 2) QKV projection, split-K=2 -> partials
    {
        dim3 g(QKVN / 256, MROWS / 128, 2);
        gemm_mma<<<g, 256, GSMEM_SZ>>>(p_ah, p_al, p_wth, p_wtl, p_part, QKVN, D_);
    }
    // 3) fused reduce + RMSNorm + RoPE -> split-bf16 q/k/v
    norm_rope_kernel<<<B_ * S_, 256>>>(p_part, q_scale, k_scale, cosc, sinc);
    // 4) tensor-core flash attention (heavy-first) -> g_ah/g_al
    {
        dim3 g(B_ * H_, S_ / 64);
        attn_mma<<<g, 256, ATT_SMEM>>>();
    }
    // 5) transpose+split w_out ; out projection split-K=2 -> partials ; reduce -> out
    {
        dim3 g(D_ / 32, D_ / 32);
        transpose_split<<<g, dim3(32, 8)>>>(w_out, p_wth, p_wtl, D_, D_);
    }
    {
        dim3 g(D_ / 256, MROWS / 128, 2);
        gemm_mma<<<g, 256, GSMEM_SZ>>>(p_ah, p_al, p_wth, p_wtl, p_part, D_, D_);
    }
    reduce_add<<<(MROWS * (size_t)D_) / (256 * 4), 256>>>(p_part, out, (size_t)MROWS * D_);
}

// round 11
// speedup vs baseline: 3.8405x; 1.0917x over previous
#include <cuda_runtime.h>
#include <cuda_bf16.h>
#include <cuda_fp16.h>
#include <cstdint>
#include <cstddef>

#define B_    2
#define S_    2048
#define D_    4096
#define H_    32
#define KVH_  8
#define DH_   128
#define KVD_  (KVH_*DH_)          // 1024
#define QKVN  (D_ + 2*KVD_)       // 6144
#define MROWS (B_*S_)             // 4096
#define EPS_  1e-6f
#define SCALING_ 0.08838834764831845f  // 128^-0.5

// ---------------- scratch (device globals; no runtime allocation) ----------------
__device__ float g_part[(size_t)2*MROWS*QKVN];       // split-K partials (reused)
__device__ __nv_bfloat16 g_qh[(size_t)B_*H_*S_*DH_];
__device__ __nv_bfloat16 g_ql[(size_t)B_*H_*S_*DH_];
__device__ __nv_bfloat16 g_kh[(size_t)B_*KVH_*S_*DH_];
__device__ __nv_bfloat16 g_kl[(size_t)B_*KVH_*S_*DH_];
__device__ __nv_bfloat16 g_vh[(size_t)B_*KVH_*S_*DH_];
__device__ __nv_bfloat16 g_vl[(size_t)B_*KVH_*S_*DH_];
__device__ __nv_bfloat16 g_ah[(size_t)MROWS*D_];     // hidden hi (QKV input)
__device__ __nv_bfloat16 g_al[(size_t)MROWS*D_];     // hidden lo
__device__ __half        g_a16[(size_t)MROWS*D_];    // attention output, fp16 single
__device__ __nv_bfloat16 g_wth[(size_t)QKVN*D_];     // W^T hi  [N,K] (bf16 or fp16 reinterpret)
__device__ __nv_bfloat16 g_wtl[(size_t)QKVN*D_];     // W^T lo  [N,K]

// ---------------- ptx helpers ----------------
__device__ __forceinline__ uint32_t smem_u32(const void* p) {
    uint32_t a;
    asm("{ .reg .u64 t; cvta.to.shared.u64 t, %1; cvt.u32.u64 %0, t; }" : "=r"(a) : "l"(p));
    return a;
}
#define CP_ASYNC16(dst, src) \
    asm volatile("cp.async.cg.shared.global [%0], [%1], 16;" :: "r"(dst), "l"(src))
#define CP_COMMIT() asm volatile("cp.async.commit_group;" ::: "memory")
#define CP_WAIT(n)  asm volatile("cp.async.wait_group %0;" :: "n"(n) : "memory")

__device__ __forceinline__ void ldsm_x4(uint32_t* r, uint32_t addr) {
    asm volatile("ldmatrix.sync.aligned.m8n8.x4.shared.b16 {%0,%1,%2,%3}, [%4];"
        : "=r"(r[0]), "=r"(r[1]), "=r"(r[2]), "=r"(r[3]) : "r"(addr));
}
__device__ __forceinline__ void ldsm_x4_t(uint32_t* r, uint32_t addr) {
    asm volatile("ldmatrix.sync.aligned.m8n8.x4.trans.shared.b16 {%0,%1,%2,%3}, [%4];"
        : "=r"(r[0]), "=r"(r[1]), "=r"(r[2]), "=r"(r[3]) : "r"(addr));
}
__device__ __forceinline__ void mma16816(float* c, const uint32_t* a, const uint32_t* b) {
    asm volatile(
        "mma.sync.aligned.m16n8k16.row.col.f32.bf16.bf16.f32 "
        "{%0,%1,%2,%3}, {%4,%5,%6,%7}, {%8,%9}, {%0,%1,%2,%3};"
        : "+f"(c[0]), "+f"(c[1]), "+f"(c[2]), "+f"(c[3])
        : "r"(a[0]), "r"(a[1]), "r"(a[2]), "r"(a[3]), "r"(b[0]), "r"(b[1]));
}
__device__ __forceinline__ void mma16816h(float* c, const uint32_t* a, const uint32_t* b) {
    asm volatile(
        "mma.sync.aligned.m16n8k16.row.col.f32.f16.f16.f32 "
        "{%0,%1,%2,%3}, {%4,%5,%6,%7}, {%8,%9}, {%0,%1,%2,%3};"
        : "+f"(c[0]), "+f"(c[1]), "+f"(c[2]), "+f"(c[3])
        : "r"(a[0]), "r"(a[1]), "r"(a[2]), "r"(a[3]), "r"(b[0]), "r"(b[1]));
}

// swizzle for 64B-row tiles (GEMM): 4 chunks of 16B per row
__device__ __forceinline__ uint32_t swz(int row, int chunk) {
    return (uint32_t)row * 64u + (uint32_t)((chunk ^ ((row >> 1) & 3)) * 16);
}
// swizzle for 256B-row tiles (attention): 16 chunks of 16B
__device__ __forceinline__ uint32_t swz256(int row, int chunk) {
    return (uint32_t)row * 256u + (uint32_t)((chunk ^ (row & 7)) * 16);
}
// split fp32 -> packed bf16x2 hi with lo out-param
__device__ __forceinline__ uint32_t packsplit(float a, float b, uint32_t& lo) {
    __nv_bfloat16 ha = __float2bfloat16(a), hb = __float2bfloat16(b);
    __nv_bfloat16 la = __float2bfloat16(a - __bfloat162float(ha));
    __nv_bfloat16 lb = __float2bfloat16(b - __bfloat162float(hb));
    uint16_t uha = *(uint16_t*)&ha, uhb = *(uint16_t*)&hb;
    uint16_t ula = *(uint16_t*)&la, ulb = *(uint16_t*)&lb;
    lo = (uint32_t)ula | ((uint32_t)ulb << 16);
    return (uint32_t)uha | ((uint32_t)uhb << 16);
}
__device__ __forceinline__ uint32_t pack_half2(float a, float b) {
    __half ha = __float2half_rn(a), hb = __float2half_rn(b);
    uint16_t ua = *(uint16_t*)&ha, ub = *(uint16_t*)&hb;
    return (uint32_t)ua | ((uint32_t)ub << 16);
}

// ---------------- elementwise split fp32 -> (hi,lo) bf16 ----------------
__global__ __launch_bounds__(256) void split_bf16(const float* __restrict__ x,
                                                  __nv_bfloat16* __restrict__ hi,
                                                  __nv_bfloat16* __restrict__ lo) {
    size_t i = ((size_t)blockIdx.x * 256 + threadIdx.x) * 4;
    float4 v = *(const float4*)(x + i);
    uint32_t lo0, lo1;
    uint32_t hi0 = packsplit(v.x, v.y, lo0);
    uint32_t hi1 = packsplit(v.z, v.w, lo1);
    *(uint32_t*)(hi + i)     = hi0;
    *(uint32_t*)(hi + i + 2) = hi1;
    *(uint32_t*)(lo + i)     = lo0;
    *(uint32_t*)(lo + i + 2) = lo1;
}

// ---------------- final reduce for split-K out-projection ----------------
__global__ __launch_bounds__(256) void reduce_add(const float* __restrict__ p,
                                                  float* __restrict__ out, size_t n) {
    size_t i = ((size_t)blockIdx.x * 256 + threadIdx.x) * 4;
    float4 a = *(const float4*)(p + i);
    float4 b = *(const float4*)(p + n + i);
    *(float4*)(out + i) = make_float4(a.x + b.x, a.y + b.y, a.z + b.z, a.w + b.w);
}

// ---------------- transpose + split: W[K,N] -> T[N,K] hi/lo (bf16) ----------------
__global__ __launch_bounds__(256) void transpose_split(const float* __restrict__ W,
                                                       __nv_bfloat16* __restrict__ Th,
                                                       __nv_bfloat16* __restrict__ Tl,
                                                       int K, int N) {
    __shared__ float t[32][33];
    const int n0 = blockIdx.x * 32, k0 = blockIdx.y * 32;
    const int tx = threadIdx.x, ty = threadIdx.y;
    #pragma unroll
    for (int i = 0; i < 32; i += 8)
        t[ty + i][tx] = W[(size_t)(k0 + ty + i) * N + n0 + tx];
    __syncthreads();
    #pragma unroll
    for (int i = 0; i < 32; i += 8) {
        float v = t[tx][ty + i];
        __nv_bfloat16 h = __float2bfloat16(v);
        size_t o = (size_t)(n0 + ty + i) * K + k0 + tx;
        Th[o] = h;
        Tl[o] = __float2bfloat16(v - __bfloat162float(h));
    }
}

// ---------------- transpose + split fp16: W[K,N] -> T[N,K] hi/lo (half) ----------------
__global__ __launch_bounds__(256) void transpose_split_f16(const float* __restrict__ W,
                                                           __half* __restrict__ Th,
                                                           __half* __restrict__ Tl,
                                                           int K, int N) {
    __shared__ float t[32][33];
    const int n0 = blockIdx.x * 32, k0 = blockIdx.y * 32;
    const int tx = threadIdx.x, ty = threadIdx.y;
    #pragma unroll
    for (int i = 0; i < 32; i += 8)
        t[ty + i][tx] = W[(size_t)(k0 + ty + i) * N + n0 + tx];
    __syncthreads();
    #pragma unroll
    for (int i = 0; i < 32; i += 8) {
        float v = t[tx][ty + i];
        __half h = __float2half_rn(v);
        size_t o = (size_t)(n0 + ty + i) * K + k0 + tx;
        Th[o] = h;
        Tl[o] = __float2half_rn(v - __half2float(h));
    }
}

// ---------------- bf16 3-MMA GEMM (QKV), 4-stage cp.async, split-K=2 ----------------
#define A_TILE_B 8192
#define B_TILE_B 16384
#define GBUF_B   (2*A_TILE_B + 2*B_TILE_B)     // 48KB / stage
#define NSTAGE   4
#define GSMEM_SZ (NSTAGE*GBUF_B + 1024)

__global__ __launch_bounds__(256, 1) void gemm_mma(const __nv_bfloat16* __restrict__ Ah,
                                                   const __nv_bfloat16* __restrict__ Al,
                                                   const __nv_bfloat16* __restrict__ Bh,
                                                   const __nv_bfloat16* __restrict__ Bl,
                                                   float* __restrict__ C, int N, int K) {
    extern __shared__ char dsmem[];
    const int tid  = threadIdx.x;
    const int lane = tid & 31;
    const int wid  = tid >> 5;
    const int wm   = (wid >> 2) * 64;
    const int wn   = (wid & 3) * 64;
    const int row0 = blockIdx.y * 128;
    const int col0 = blockIdx.x * 256;

    const int Khalf = K >> 1;
    const size_t koff = (size_t)blockIdx.z * Khalf;
    Ah += koff; Al += koff; Bh += koff; Bl += koff;
    C  += (size_t)blockIdx.z * (size_t)MROWS * N;

    uint32_t db = smem_u32(dsmem);
    uint32_t sbase = (db + 127u) & ~127u;

    float acc[4][8][4];
    #pragma unroll
    for (int mt = 0; mt < 4; mt++)
        #pragma unroll
        for (int nt = 0; nt < 8; nt++)
            #pragma unroll
            for (int j = 0; j < 4; j++) acc[mt][nt][j] = 0.f;

    const int NK = Khalf / 32;

    auto load_tiles = [&](int buf, int kt) {
        const uint32_t bb = sbase + (uint32_t)buf * GBUF_B;
        const int k0 = kt * 32;
        #pragma unroll
        for (int i = 0; i < 2; i++) {
            int idx = tid + i * 256;
            int row = idx >> 2, ch = idx & 3;
            uint32_t sw = swz(row, ch);
            size_t g = (size_t)(row0 + row) * K + k0 + ch * 8;
            CP_ASYNC16(bb + sw,            Ah + g);
            CP_ASYNC16(bb + A_TILE_B + sw, Al + g);
        }
        #pragma unroll
        for (int i = 0; i < 4; i++) {
            int idx = tid + i * 256;
            int row = idx >> 2, ch = idx & 3;
            uint32_t sw = swz(row, ch);
            size_t g = (size_t)(col0 + row) * K + k0 + ch * 8;
            CP_ASYNC16(bb + 2*A_TILE_B + sw,            Bh + g);
            CP_ASYNC16(bb + 2*A_TILE_B + B_TILE_B + sw, Bl + g);
        }
    };

    #pragma unroll
    for (int s = 0; s < NSTAGE - 1; s++) { load_tiles(s, s); CP_COMMIT(); }

    const int mat = lane >> 3;
    const int wi  = lane & 7;

    for (int kt = 0; kt < NK; kt++) {
        CP_WAIT(NSTAGE - 2);
        __syncthreads();
        {
            int pf = kt + NSTAGE - 1;
            if (pf < NK) load_tiles(pf & (NSTAGE - 1), pf);
            CP_COMMIT();
        }

        const uint32_t bb = sbase + (uint32_t)(kt & (NSTAGE - 1)) * GBUF_B;
        const uint32_t aH = bb, aL = bb + A_TILE_B;
        const uint32_t bH = bb + 2*A_TILE_B, bL = bH + B_TILE_B;

        #pragma unroll
        for (int kh = 0; kh < 2; kh++) {
            uint32_t ah[4][4], al[4][4], bh[4][4], bl[4][4];
            #pragma unroll
            for (int mt = 0; mt < 4; mt++) {
                int row = wm + mt * 16 + wi + (mat & 1) * 8;
                int ch  = kh * 2 + (mat >> 1);
                uint32_t sw = swz(row, ch);
                ldsm_x4(ah[mt], aH + sw);
                ldsm_x4(al[mt], aL + sw);
            }
            #pragma unroll
            for (int np = 0; np < 4; np++) {
                int row = wn + np * 16 + wi + (mat >> 1) * 8;
                int ch  = kh * 2 + (mat & 1);
                uint32_t sw = swz(row, ch);
                ldsm_x4(bh[np], bH + sw);
                ldsm_x4(bl[np], bL + sw);
            }
            #pragma unroll
            for (int mt = 0; mt < 4; mt++)
                #pragma unroll
                for (int np = 0; np < 4; np++)
                    #pragma unroll
                    for (int s = 0; s < 2; s++) {
                        float* a = acc[mt][np * 2 + s];
                        mma16816(a, ah[mt], &bh[np][s * 2]);
                        mma16816(a, ah[mt], &bl[np][s * 2]);
                        mma16816(a, al[mt], &bh[np][s * 2]);
                    }
        }
    }

    #pragma unroll
    for (int mt = 0; mt < 4; mt++)
        #pragma unroll
        for (int nt = 0; nt < 8; nt++) {
            int m = row0 + wm + mt * 16 + (lane >> 2);
            int n = col0 + wn + nt * 8 + (lane & 3) * 2;
            float* a = acc[mt][nt];
            *(float2*)(C + (size_t)m * N + n)       = make_float2(a[0], a[1]);
            *(float2*)(C + (size_t)(m + 8) * N + n) = make_float2(a[2], a[3]);
        }
}

// ---------------- fp16 2-MMA GEMM (out-proj): A single fp16, B split hi/lo ----------------
#define HBUF_B   (A_TILE_B + 2*B_TILE_B)       // 40KB / stage
#define HSMEM_SZ (NSTAGE*HBUF_B + 1024)

__global__ __launch_bounds__(256, 1) void gemm_mma_a16(const __half* __restrict__ A,
                                                       const __half* __restrict__ Bh,
                                                       const __half* __restrict__ Bl,
                                                       float* __restrict__ C, int N, int K) {
    extern __shared__ char dsmem[];
    const int tid  = threadIdx.x;
    const int lane = tid & 31;
    const int wid  = tid >> 5;
    const int wm   = (wid >> 2) * 64;
    const int wn   = (wid & 3) * 64;
    const int row0 = blockIdx.y * 128;
    const int col0 = blockIdx.x * 256;

    const int Khalf = K >> 1;
    const size_t koff = (size_t)blockIdx.z * Khalf;
    A += koff; Bh += koff; Bl += koff;
    C += (size_t)blockIdx.z * (size_t)MROWS * N;

    uint32_t db = smem_u32(dsmem);
    uint32_t sbase = (db + 127u) & ~127u;

    float acc[4][8][4];
    #pragma unroll
    for (int mt = 0; mt < 4; mt++)
        #pragma unroll
        for (int nt = 0; nt < 8; nt++)
            #pragma unroll
            for (int j = 0; j < 4; j++) acc[mt][nt][j] = 0.f;

    const int NK = Khalf / 32;

    auto load_tiles = [&](int buf, int kt) {
        const uint32_t bb = sbase + (uint32_t)buf * HBUF_B;
        const int k0 = kt * 32;
        #pragma unroll
        for (int i = 0; i < 2; i++) {
            int idx = tid + i * 256;
            int row = idx >> 2, ch = idx & 3;
            uint32_t sw = swz(row, ch);
            size_t g = (size_t)(row0 + row) * K + k0 + ch * 8;
            CP_ASYNC16(bb + sw, A + g);
        }
        #pragma unroll
        for (int i = 0; i < 4; i++) {
            int idx = tid + i * 256;
            int row = idx >> 2, ch = idx & 3;
            uint32_t sw = swz(row, ch);
            size_t g = (size_t)(col0 + row) * K + k0 + ch * 8;
            CP_ASYNC16(bb + A_TILE_B + sw,            Bh + g);
            CP_ASYNC16(bb + A_TILE_B + B_TILE_B + sw, Bl + g);
        }
    };

    #pragma unroll
    for (int s = 0; s < NSTAGE - 1; s++) { load_tiles(s, s); CP_COMMIT(); }

    const int mat = lane >> 3;
    const int wi  = lane & 7;

    for (int kt = 0; kt < NK; kt++) {
        CP_WAIT(NSTAGE - 2);
        __syncthreads();
        {
            int pf = kt + NSTAGE - 1;
            if (pf < NK) load_tiles(pf & (NSTAGE - 1), pf);
            CP_COMMIT();
        }

        const uint32_t bb = sbase + (uint32_t)(kt & (NSTAGE - 1)) * HBUF_B;
        const uint32_t aT = bb;
        const uint32_t bH = bb + A_TILE_B, bL = bH + B_TILE_B;

        #pragma unroll
        for (int kh = 0; kh < 2; kh++) {
            uint32_t ah[4][4], bh[4][4], bl[4][4];
            #pragma unroll
            for (int mt = 0; mt < 4; mt++) {
                int row = wm + mt * 16 + wi + (mat & 1) * 8;
                int ch  = kh * 2 + (mat >> 1);
                ldsm_x4(ah[mt], aT + swz(row, ch));
            }
            #pragma unroll
            for (int np = 0; np < 4; np++) {
                int row = wn + np * 16 + wi + (mat >> 1) * 8;
                int ch  = kh * 2 + (mat & 1);
                uint32_t sw = swz(row, ch);
                ldsm_x4(bh[np], bH + sw);
                ldsm_x4(bl[np], bL + sw);
            }
            #pragma unroll
            for (int mt = 0; mt < 4; mt++)
                #pragma unroll
                for (int np = 0; np < 4; np++)
                    #pragma unroll
                    for (int s = 0; s < 2; s++) {
                        float* a = acc[mt][np * 2 + s];
                        mma16816h(a, ah[mt], &bh[np][s * 2]);
                        mma16816h(a, ah[mt], &bl[np][s * 2]);
                    }
        }
    }

    #pragma unroll
    for (int mt = 0; mt < 4; mt++)
        #pragma unroll
        for (int nt = 0; nt < 8; nt++) {
            int m = row0 + wm + mt * 16 + (lane >> 2);
            int n = col0 + wn + nt * 8 + (lane & 3) * 2;
            float* a = acc[mt][nt];
            *(float2*)(C + (size_t)m * N + n)       = make_float2(a[0], a[1]);
            *(float2*)(C + (size_t)(m + 8) * N + n) = make_float2(a[2], a[3]);
        }
}

// ---------------- fused split-K reduce + RMSNorm + RoPE + split-bf16 scatter ----------------
__global__ __launch_bounds__(256) void norm_rope_kernel(const float* __restrict__ part,
                                                        const float* __restrict__ q_scale,
                                                        const float* __restrict__ k_scale,
                                                        const float* __restrict__ cosc,
                                                        const float* __restrict__ sinc) {
    __shared__ float srow[QKVN];
    __shared__ float red[256];
    __shared__ float s_qinv, s_kinv;
    const int bs = blockIdx.x;
    const int b = bs / S_;
    const int s = bs % S_;
    const int tid = threadIdx.x;
    const float* p0 = part + (size_t)bs * QKVN;
    const float* p1 = part + (size_t)MROWS * QKVN + (size_t)bs * QKVN;

    for (int i = tid * 4; i < QKVN; i += 1024) {
        float4 a = *(const float4*)(p0 + i);
        float4 c = *(const float4*)(p1 + i);
        *(float4*)(srow + i) = make_float4(a.x + c.x, a.y + c.y, a.z + c.z, a.w + c.w);
    }
    __syncthreads();

    float ss = 0.f;
    for (int i = tid * 4; i < D_; i += 1024) {
        float4 v = *(const float4*)(srow + i);
        ss += v.x*v.x + v.y*v.y + v.z*v.z + v.w*v.w;
    }
    red[tid] = ss; __syncthreads();
    for (int st = 128; st > 0; st >>= 1) { if (tid < st) red[tid] += red[tid + st]; __syncthreads(); }
    if (tid == 0) s_qinv = rsqrtf(red[0] / (float)D_ + EPS_);
    __syncthreads();

    ss = 0.f;
    for (int i = tid * 4; i < KVD_; i += 1024) {
        float4 v = *(const float4*)(srow + D_ + i);
        ss += v.x*v.x + v.y*v.y + v.z*v.z + v.w*v.w;
    }
    red[tid] = ss; __syncthreads();
    for (int st = 128; st > 0; st >>= 1) { if (tid < st) red[tid] += red[tid + st]; __syncthreads(); }
    if (tid == 0) s_kinv = rsqrtf(red[0] / (float)KVD_ + EPS_);
    __syncthreads();

    const float qinv = s_qinv, kinv = s_kinv;
    const float* cs = cosc + (size_t)bs * DH_;
    const float* sn = sinc + (size_t)bs * DH_;

    for (int i2 = tid; i2 < D_ / 2; i2 += 256) {
        int i = i2 * 2;
        int h = i >> 7, dd = i & 127;
        int rj = (dd < 64) ? (i + 64) : (i - 64);
        float sgn = (dd < 64) ? -1.f : 1.f;
        float x0 = srow[i]   * qinv * q_scale[i];
        float x1 = srow[i+1] * qinv * q_scale[i+1];
        float r0 = srow[rj]   * qinv * q_scale[rj]   * sgn;
        float r1 = srow[rj+1] * qinv * q_scale[rj+1] * sgn;
        float v0 = x0 * cs[dd]   + r0 * sn[dd];
        float v1 = x1 * cs[dd+1] + r1 * sn[dd+1];
        size_t o = (((size_t)b * H_ + h) * S_ + s) * DH_ + dd;
        uint32_t lo, hi = packsplit(v0, v1, lo);
        *(uint32_t*)(g_qh + o) = hi;
        *(uint32_t*)(g_ql + o) = lo;
    }
    for (int i2 = tid; i2 < KVD_ / 2; i2 += 256) {
        int i = i2 * 2;
        int h = i >> 7, dd = i & 127;
        int rj = (dd < 64) ? (i + 64) : (i - 64);
        float sgn = (dd < 64) ? -1.f : 1.f;
        float x0 = srow[D_ + i]   * kinv * k_scale[i];
        float x1 = srow[D_ + i+1] * kinv * k_scale[i+1];
        float r0 = srow[D_ + rj]   * kinv * k_scale[rj]   * sgn;
        float r1 = srow[D_ + rj+1] * kinv * k_scale[rj+1] * sgn;
        float v0 = x0 * cs[dd]   + r0 * sn[dd];
        float v1 = x1 * cs[dd+1] + r1 * sn[dd+1];
        size_t o = (((size_t)b * KVH_ + h) * S_ + s) * DH_ + dd;
        uint32_t lo, hi = packsplit(v0, v1, lo);
        *(uint32_t*)(g_kh + o) = hi;
        *(uint32_t*)(g_kl + o) = lo;
    }
    for (int i2 = tid; i2 < KVD_ / 2; i2 += 256) {
        int i = i2 * 2;
        int h = i >> 7, dd = i & 127;
        size_t o = (((size_t)b * KVH_ + h) * S_ + s) * DH_ + dd;
        uint32_t lo, hi = packsplit(srow[D_ + KVD_ + i], srow[D_ + KVD_ + i + 1], lo);
        *(uint32_t*)(g_vh + o) = hi;
        *(uint32_t*)(g_vl + o) = lo;
    }
}

// ---------------- tensor-core flash attention (causal, split-bf16 3xMMA) ----------------
#define AT_QH   0
#define AT_QL   16384
#define AT_KV   32768
#define AKV_STG 65536
#define AT_SO   (AT_KV + 2*AKV_STG)
#define SO_STRIDE 132
#define AT_RED  (AT_SO + 64*SO_STRIDE*4)
#define ATT_SMEM (AT_RED + 1024 + 128)

__global__ __launch_bounds__(256, 1) void attn_mma() {
    extern __shared__ char dsmem[];
    const int bh = blockIdx.x;
    const int b = bh / H_;
    const int h = bh % H_;
    const int kvh = h / (H_ / KVH_);
    const int qb = (S_ / 64 - 1) - blockIdx.y;   // heavy blocks first
    const int tid = threadIdx.x;
    const int lane = tid & 31;
    const int wid = tid >> 5;
    const int warp_m = wid >> 1;
    const int warp_n = wid & 1;

    uint32_t db = smem_u32(dsmem);
    uint32_t sbase = (db + 127u) & ~127u;
    float* sO   = (float*)(dsmem + (sbase - db) + AT_SO);
    float* redm = (float*)(dsmem + (sbase - db) + AT_RED);
    float* redl = redm + 128;

    const __nv_bfloat16* QhG = g_qh + (((size_t)b * H_ + h) * S_ + (size_t)qb * 64) * DH_;
    const __nv_bfloat16* QlG = g_ql + (((size_t)b * H_ + h) * S_ + (size_t)qb * 64) * DH_;
    const __nv_bfloat16* KhB = g_kh + ((size_t)b * KVH_ + kvh) * S_ * DH_;
    const __nv_bfloat16* KlB = g_kl + ((size_t)b * KVH_ + kvh) * S_ * DH_;
    const __nv_bfloat16* VhB = g_vh + ((size_t)b * KVH_ + kvh) * S_ * DH_;
    const __nv_bfloat16* VlB = g_vl + ((size_t)b * KVH_ + kvh) * S_ * DH_;

    #pragma unroll
    for (int i = 0; i < 4; i++) {
        int idx = tid + i * 256;
        int row = idx >> 4, ch = idx & 15;
        uint32_t sw = swz256(row, ch);
        size_t g = (size_t)row * DH_ + ch * 8;
        CP_ASYNC16(sbase + AT_QH + sw, QhG + g);
        CP_ASYNC16(sbase + AT_QL + sw, QlG + g);
    }
    auto load_kv = [&](int buf, int jt) {
        uint32_t sb = sbase + AT_KV + (uint32_t)buf * AKV_STG;
        size_t gb = (size_t)jt * 64 * DH_;
        #pragma unroll
        for (int i = 0; i < 4; i++) {
            int idx = tid + i * 256;
            int row = idx >> 4, ch = idx & 15;
            uint32_t sw = swz256(row, ch);
            size_t g = gb + (size_t)row * DH_ + ch * 8;
            CP_ASYNC16(sb +         sw, KhB + g);
            CP_ASYNC16(sb + 16384 + sw, KlB + g);
            CP_ASYNC16(sb + 32768 + sw, VhB + g);
            CP_ASYNC16(sb + 49152 + sw, VlB + g);
        }
    };
    load_kv(0, 0);
    CP_COMMIT();

    float oacc[16][4];
    #pragma unroll
    for (int nt = 0; nt < 16; nt++)
        #pragma unroll
        for (int j = 0; j < 4; j++) oacc[nt][j] = 0.f;
    float m0 = -1e30f, m1 = -1e30f, l0 = 0.f, l1 = 0.f;

    const int gr  = lane >> 2;
    const int rI0 = warp_m * 16 + gr;
    const int nj = qb + 1;

    for (int jt = 0; jt < nj; jt++) {
        const int buf = jt & 1;
        CP_WAIT(0);
        __syncthreads();
        if (jt + 1 < nj) { load_kv(buf ^ 1, jt + 1); CP_COMMIT(); }

        const uint32_t sQH = sbase + AT_QH, sQL = sbase + AT_QL;
        const uint32_t kb = sbase + AT_KV + (uint32_t)buf * AKV_STG;
        const uint32_t sKH = kb, sKL = kb + 16384, sVH = kb + 32768, sVL = kb + 49152;

        float sacc[4][4];
        #pragma unroll
        for (int nt = 0; nt < 4; nt++)
            #pragma unroll
            for (int j = 0; j < 4; j++) sacc[nt][j] = 0.f;

        #pragma unroll
        for (int kt = 0; kt < 8; kt++) {
            uint32_t qh4[4], ql4[4], kbh[2][4], kbl[2][4];
            int qrow = warp_m * 16 + (lane & 15);
            int qch  = kt * 2 + (lane >> 4);
            ldsm_x4(qh4, sQH + swz256(qrow, qch));
            ldsm_x4(ql4, sQL + swz256(qrow, qch));
            #pragma unroll
            for (int ng = 0; ng < 2; ng++) {
                int krow = warp_n * 32 + ng * 16 + (lane & 7) + (lane >> 4) * 8;
                int kch  = kt * 2 + ((lane >> 3) & 1);
                ldsm_x4(kbh[ng], sKH + swz256(krow, kch));
                ldsm_x4(kbl[ng], sKL + swz256(krow, kch));
            }
            #pragma unroll
            for (int ng = 0; ng < 2; ng++)
                #pragma unroll
                for (int s = 0; s < 2; s++) {
                    float* a = sacc[ng * 2 + s];
                    mma16816(a, qh4, &kbh[ng][s * 2]);
                    mma16816(a, qh4, &kbl[ng][s * 2]);
                    mma16816(a, ql4, &kbh[ng][s * 2]);
                }
        }

        #pragma unroll
        for (int nt = 0; nt < 4; nt++)
            #pragma unroll
            for (int j = 0; j < 4; j++) sacc[nt][j] *= SCALING_;
        if (jt == qb) {
            int r0g = qb * 64 + rI0;
            #pragma unroll
            for (int nt = 0; nt < 4; nt++) {
                int c = jt * 64 + warp_n * 32 + nt * 8 + (lane & 3) * 2;
                if (c     > r0g)     sacc[nt][0] = -1e30f;
                if (c + 1 > r0g)     sacc[nt][1] = -1e30f;
                if (c     > r0g + 8) sacc[nt][2] = -1e30f;
                if (c + 1 > r0g + 8) sacc[nt][3] = -1e30f;
            }
        }

        float pm0 = -1e30f, pm1 = -1e30f;
        #pragma unroll
        for (int nt = 0; nt < 4; nt++) {
            pm0 = fmaxf(pm0, fmaxf(sacc[nt][0], sacc[nt][1]));
            pm1 = fmaxf(pm1, fmaxf(sacc[nt][2], sacc[nt][3]));
        }
        pm0 = fmaxf(pm0, __shfl_xor_sync(0xFFFFFFFFu, pm0, 1));
        pm0 = fmaxf(pm0, __shfl_xor_sync(0xFFFFFFFFu, pm0, 2));
        pm1 = fmaxf(pm1, __shfl_xor_sync(0xFFFFFFFFu, pm1, 1));
        pm1 = fmaxf(pm1, __shfl_xor_sync(0xFFFFFFFFu, pm1, 2));
        if ((lane & 3) == 0) {
            redm[warp_n * 64 + rI0]     = pm0;
            redm[warp_n * 64 + rI0 + 8] = pm1;
        }
        __syncthreads();
        float mt0 = fmaxf(redm[rI0],     redm[64 + rI0]);
        float mt1 = fmaxf(redm[rI0 + 8], redm[64 + rI0 + 8]);

        float mn0 = fmaxf(m0, mt0), mn1 = fmaxf(m1, mt1);
        float c0 = __expf(m0 - mn0), c1 = __expf(m1 - mn1);

        float ps0 = 0.f, ps1 = 0.f;
        #pragma unroll
        for (int nt = 0; nt < 4; nt++) {
            sacc[nt][0] = __expf(sacc[nt][0] - mn0);
            sacc[nt][1] = __expf(sacc[nt][1] - mn0);
            sacc[nt][2] = __expf(sacc[nt][2] - mn1);
            sacc[nt][3] = __expf(sacc[nt][3] - mn1);
            ps0 += sacc[nt][0] + sacc[nt][1];
            ps1 += sacc[nt][2] + sacc[nt][3];
        }
        ps0 += __shfl_xor_sync(0xFFFFFFFFu, ps0, 1);
        ps0 += __shfl_xor_sync(0xFFFFFFFFu, ps0, 2);
        ps1 += __shfl_xor_sync(0xFFFFFFFFu, ps1, 1);
        ps1 += __shfl_xor_sync(0xFFFFFFFFu, ps1, 2);
        if ((lane & 3) == 0) {
            redl[warp_n * 64 + rI0]     = ps0;
            redl[warp_n * 64 + rI0 + 8] = ps1;
        }
        __syncthreads();
        l0 = l0 * c0 + redl[rI0]     + redl[64 + rI0];
        l1 = l1 * c1 + redl[rI0 + 8] + redl[64 + rI0 + 8];
        m0 = mn0; m1 = mn1;

        #pragma unroll
        for (int nt = 0; nt < 16; nt++) {
            oacc[nt][0] *= c0; oacc[nt][1] *= c0;
            oacc[nt][2] *= c1; oacc[nt][3] *= c1;
        }

        uint32_t pah[2][4], pal[2][4];
        #pragma unroll
        for (int kt = 0; kt < 2; kt++) {
            pah[kt][0] = packsplit(sacc[2*kt][0],   sacc[2*kt][1],   pal[kt][0]);
            pah[kt][1] = packsplit(sacc[2*kt][2],   sacc[2*kt][3],   pal[kt][1]);
            pah[kt][2] = packsplit(sacc[2*kt+1][0], sacc[2*kt+1][1], pal[kt][2]);
            pah[kt][3] = packsplit(sacc[2*kt+1][2], sacc[2*kt+1][3], pal[kt][3]);
        }

        #pragma unroll
        for (int ndg = 0; ndg < 8; ndg++) {
            #pragma unroll
            for (int kt = 0; kt < 2; kt++) {
                uint32_t vh4[4], vl4[4];
                int vrow = warp_n * 32 + kt * 16 + (lane & 15);
                int vch  = ndg * 2 + (lane >> 4);
                ldsm_x4_t(vh4, sVH + swz256(vrow, vch));
                ldsm_x4_t(vl4, sVL + swz256(vrow, vch));
                #pragma unroll
                for (int hf = 0; hf < 2; hf++) {
                    float* o = oacc[ndg * 2 + hf];
                    mma16816(o, pah[kt], &vh4[hf * 2]);
                    mma16816(o, pah[kt], &vl4[hf * 2]);
                    mma16816(o, pal[kt], &vh4[hf * 2]);
                }
            }
        }
    }

    __syncthreads();
    if (warp_n == 0) {
        #pragma unroll
        for (int nt = 0; nt < 16; nt++) {
            int d = nt * 8 + (lane & 3) * 2;
            *(float2*)&sO[(size_t)rI0 * SO_STRIDE + d]       = make_float2(oacc[nt][0], oacc[nt][1]);
            *(float2*)&sO[(size_t)(rI0 + 8) * SO_STRIDE + d] = make_float2(oacc[nt][2], oacc[nt][3]);
        }
    }
    __syncthreads();
    if (warp_n == 1) {
        float inv0 = 1.0f / l0, inv1 = 1.0f / l1;
        size_t row0g = (size_t)b * S_ + qb * 64 + rI0;
        size_t row1g = row0g + 8;
        #pragma unroll
        for (int nt = 0; nt < 16; nt++) {
            int d = nt * 8 + (lane & 3) * 2;
            float2 t0 = *(float2*)&sO[(size_t)rI0 * SO_STRIDE + d];
            float2 t1 = *(float2*)&sO[(size_t)(rI0 + 8) * SO_STRIDE + d];
            size_t o0 = row0g * D_ + h * DH_ + d;
            size_t o1 = row1g * D_ + h * DH_ + d;
            // fp16 single output (no split) for the 2-MMA out-projection
            *(uint32_t*)(g_a16 + o0) = pack_half2((t0.x + oacc[nt][0]) * inv0,
                                                  (t0.y + oacc[nt][1]) * inv0);
            *(uint32_t*)(g_a16 + o1) = pack_half2((t1.x + oacc[nt][2]) * inv1,
                                                  (t1.y + oacc[nt][3]) * inv1);
        }
    }
}

// ---------------- launch ----------------
extern "C" void kernel_launch(void* const* d_in, const int* in_sizes, int n_in,
                              void* d_out, int out_size) {
    const float* hidden  = (const float*)d_in[0];
    const float* w_qkv   = (const float*)d_in[1];
    const float* w_out   = (const float*)d_in[2];
    const float* q_scale = (const float*)d_in[3];
    const float* k_scale = (const float*)d_in[4];
    const float* cosc    = (const float*)d_in[5];
    const float* sinc    = (const float*)d_in[6];
    float* out = (float*)d_out;

    float* p_part;
    __nv_bfloat16 *p_ah, *p_al, *p_wth, *p_wtl;
    __half* p_a16;
    cudaGetSymbolAddress((void**)&p_part, g_part);
    cudaGetSymbolAddress((void**)&p_ah,   g_ah);
    cudaGetSymbolAddress((void**)&p_al,   g_al);
    cudaGetSymbolAddress((void**)&p_a16,  g_a16);
    cudaGetSymbolAddress((void**)&p_wth,  g_wth);
    cudaGetSymbolAddress((void**)&p_wtl,  g_wtl);

    cudaFuncSetAttribute(gemm_mma,     cudaFuncAttributeMaxDynamicSharedMemorySize, GSMEM_SZ);
    cudaFuncSetAttribute(gemm_mma_a16, cudaFuncAttributeMaxDynamicSharedMemorySize, HSMEM_SZ);
    cudaFuncSetAttribute(attn_mma,     cudaFuncAttributeMaxDynamicSharedMemorySize, ATT_SMEM);

    // 1) split hidden (bf16 hi/lo) ; transpose+split w_qkv (bf16)
    split_bf16<<<(MROWS * (size_t)D_) / (256 * 4), 256>>>(hidden, p_ah, p_al);
    {
        dim3 g(QKVN / 32, D_ / 32);
        transpose_split<<<g, dim3(32, 8)>>>(w_qkv, p_wth, p_wtl, D_, QKVN);
    }
    // 2) QKV projection (bf16 3-MMA), split-K=2 -> partials
    {
        dim3 g(QKVN / 256, MROWS / 128, 2);
        gemm_mma<<<g, 256, GSMEM_SZ>>>(p_ah, p_al, p_wth, p_wtl, p_part, QKVN, D_);
    }
    // 3) fused reduce + RMSNorm + RoPE -> split-bf16 q/k/v
    norm_rope_kernel<<<B_ * S_, 256>>>(p_part, q_scale, k_scale, cosc, sinc);
    // 4) attention (bf16 3-MMA) -> fp16 single output g_a16
    {
        dim3 g(B_ * H_, S_ / 64);
        attn_mma<<<g, 256, ATT_SMEM>>>();
    }
    // 5) transpose+split w_out (fp16 hi/lo, reusing g_wth/g_wtl storage)
    {
        dim3 g(D_ / 32, D_ / 32);
        transpose_split_f16<<<g, dim3(32, 8)>>>(w_out, (__half*)p_wth, (__half*)p_wtl, D_, D_);
    }
    // 6) out-projection (fp16 2-MMA), split-K=2 -> partials ; reduce -> out
    {
        dim3 g(D_ / 256, MROWS / 128, 2);
        gemm_mma_a16<<<g, 256, HSMEM_SZ>>>(p_a16, (const __half*)p_wth, (const __half*)p_wtl,
                                           p_part, D_, D_);
    }
    reduce_add<<<(MROWS * (size_t)D_) / (256 * 4), 256>>>(p_part, out, (size_t)MROWS * D_);
}

// round 12
// speedup vs baseline: 4.4519x; 1.1592x over previous
#include <cuda_runtime.h>
#include <cuda_bf16.h>
#include <cuda_fp16.h>
#include <cstdint>
#include <cstddef>

#define B_    2
#define S_    2048
#define D_    4096
#define H_    32
#define KVH_  8
#define DH_   128
#define KVD_  (KVH_*DH_)          // 1024
#define QKVN  (D_ + 2*KVD_)       // 6144
#define MROWS (B_*S_)             // 4096
#define EPS_  1e-6f
#define SCALING_ 0.08838834764831845f  // 128^-0.5

// ---------------- scratch (device globals; no runtime allocation) ----------------
__device__ float g_part[(size_t)2*MROWS*QKVN];       // split-K partials (reused)
__device__ __nv_bfloat16 g_qh[(size_t)B_*H_*S_*DH_];
__device__ __nv_bfloat16 g_ql[(size_t)B_*H_*S_*DH_];
__device__ __nv_bfloat16 g_kh[(size_t)B_*KVH_*S_*DH_];
__device__ __nv_bfloat16 g_kl[(size_t)B_*KVH_*S_*DH_];
__device__ __nv_bfloat16 g_vh[(size_t)B_*KVH_*S_*DH_];
__device__ __nv_bfloat16 g_vl[(size_t)B_*KVH_*S_*DH_];
__device__ __half        g_a16[(size_t)MROWS*D_];    // fp16 activations (hidden, then attn out)
__device__ __half        g_wth[(size_t)QKVN*D_];     // W^T hi  [N,K] fp16
__device__ __half        g_wtl[(size_t)QKVN*D_];     // W^T lo  [N,K] fp16

// ---------------- ptx helpers ----------------
__device__ __forceinline__ uint32_t smem_u32(const void* p) {
    uint32_t a;
    asm("{ .reg .u64 t; cvta.to.shared.u64 t, %1; cvt.u32.u64 %0, t; }" : "=r"(a) : "l"(p));
    return a;
}
#define CP_ASYNC16(dst, src) \
    asm volatile("cp.async.cg.shared.global [%0], [%1], 16;" :: "r"(dst), "l"(src))
#define CP_COMMIT() asm volatile("cp.async.commit_group;" ::: "memory")
#define CP_WAIT(n)  asm volatile("cp.async.wait_group %0;" :: "n"(n) : "memory")

__device__ __forceinline__ void ldsm_x4(uint32_t* r, uint32_t addr) {
    asm volatile("ldmatrix.sync.aligned.m8n8.x4.shared.b16 {%0,%1,%2,%3}, [%4];"
        : "=r"(r[0]), "=r"(r[1]), "=r"(r[2]), "=r"(r[3]) : "r"(addr));
}
__device__ __forceinline__ void ldsm_x4_t(uint32_t* r, uint32_t addr) {
    asm volatile("ldmatrix.sync.aligned.m8n8.x4.trans.shared.b16 {%0,%1,%2,%3}, [%4];"
        : "=r"(r[0]), "=r"(r[1]), "=r"(r[2]), "=r"(r[3]) : "r"(addr));
}
__device__ __forceinline__ void mma16816(float* c, const uint32_t* a, const uint32_t* b) {
    asm volatile(
        "mma.sync.aligned.m16n8k16.row.col.f32.bf16.bf16.f32 "
        "{%0,%1,%2,%3}, {%4,%5,%6,%7}, {%8,%9}, {%0,%1,%2,%3};"
        : "+f"(c[0]), "+f"(c[1]), "+f"(c[2]), "+f"(c[3])
        : "r"(a[0]), "r"(a[1]), "r"(a[2]), "r"(a[3]), "r"(b[0]), "r"(b[1]));
}
__device__ __forceinline__ void mma16816h(float* c, const uint32_t* a, const uint32_t* b) {
    asm volatile(
        "mma.sync.aligned.m16n8k16.row.col.f32.f16.f16.f32 "
        "{%0,%1,%2,%3}, {%4,%5,%6,%7}, {%8,%9}, {%0,%1,%2,%3};"
        : "+f"(c[0]), "+f"(c[1]), "+f"(c[2]), "+f"(c[3])
        : "r"(a[0]), "r"(a[1]), "r"(a[2]), "r"(a[3]), "r"(b[0]), "r"(b[1]));
}

// swizzle for 64B-row tiles (GEMM): 4 chunks of 16B per row
__device__ __forceinline__ uint32_t swz(int row, int chunk) {
    return (uint32_t)row * 64u + (uint32_t)((chunk ^ ((row >> 1) & 3)) * 16);
}
// swizzle for 256B-row tiles (attention): 16 chunks of 16B
__device__ __forceinline__ uint32_t swz256(int row, int chunk) {
    return (uint32_t)row * 256u + (uint32_t)((chunk ^ (row & 7)) * 16);
}
// split fp32 -> packed bf16x2 hi with lo out-param
__device__ __forceinline__ uint32_t packsplit(float a, float b, uint32_t& lo) {
    __nv_bfloat16 ha = __float2bfloat16(a), hb = __float2bfloat16(b);
    __nv_bfloat16 la = __float2bfloat16(a - __bfloat162float(ha));
    __nv_bfloat16 lb = __float2bfloat16(b - __bfloat162float(hb));
    uint16_t uha = *(uint16_t*)&ha, uhb = *(uint16_t*)&hb;
    uint16_t ula = *(uint16_t*)&la, ulb = *(uint16_t*)&lb;
    lo = (uint32_t)ula | ((uint32_t)ulb << 16);
    return (uint32_t)uha | ((uint32_t)uhb << 16);
}
__device__ __forceinline__ uint32_t pack_half2(float a, float b) {
    __half ha = __float2half_rn(a), hb = __float2half_rn(b);
    uint16_t ua = *(uint16_t*)&ha, ub = *(uint16_t*)&hb;
    return (uint32_t)ua | ((uint32_t)ub << 16);
}

// ---------------- elementwise fp32 -> fp16 ----------------
__global__ __launch_bounds__(256) void split_f16(const float* __restrict__ x,
                                                 __half* __restrict__ o) {
    size_t i = ((size_t)blockIdx.x * 256 + threadIdx.x) * 4;
    float4 v = *(const float4*)(x + i);
    *(uint32_t*)(o + i)     = pack_half2(v.x, v.y);
    *(uint32_t*)(o + i + 2) = pack_half2(v.z, v.w);
}

// ---------------- final reduce for split-K out-projection ----------------
__global__ __launch_bounds__(256) void reduce_add(const float* __restrict__ p,
                                                  float* __restrict__ out, size_t n) {
    size_t i = ((size_t)blockIdx.x * 256 + threadIdx.x) * 4;
    float4 a = *(const float4*)(p + i);
    float4 b = *(const float4*)(p + n + i);
    *(float4*)(out + i) = make_float4(a.x + b.x, a.y + b.y, a.z + b.z, a.w + b.w);
}

// ---------------- transpose + split fp16: W[K,N] -> T[N,K] hi/lo (half) ----------------
__global__ __launch_bounds__(256) void transpose_split_f16(const float* __restrict__ W,
                                                           __half* __restrict__ Th,
                                                           __half* __restrict__ Tl,
                                                           int K, int N) {
    __shared__ float t[32][33];
    const int n0 = blockIdx.x * 32, k0 = blockIdx.y * 32;
    const int tx = threadIdx.x, ty = threadIdx.y;
    #pragma unroll
    for (int i = 0; i < 32; i += 8)
        t[ty + i][tx] = W[(size_t)(k0 + ty + i) * N + n0 + tx];
    __syncthreads();
    #pragma unroll
    for (int i = 0; i < 32; i += 8) {
        float v = t[tx][ty + i];
        __half h = __float2half_rn(v);
        size_t o = (size_t)(n0 + ty + i) * K + k0 + tx;
        Th[o] = h;
        Tl[o] = __float2half_rn(v - __half2float(h));
    }
}

// ---------------- fp16 2-MMA GEMM: A single fp16, B split hi/lo; split-K=2 ----------------
#define A_TILE_B 8192
#define B_TILE_B 16384
#define NSTAGE   4
#define HBUF_B   (A_TILE_B + 2*B_TILE_B)       // 40KB / stage
#define HSMEM_SZ (NSTAGE*HBUF_B + 1024)

__global__ __launch_bounds__(256, 1) void gemm_mma_a16(const __half* __restrict__ A,
                                                       const __half* __restrict__ Bh,
                                                       const __half* __restrict__ Bl,
                                                       float* __restrict__ C, int N, int K) {
    extern __shared__ char dsmem[];
    const int tid  = threadIdx.x;
    const int lane = tid & 31;
    const int wid  = tid >> 5;
    const int wm   = (wid >> 2) * 64;
    const int wn   = (wid & 3) * 64;
    const int row0 = blockIdx.y * 128;
    const int col0 = blockIdx.x * 256;

    const int Khalf = K >> 1;
    const size_t koff = (size_t)blockIdx.z * Khalf;
    A += koff; Bh += koff; Bl += koff;
    C += (size_t)blockIdx.z * (size_t)MROWS * N;

    uint32_t db = smem_u32(dsmem);
    uint32_t sbase = (db + 127u) & ~127u;

    float acc[4][8][4];
    #pragma unroll
    for (int mt = 0; mt < 4; mt++)
        #pragma unroll
        for (int nt = 0; nt < 8; nt++)
            #pragma unroll
            for (int j = 0; j < 4; j++) acc[mt][nt][j] = 0.f;

    const int NK = Khalf / 32;

    auto load_tiles = [&](int buf, int kt) {
        const uint32_t bb = sbase + (uint32_t)buf * HBUF_B;
        const int k0 = kt * 32;
        #pragma unroll
        for (int i = 0; i < 2; i++) {
            int idx = tid + i * 256;
            int row = idx >> 2, ch = idx & 3;
            uint32_t sw = swz(row, ch);
            size_t g = (size_t)(row0 + row) * K + k0 + ch * 8;
            CP_ASYNC16(bb + sw, A + g);
        }
        #pragma unroll
        for (int i = 0; i < 4; i++) {
            int idx = tid + i * 256;
            int row = idx >> 2, ch = idx & 3;
            uint32_t sw = swz(row, ch);
            size_t g = (size_t)(col0 + row) * K + k0 + ch * 8;
            CP_ASYNC16(bb + A_TILE_B + sw,            Bh + g);
            CP_ASYNC16(bb + A_TILE_B + B_TILE_B + sw, Bl + g);
        }
    };

    #pragma unroll
    for (int s = 0; s < NSTAGE - 1; s++) { load_tiles(s, s); CP_COMMIT(); }

    const int mat = lane >> 3;
    const int wi  = lane & 7;

    for (int kt = 0; kt < NK; kt++) {
        CP_WAIT(NSTAGE - 2);
        __syncthreads();
        {
            int pf = kt + NSTAGE - 1;
            if (pf < NK) load_tiles(pf & (NSTAGE - 1), pf);
            CP_COMMIT();
        }

        const uint32_t bb = sbase + (uint32_t)(kt & (NSTAGE - 1)) * HBUF_B;
        const uint32_t aT = bb;
        const uint32_t bH = bb + A_TILE_B, bL = bH + B_TILE_B;

        #pragma unroll
        for (int kh = 0; kh < 2; kh++) {
            uint32_t ah[4][4], bh[4][4], bl[4][4];
            #pragma unroll
            for (int mt = 0; mt < 4; mt++) {
                int row = wm + mt * 16 + wi + (mat & 1) * 8;
                int ch  = kh * 2 + (mat >> 1);
                ldsm_x4(ah[mt], aT + swz(row, ch));
            }
            #pragma unroll
            for (int np = 0; np < 4; np++) {
                int row = wn + np * 16 + wi + (mat >> 1) * 8;
                int ch  = kh * 2 + (mat & 1);
                uint32_t sw = swz(row, ch);
                ldsm_x4(bh[np], bH + sw);
                ldsm_x4(bl[np], bL + sw);
            }
            #pragma unroll
            for (int mt = 0; mt < 4; mt++)
                #pragma unroll
                for (int np = 0; np < 4; np++)
                    #pragma unroll
                    for (int s = 0; s < 2; s++) {
                        float* a = acc[mt][np * 2 + s];
                        mma16816h(a, ah[mt], &bh[np][s * 2]);
                        mma16816h(a, ah[mt], &bl[np][s * 2]);
                    }
        }
    }

    #pragma unroll
    for (int mt = 0; mt < 4; mt++)
        #pragma unroll
        for (int nt = 0; nt < 8; nt++) {
            int m = row0 + wm + mt * 16 + (lane >> 2);
            int n = col0 + wn + nt * 8 + (lane & 3) * 2;
            float* a = acc[mt][nt];
            *(float2*)(C + (size_t)m * N + n)       = make_float2(a[0], a[1]);
            *(float2*)(C + (size_t)(m + 8) * N + n) = make_float2(a[2], a[3]);
        }
}

// ---------------- fused split-K reduce + RMSNorm + RoPE + split-bf16 scatter ----------------
__global__ __launch_bounds__(256) void norm_rope_kernel(const float* __restrict__ part,
                                                        const float* __restrict__ q_scale,
                                                        const float* __restrict__ k_scale,
                                                        const float* __restrict__ cosc,
                                                        const float* __restrict__ sinc) {
    __shared__ float srow[QKVN];
    __shared__ float red[256];
    __shared__ float s_qinv, s_kinv;
    const int bs = blockIdx.x;
    const int b = bs / S_;
    const int s = bs % S_;
    const int tid = threadIdx.x;
    const float* p0 = part + (size_t)bs * QKVN;
    const float* p1 = part + (size_t)MROWS * QKVN + (size_t)bs * QKVN;

    for (int i = tid * 4; i < QKVN; i += 1024) {
        float4 a = *(const float4*)(p0 + i);
        float4 c = *(const float4*)(p1 + i);
        *(float4*)(srow + i) = make_float4(a.x + c.x, a.y + c.y, a.z + c.z, a.w + c.w);
    }
    __syncthreads();

    float ss = 0.f;
    for (int i = tid * 4; i < D_; i += 1024) {
        float4 v = *(const float4*)(srow + i);
        ss += v.x*v.x + v.y*v.y + v.z*v.z + v.w*v.w;
    }
    red[tid] = ss; __syncthreads();
    for (int st = 128; st > 0; st >>= 1) { if (tid < st) red[tid] += red[tid + st]; __syncthreads(); }
    if (tid == 0) s_qinv = rsqrtf(red[0] / (float)D_ + EPS_);
    __syncthreads();

    ss = 0.f;
    for (int i = tid * 4; i < KVD_; i += 1024) {
        float4 v = *(const float4*)(srow + D_ + i);
        ss += v.x*v.x + v.y*v.y + v.z*v.z + v.w*v.w;
    }
    red[tid] = ss; __syncthreads();
    for (int st = 128; st > 0; st >>= 1) { if (tid < st) red[tid] += red[tid + st]; __syncthreads(); }
    if (tid == 0) s_kinv = rsqrtf(red[0] / (float)KVD_ + EPS_);
    __syncthreads();

    const float qinv = s_qinv, kinv = s_kinv;
    const float* cs = cosc + (size_t)bs * DH_;
    const float* sn = sinc + (size_t)bs * DH_;

    for (int i2 = tid; i2 < D_ / 2; i2 += 256) {
        int i = i2 * 2;
        int h = i >> 7, dd = i & 127;
        int rj = (dd < 64) ? (i + 64) : (i - 64);
        float sgn = (dd < 64) ? -1.f : 1.f;
        float x0 = srow[i]   * qinv * q_scale[i];
        float x1 = srow[i+1] * qinv * q_scale[i+1];
        float r0 = srow[rj]   * qinv * q_scale[rj]   * sgn;
        float r1 = srow[rj+1] * qinv * q_scale[rj+1] * sgn;
        float v0 = x0 * cs[dd]   + r0 * sn[dd];
        float v1 = x1 * cs[dd+1] + r1 * sn[dd+1];
        size_t o = (((size_t)b * H_ + h) * S_ + s) * DH_ + dd;
        uint32_t lo, hi = packsplit(v0, v1, lo);
        *(uint32_t*)(g_qh + o) = hi;
        *(uint32_t*)(g_ql + o) = lo;
    }
    for (int i2 = tid; i2 < KVD_ / 2; i2 += 256) {
        int i = i2 * 2;
        int h = i >> 7, dd = i & 127;
        int rj = (dd < 64) ? (i + 64) : (i - 64);
        float sgn = (dd < 64) ? -1.f : 1.f;
        float x0 = srow[D_ + i]   * kinv * k_scale[i];
        float x1 = srow[D_ + i+1] * kinv * k_scale[i+1];
        float r0 = srow[D_ + rj]   * kinv * k_scale[rj]   * sgn;
        float r1 = srow[D_ + rj+1] * kinv * k_scale[rj+1] * sgn;
        float v0 = x0 * cs[dd]   + r0 * sn[dd];
        float v1 = x1 * cs[dd+1] + r1 * sn[dd+1];
        size_t o = (((size_t)b * KVH_ + h) * S_ + s) * DH_ + dd;
        uint32_t lo, hi = packsplit(v0, v1, lo);
        *(uint32_t*)(g_kh + o) = hi;
        *(uint32_t*)(g_kl + o) = lo;
    }
    for (int i2 = tid; i2 < KVD_ / 2; i2 += 256) {
        int i = i2 * 2;
        int h = i >> 7, dd = i & 127;
        size_t o = (((size_t)b * KVH_ + h) * S_ + s) * DH_ + dd;
        uint32_t lo, hi = packsplit(srow[D_ + KVD_ + i], srow[D_ + KVD_ + i + 1], lo);
        *(uint32_t*)(g_vh + o) = hi;
        *(uint32_t*)(g_vl + o) = lo;
    }
}

// ---------------- tensor-core flash attention (causal, split-bf16 3xMMA) ----------------
#define AT_QH   0
#define AT_QL   16384
#define AT_KV   32768
#define AKV_STG 65536
#define AT_SO   (AT_KV + 2*AKV_STG)
#define SO_STRIDE 132
#define AT_RED  (AT_SO + 64*SO_STRIDE*4)
#define ATT_SMEM (AT_RED + 1024 + 128)

__global__ __launch_bounds__(256, 1) void attn_mma() {
    extern __shared__ char dsmem[];
    const int bh = blockIdx.x;
    const int b = bh / H_;
    const int h = bh % H_;
    const int kvh = h / (H_ / KVH_);
    const int qb = (S_ / 64 - 1) - blockIdx.y;   // heavy blocks first
    const int tid = threadIdx.x;
    const int lane = tid & 31;
    const int wid = tid >> 5;
    const int warp_m = wid >> 1;
    const int warp_n = wid & 1;

    uint32_t db = smem_u32(dsmem);
    uint32_t sbase = (db + 127u) & ~127u;
    float* sO   = (float*)(dsmem + (sbase - db) + AT_SO);
    float* redm = (float*)(dsmem + (sbase - db) + AT_RED);
    float* redl = redm + 128;

    const __nv_bfloat16* QhG = g_qh + (((size_t)b * H_ + h) * S_ + (size_t)qb * 64) * DH_;
    const __nv_bfloat16* QlG = g_ql + (((size_t)b * H_ + h) * S_ + (size_t)qb * 64) * DH_;
    const __nv_bfloat16* KhB = g_kh + ((size_t)b * KVH_ + kvh) * S_ * DH_;
    const __nv_bfloat16* KlB = g_kl + ((size_t)b * KVH_ + kvh) * S_ * DH_;
    const __nv_bfloat16* VhB = g_vh + ((size_t)b * KVH_ + kvh) * S_ * DH_;
    const __nv_bfloat16* VlB = g_vl + ((size_t)b * KVH_ + kvh) * S_ * DH_;

    #pragma unroll
    for (int i = 0; i < 4; i++) {
        int idx = tid + i * 256;
        int row = idx >> 4, ch = idx & 15;
        uint32_t sw = swz256(row, ch);
        size_t g = (size_t)row * DH_ + ch * 8;
        CP_ASYNC16(sbase + AT_QH + sw, QhG + g);
        CP_ASYNC16(sbase + AT_QL + sw, QlG + g);
    }
    auto load_kv = [&](int buf, int jt) {
        uint32_t sb = sbase + AT_KV + (uint32_t)buf * AKV_STG;
        size_t gb = (size_t)jt * 64 * DH_;
        #pragma unroll
        for (int i = 0; i < 4; i++) {
            int idx = tid + i * 256;
            int row = idx >> 4, ch = idx & 15;
            uint32_t sw = swz256(row, ch);
            size_t g = gb + (size_t)row * DH_ + ch * 8;
            CP_ASYNC16(sb +         sw, KhB + g);
            CP_ASYNC16(sb + 16384 + sw, KlB + g);
            CP_ASYNC16(sb + 32768 + sw, VhB + g);
            CP_ASYNC16(sb + 49152 + sw, VlB + g);
        }
    };
    load_kv(0, 0);
    CP_COMMIT();

    float oacc[16][4];
    #pragma unroll
    for (int nt = 0; nt < 16; nt++)
        #pragma unroll
        for (int j = 0; j < 4; j++) oacc[nt][j] = 0.f;
    float m0 = -1e30f, m1 = -1e30f, l0 = 0.f, l1 = 0.f;

    const int gr  = lane >> 2;
    const int rI0 = warp_m * 16 + gr;
    const int nj = qb + 1;

    for (int jt = 0; jt < nj; jt++) {
        const int buf = jt & 1;
        CP_WAIT(0);
        __syncthreads();
        if (jt + 1 < nj) { load_kv(buf ^ 1, jt + 1); CP_COMMIT(); }

        const uint32_t sQH = sbase + AT_QH, sQL = sbase + AT_QL;
        const uint32_t kb = sbase + AT_KV + (uint32_t)buf * AKV_STG;
        const uint32_t sKH = kb, sKL = kb + 16384, sVH = kb + 32768, sVL = kb + 49152;

        float sacc[4][4];
        #pragma unroll
        for (int nt = 0; nt < 4; nt++)
            #pragma unroll
            for (int j = 0; j < 4; j++) sacc[nt][j] = 0.f;

        #pragma unroll
        for (int kt = 0; kt < 8; kt++) {
            uint32_t qh4[4], ql4[4], kbh[2][4], kbl[2][4];
            int qrow = warp_m * 16 + (lane & 15);
            int qch  = kt * 2 + (lane >> 4);
            ldsm_x4(qh4, sQH + swz256(qrow, qch));
            ldsm_x4(ql4, sQL + swz256(qrow, qch));
            #pragma unroll
            for (int ng = 0; ng < 2; ng++) {
                int krow = warp_n * 32 + ng * 16 + (lane & 7) + (lane >> 4) * 8;
                int kch  = kt * 2 + ((lane >> 3) & 1);
                ldsm_x4(kbh[ng], sKH + swz256(krow, kch));
                ldsm_x4(kbl[ng], sKL + swz256(krow, kch));
            }
            #pragma unroll
            for (int ng = 0; ng < 2; ng++)
                #pragma unroll
                for (int s = 0; s < 2; s++) {
                    float* a = sacc[ng * 2 + s];
                    mma16816(a, qh4, &kbh[ng][s * 2]);
                    mma16816(a, qh4, &kbl[ng][s * 2]);
                    mma16816(a, ql4, &kbh[ng][s * 2]);
                }
        }

        #pragma unroll
        for (int nt = 0; nt < 4; nt++)
            #pragma unroll
            for (int j = 0; j < 4; j++) sacc[nt][j] *= SCALING_;
        if (jt == qb) {
            int r0g = qb * 64 + rI0;
            #pragma unroll
            for (int nt = 0; nt < 4; nt++) {
                int c = jt * 64 + warp_n * 32 + nt * 8 + (lane & 3) * 2;
                if (c     > r0g)     sacc[nt][0] = -1e30f;
                if (c + 1 > r0g)     sacc[nt][1] = -1e30f;
                if (c     > r0g + 8) sacc[nt][2] = -1e30f;
                if (c + 1 > r0g + 8) sacc[nt][3] = -1e30f;
            }
        }

        float pm0 = -1e30f, pm1 = -1e30f;
        #pragma unroll
        for (int nt = 0; nt < 4; nt++) {
            pm0 = fmaxf(pm0, fmaxf(sacc[nt][0], sacc[nt][1]));
            pm1 = fmaxf(pm1, fmaxf(sacc[nt][2], sacc[nt][3]));
        }
        pm0 = fmaxf(pm0, __shfl_xor_sync(0xFFFFFFFFu, pm0, 1));
        pm0 = fmaxf(pm0, __shfl_xor_sync(0xFFFFFFFFu, pm0, 2));
        pm1 = fmaxf(pm1, __shfl_xor_sync(0xFFFFFFFFu, pm1, 1));
        pm1 = fmaxf(pm1, __shfl_xor_sync(0xFFFFFFFFu, pm1, 2));
        if ((lane & 3) == 0) {
            redm[warp_n * 64 + rI0]     = pm0;
            redm[warp_n * 64 + rI0 + 8] = pm1;
        }
        __syncthreads();
        float mt0 = fmaxf(redm[rI0],     redm[64 + rI0]);
        float mt1 = fmaxf(redm[rI0 + 8], redm[64 + rI0 + 8]);

        float mn0 = fmaxf(m0, mt0), mn1 = fmaxf(m1, mt1);
        float c0 = __expf(m0 - mn0), c1 = __expf(m1 - mn1);

        float ps0 = 0.f, ps1 = 0.f;
        #pragma unroll
        for (int nt = 0; nt < 4; nt++) {
            sacc[nt][0] = __expf(sacc[nt][0] - mn0);
            sacc[nt][1] = __expf(sacc[nt][1] - mn0);
            sacc[nt][2] = __expf(sacc[nt][2] - mn1);
            sacc[nt][3] = __expf(sacc[nt][3] - mn1);
            ps0 += sacc[nt][0] + sacc[nt][1];
            ps1 += sacc[nt][2] + sacc[nt][3];
        }
        ps0 += __shfl_xor_sync(0xFFFFFFFFu, ps0, 1);
        ps0 += __shfl_xor_sync(0xFFFFFFFFu, ps0, 2);
        ps1 += __shfl_xor_sync(0xFFFFFFFFu, ps1, 1);
        ps1 += __shfl_xor_sync(0xFFFFFFFFu, ps1, 2);
        if ((lane & 3) == 0) {
            redl[warp_n * 64 + rI0]     = ps0;
            redl[warp_n * 64 + rI0 + 8] = ps1;
        }
        __syncthreads();
        l0 = l0 * c0 + redl[rI0]     + redl[64 + rI0];
        l1 = l1 * c1 + redl[rI0 + 8] + redl[64 + rI0 + 8];
        m0 = mn0; m1 = mn1;

        #pragma unroll
        for (int nt = 0; nt < 16; nt++) {
            oacc[nt][0] *= c0; oacc[nt][1] *= c0;
            oacc[nt][2] *= c1; oacc[nt][3] *= c1;
        }

        uint32_t pah[2][4], pal[2][4];
        #pragma unroll
        for (int kt = 0; kt < 2; kt++) {
            pah[kt][0] = packsplit(sacc[2*kt][0],   sacc[2*kt][1],   pal[kt][0]);
            pah[kt][1] = packsplit(sacc[2*kt][2],   sacc[2*kt][3],   pal[kt][1]);
            pah[kt][2] = packsplit(sacc[2*kt+1][0], sacc[2*kt+1][1], pal[kt][2]);
            pah[kt][3] = packsplit(sacc[2*kt+1][2], sacc[2*kt+1][3], pal[kt][3]);
        }

        #pragma unroll
        for (int ndg = 0; ndg < 8; ndg++) {
            #pragma unroll
            for (int kt = 0; kt < 2; kt++) {
                uint32_t vh4[4], vl4[4];
                int vrow = warp_n * 32 + kt * 16 + (lane & 15);
                int vch  = ndg * 2 + (lane >> 4);
                ldsm_x4_t(vh4, sVH + swz256(vrow, vch));
                ldsm_x4_t(vl4, sVL + swz256(vrow, vch));
                #pragma unroll
                for (int hf = 0; hf < 2; hf++) {
                    float* o = oacc[ndg * 2 + hf];
                    mma16816(o, pah[kt], &vh4[hf * 2]);
                    mma16816(o, pah[kt], &vl4[hf * 2]);
                    mma16816(o, pal[kt], &vh4[hf * 2]);
                }
            }
        }
    }

    __syncthreads();
    if (warp_n == 0) {
        #pragma unroll
        for (int nt = 0; nt < 16; nt++) {
            int d = nt * 8 + (lane & 3) * 2;
            *(float2*)&sO[(size_t)rI0 * SO_STRIDE + d]       = make_float2(oacc[nt][0], oacc[nt][1]);
            *(float2*)&sO[(size_t)(rI0 + 8) * SO_STRIDE + d] = make_float2(oacc[nt][2], oacc[nt][3]);
        }
    }
    __syncthreads();
    if (warp_n == 1) {
        float inv0 = 1.0f / l0, inv1 = 1.0f / l1;
        size_t row0g = (size_t)b * S_ + qb * 64 + rI0;
        size_t row1g = row0g + 8;
        #pragma unroll
        for (int nt = 0; nt < 16; nt++) {
            int d = nt * 8 + (lane & 3) * 2;
            float2 t0 = *(float2*)&sO[(size_t)rI0 * SO_STRIDE + d];
            float2 t1 = *(float2*)&sO[(size_t)(rI0 + 8) * SO_STRIDE + d];
            size_t o0 = row0g * D_ + h * DH_ + d;
            size_t o1 = row1g * D_ + h * DH_ + d;
            *(uint32_t*)(g_a16 + o0) = pack_half2((t0.x + oacc[nt][0]) * inv0,
                                                  (t0.y + oacc[nt][1]) * inv0);
            *(uint32_t*)(g_a16 + o1) = pack_half2((t1.x + oacc[nt][2]) * inv1,
                                                  (t1.y + oacc[nt][3]) * inv1);
        }
    }
}

// ---------------- launch ----------------
extern "C" void kernel_launch(void* const* d_in, const int* in_sizes, int n_in,
                              void* d_out, int out_size) {
    const float* hidden  = (const float*)d_in[0];
    const float* w_qkv   = (const float*)d_in[1];
    const float* w_out   = (const float*)d_in[2];
    const float* q_scale = (const float*)d_in[3];
    const float* k_scale = (const float*)d_in[4];
    const float* cosc    = (const float*)d_in[5];
    const float* sinc    = (const float*)d_in[6];
    float* out = (float*)d_out;

    float* p_part;
    __half *p_a16, *p_wth, *p_wtl;
    cudaGetSymbolAddress((void**)&p_part, g_part);
    cudaGetSymbolAddress((void**)&p_a16,  g_a16);
    cudaGetSymbolAddress((void**)&p_wth,  g_wth);
    cudaGetSymbolAddress((void**)&p_wtl,  g_wtl);

    cudaFuncSetAttribute(gemm_mma_a16, cudaFuncAttributeMaxDynamicSharedMemorySize, HSMEM_SZ);
    cudaFuncSetAttribute(attn_mma,     cudaFuncAttributeMaxDynamicSharedMemorySize, ATT_SMEM);

    // 1) hidden -> fp16 ; w_qkv -> fp16 hi/lo transpose
    split_f16<<<(MROWS * (size_t)D_) / (256 * 4), 256>>>(hidden, p_a16);
    {
        dim3 g(QKVN / 32, D_ / 32);
        transpose_split_f16<<<g, dim3(32, 8)>>>(w_qkv, p_wth, p_wtl, D_, QKVN);
    }
    // 2) QKV projection (fp16 2-MMA), split-K=2 -> partials
    {
        dim3 g(QKVN / 256, MROWS / 128, 2);
        gemm_mma_a16<<<g, 256, HSMEM_SZ>>>(p_a16, p_wth, p_wtl, p_part, QKVN, D_);
    }
    // 3) fused reduce + RMSNorm + RoPE -> split-bf16 q/k/v
    norm_rope_kernel<<<B_ * S_, 256>>>(p_part, q_scale, k_scale, cosc, sinc);
    // 4) attention (bf16 3-MMA) -> fp16 output g_a16 (hidden fp16 dead by now)
    {
        dim3 g(B_ * H_, S_ / 64);
        attn_mma<<<g, 256, ATT_SMEM>>>();
    }
    // 5) w_out -> fp16 hi/lo transpose (reuse weight buffers)
    {
        dim3 g(D_ / 32, D_ / 32);
        transpose_split_f16<<<g, dim3(32, 8)>>>(w_out, p_wth, p_wtl, D_, D_);
    }
    // 6) out-projection (fp16 2-MMA), split-K=2 -> partials ; reduce -> out
    {
        dim3 g(D_ / 256, MROWS / 128, 2);
        gemm_mma_a16<<<g, 256, HSMEM_SZ>>>(p_a16, p_wth, p_wtl, p_part, D_, D_);
    }
    reduce_add<<<(MROWS * (size_t)D_) / (256 * 4), 256>>>(p_part, out, (size_t)MROWS * D_);
}

// round 15
// speedup vs baseline: 4.7529x; 1.0676x over previous
#include <cuda_runtime.h>
#include <cuda_fp16.h>
#include <cstdint>
#include <cstddef>

#define B_    2
#define S_    2048
#define D_    4096
#define H_    32
#define KVH_  8
#define DH_   128
#define KVD_  (KVH_*DH_)          // 1024
#define QKVN  (D_ + 2*KVD_)       // 6144
#define MROWS (B_*S_)             // 4096
#define EPS_  1e-6f
#define SCALING_ 0.08838834764831845f  // 128^-0.5

// ---------------- scratch (device globals; no runtime allocation) ----------------
__device__ float g_part[(size_t)2*MROWS*QKVN];       // split-K partials (reused)
__device__ __half g_q16h[(size_t)B_*H_*S_*DH_];      // Q hi (fp16 split pair: exact)
__device__ __half g_q16l[(size_t)B_*H_*S_*DH_];      // Q lo
__device__ __half g_k16[(size_t)B_*KVH_*S_*DH_];     // K single fp16
__device__ __half g_v16[(size_t)B_*KVH_*S_*DH_];     // V single fp16
__device__ __half g_a16[(size_t)MROWS*D_];           // fp16 activations (hidden, then attn out)
__device__ __half g_wth[(size_t)QKVN*D_];            // W^T hi  [N,K] fp16
__device__ __half g_wtl[(size_t)QKVN*D_];            // W^T lo  [N,K] fp16

// ---------------- ptx helpers ----------------
__device__ __forceinline__ uint32_t smem_u32(const void* p) {
    uint32_t a;
    asm("{ .reg .u64 t; cvta.to.shared.u64 t, %1; cvt.u32.u64 %0, t; }" : "=r"(a) : "l"(p));
    return a;
}
#define CP_ASYNC16(dst, src) \
    asm volatile("cp.async.cg.shared.global [%0], [%1], 16;" :: "r"(dst), "l"(src))
#define CP_COMMIT() asm volatile("cp.async.commit_group;" ::: "memory")
#define CP_WAIT(n)  asm volatile("cp.async.wait_group %0;" :: "n"(n) : "memory")

__device__ __forceinline__ void ldsm_x4(uint32_t* r, uint32_t addr) {
    asm volatile("ldmatrix.sync.aligned.m8n8.x4.shared.b16 {%0,%1,%2,%3}, [%4];"
        : "=r"(r[0]), "=r"(r[1]), "=r"(r[2]), "=r"(r[3]) : "r"(addr));
}
__device__ __forceinline__ void ldsm_x4_t(uint32_t* r, uint32_t addr) {
    asm volatile("ldmatrix.sync.aligned.m8n8.x4.trans.shared.b16 {%0,%1,%2,%3}, [%4];"
        : "=r"(r[0]), "=r"(r[1]), "=r"(r[2]), "=r"(r[3]) : "r"(addr));
}
__device__ __forceinline__ void mma16816h(float* c, const uint32_t* a, const uint32_t* b) {
    asm volatile(
        "mma.sync.aligned.m16n8k16.row.col.f32.f16.f16.f32 "
        "{%0,%1,%2,%3}, {%4,%5,%6,%7}, {%8,%9}, {%0,%1,%2,%3};"
        : "+f"(c[0]), "+f"(c[1]), "+f"(c[2]), "+f"(c[3])
        : "r"(a[0]), "r"(a[1]), "r"(a[2]), "r"(a[3]), "r"(b[0]), "r"(b[1]));
}

// swizzle for 64B-row tiles (GEMM): 4 chunks of 16B per row
__device__ __forceinline__ uint32_t swz(int row, int chunk) {
    return (uint32_t)row * 64u + (uint32_t)((chunk ^ ((row >> 1) & 3)) * 16);
}
// swizzle for 256B-row tiles (attention): 16 chunks of 16B
__device__ __forceinline__ uint32_t swz256(int row, int chunk) {
    return (uint32_t)row * 256u + (uint32_t)((chunk ^ (row & 7)) * 16);
}
__device__ __forceinline__ uint32_t pack_half2(float a, float b) {
    __half ha = __float2half_rn(a), hb = __float2half_rn(b);
    uint16_t ua = *(uint16_t*)&ha, ub = *(uint16_t*)&hb;
    return (uint32_t)ua | ((uint32_t)ub << 16);
}
// split fp32 -> packed fp16x2 hi with lo out-param (hi+lo ~exact)
__device__ __forceinline__ uint32_t packsplit_h(float a, float b, uint32_t& lo) {
    __half ha = __float2half_rn(a), hb = __float2half_rn(b);
    __half la = __float2half_rn(a - __half2float(ha));
    __half lb = __float2half_rn(b - __half2float(hb));
    uint16_t uha = *(uint16_t*)&ha, uhb = *(uint16_t*)&hb;
    uint16_t ula = *(uint16_t*)&la, ulb = *(uint16_t*)&lb;
    lo = (uint32_t)ula | ((uint32_t)ulb << 16);
    return (uint32_t)uha | ((uint32_t)uhb << 16);
}

// ---------------- elementwise fp32 -> fp16 ----------------
__global__ __launch_bounds__(256) void split_f16(const float* __restrict__ x,
                                                 __half* __restrict__ o) {
    size_t i = ((size_t)blockIdx.x * 256 + threadIdx.x) * 4;
    float4 v = *(const float4*)(x + i);
    *(uint32_t*)(o + i)     = pack_half2(v.x, v.y);
    *(uint32_t*)(o + i + 2) = pack_half2(v.z, v.w);
}

// ---------------- final reduce for split-K out-projection ----------------
__global__ __launch_bounds__(256) void reduce_add(const float* __restrict__ p,
                                                  float* __restrict__ out, size_t n) {
    size_t i = ((size_t)blockIdx.x * 256 + threadIdx.x) * 4;
    float4 a = *(const float4*)(p + i);
    float4 b = *(const float4*)(p + n + i);
    *(float4*)(out + i) = make_float4(a.x + b.x, a.y + b.y, a.z + b.z, a.w + b.w);
}

// ---------------- transpose + split fp16: W[K,N] -> T[N,K] hi/lo (half) ----------------
__global__ __launch_bounds__(256) void transpose_split_f16(const float* __restrict__ W,
                                                           __half* __restrict__ Th,
                                                           __half* __restrict__ Tl,
                                                           int K, int N) {
    __shared__ float t[32][33];
    const int n0 = blockIdx.x * 32, k0 = blockIdx.y * 32;
    const int tx = threadIdx.x, ty = threadIdx.y;
    #pragma unroll
    for (int i = 0; i < 32; i += 8)
        t[ty + i][tx] = W[(size_t)(k0 + ty + i) * N + n0 + tx];
    __syncthreads();
    #pragma unroll
    for (int i = 0; i < 32; i += 8) {
        float v = t[tx][ty + i];
        __half h = __float2half_rn(v);
        size_t o = (size_t)(n0 + ty + i) * K + k0 + tx;
        Th[o] = h;
        Tl[o] = __float2half_rn(v - __half2float(h));
    }
}

// ---------------- fp16 2-MMA GEMM: A single fp16, B split hi/lo; split-K=2 ----------------
#define A_TILE_B 8192
#define B_TILE_B 16384
#define NSTAGE   4
#define HBUF_B   (A_TILE_B + 2*B_TILE_B)       // 40KB / stage
#define HSMEM_SZ (NSTAGE*HBUF_B + 1024)

__global__ __launch_bounds__(256, 1) void gemm_mma_a16(const __half* __restrict__ A,
                                                       const __half* __restrict__ Bh,
                                                       const __half* __restrict__ Bl,
                                                       float* __restrict__ C, int N, int K) {
    extern __shared__ char dsmem[];
    const int tid  = threadIdx.x;
    const int lane = tid & 31;
    const int wid  = tid >> 5;
    const int wm   = (wid >> 2) * 64;
    const int wn   = (wid & 3) * 64;
    const int row0 = blockIdx.y * 128;
    const int col0 = blockIdx.x * 256;

    const int Khalf = K >> 1;
    const size_t koff = (size_t)blockIdx.z * Khalf;
    A += koff; Bh += koff; Bl += koff;
    C += (size_t)blockIdx.z * (size_t)MROWS * N;

    uint32_t db = smem_u32(dsmem);
    uint32_t sbase = (db + 127u) & ~127u;

    float acc[4][8][4];
    #pragma unroll
    for (int mt = 0; mt < 4; mt++)
        #pragma unroll
        for (int nt = 0; nt < 8; nt++)
            #pragma unroll
            for (int j = 0; j < 4; j++) acc[mt][nt][j] = 0.f;

    const int NK = Khalf / 32;

    auto load_tiles = [&](int buf, int kt) {
        const uint32_t bb = sbase + (uint32_t)buf * HBUF_B;
        const int k0 = kt * 32;
        #pragma unroll
        for (int i = 0; i < 2; i++) {
            int idx = tid + i * 256;
            int row = idx >> 2, ch = idx & 3;
            uint32_t sw = swz(row, ch);
            size_t g = (size_t)(row0 + row) * K + k0 + ch * 8;
            CP_ASYNC16(bb + sw, A + g);
        }
        #pragma unroll
        for (int i = 0; i < 4; i++) {
            int idx = tid + i * 256;
            int row = idx >> 2, ch = idx & 3;
            uint32_t sw = swz(row, ch);
            size_t g = (size_t)(col0 + row) * K + k0 + ch * 8;
            CP_ASYNC16(bb + A_TILE_B + sw,            Bh + g);
            CP_ASYNC16(bb + A_TILE_B + B_TILE_B + sw, Bl + g);
        }
    };

    #pragma unroll
    for (int s = 0; s < NSTAGE - 1; s++) { load_tiles(s, s); CP_COMMIT(); }

    const int mat = lane >> 3;
    const int wi  = lane & 7;

    for (int kt = 0; kt < NK; kt++) {
        CP_WAIT(NSTAGE - 2);
        __syncthreads();
        {
            int pf = kt + NSTAGE - 1;
            if (pf < NK) load_tiles(pf & (NSTAGE - 1), pf);
            CP_COMMIT();
        }

        const uint32_t bb = sbase + (uint32_t)(kt & (NSTAGE - 1)) * HBUF_B;
        const uint32_t aT = bb;
        const uint32_t bH = bb + A_TILE_B, bL = bH + B_TILE_B;

        #pragma unroll
        for (int kh = 0; kh < 2; kh++) {
            uint32_t ah[4][4], bh[4][4], bl[4][4];
            #pragma unroll
            for (int mt = 0; mt < 4; mt++) {
                int row = wm + mt * 16 + wi + (mat & 1) * 8;
                int ch  = kh * 2 + (mat >> 1);
                ldsm_x4(ah[mt], aT + swz(row, ch));
            }
            #pragma unroll
            for (int np = 0; np < 4; np++) {
                int row = wn + np * 16 + wi + (mat >> 1) * 8;
                int ch  = kh * 2 + (mat & 1);
                uint32_t sw = swz(row, ch);
                ldsm_x4(bh[np], bH + sw);
                ldsm_x4(bl[np], bL + sw);
            }
            #pragma unroll
            for (int mt = 0; mt < 4; mt++)
                #pragma unroll
                for (int np = 0; np < 4; np++)
                    #pragma unroll
                    for (int s = 0; s < 2; s++) {
                        float* a = acc[mt][np * 2 + s];
                        mma16816h(a, ah[mt], &bh[np][s * 2]);
                        mma16816h(a, ah[mt], &bl[np][s * 2]);
                    }
        }
    }

    #pragma unroll
    for (int mt = 0; mt < 4; mt++)
        #pragma unroll
        for (int nt = 0; nt < 8; nt++) {
            int m = row0 + wm + mt * 16 + (lane >> 2);
            int n = col0 + wn + nt * 8 + (lane & 3) * 2;
            float* a = acc[mt][nt];
            *(float2*)(C + (size_t)m * N + n)       = make_float2(a[0], a[1]);
            *(float2*)(C + (size_t)(m + 8) * N + n) = make_float2(a[2], a[3]);
        }
}

// ---------------- fused split-K reduce + RMSNorm + RoPE + fp16 scatter ----------------
__global__ __launch_bounds__(256) void norm_rope_kernel(const float* __restrict__ part,
                                                        const float* __restrict__ q_scale,
                                                        const float* __restrict__ k_scale,
                                                        const float* __restrict__ cosc,
                                                        const float* __restrict__ sinc) {
    __shared__ float srow[QKVN];
    __shared__ float red[256];
    __shared__ float s_qinv, s_kinv;
    const int bs = blockIdx.x;
    const int b = bs / S_;
    const int s = bs % S_;
    const int tid = threadIdx.x;
    const float* p0 = part + (size_t)bs * QKVN;
    const float* p1 = part + (size_t)MROWS * QKVN + (size_t)bs * QKVN;

    for (int i = tid * 4; i < QKVN; i += 1024) {
        float4 a = *(const float4*)(p0 + i);
        float4 c = *(const float4*)(p1 + i);
        *(float4*)(srow + i) = make_float4(a.x + c.x, a.y + c.y, a.z + c.z, a.w + c.w);
    }
    __syncthreads();

    float ss = 0.f;
    for (int i = tid * 4; i < D_; i += 1024) {
        float4 v = *(const float4*)(srow + i);
        ss += v.x*v.x + v.y*v.y + v.z*v.z + v.w*v.w;
    }
    red[tid] = ss; __syncthreads();
    for (int st = 128; st > 0; st >>= 1) { if (tid < st) red[tid] += red[tid + st]; __syncthreads(); }
    if (tid == 0) s_qinv = rsqrtf(red[0] / (float)D_ + EPS_);
    __syncthreads();

    ss = 0.f;
    for (int i = tid * 4; i < KVD_; i += 1024) {
        float4 v = *(const float4*)(srow + D_ + i);
        ss += v.x*v.x + v.y*v.y + v.z*v.z + v.w*v.w;
    }
    red[tid] = ss; __syncthreads();
    for (int st = 128; st > 0; st >>= 1) { if (tid < st) red[tid] += red[tid + st]; __syncthreads(); }
    if (tid == 0) s_kinv = rsqrtf(red[0] / (float)KVD_ + EPS_);
    __syncthreads();

    const float qinv = s_qinv, kinv = s_kinv;
    const float* cs = cosc + (size_t)bs * DH_;
    const float* sn = sinc + (size_t)bs * DH_;

    // Q: exact fp16 split pair
    for (int i2 = tid; i2 < D_ / 2; i2 += 256) {
        int i = i2 * 2;
        int h = i >> 7, dd = i & 127;
        int rj = (dd < 64) ? (i + 64) : (i - 64);
        float sgn = (dd < 64) ? -1.f : 1.f;
        float x0 = srow[i]   * qinv * q_scale[i];
        float x1 = srow[i+1] * qinv * q_scale[i+1];
        float r0 = srow[rj]   * qinv * q_scale[rj]   * sgn;
        float r1 = srow[rj+1] * qinv * q_scale[rj+1] * sgn;
        float v0 = x0 * cs[dd]   + r0 * sn[dd];
        float v1 = x1 * cs[dd+1] + r1 * sn[dd+1];
        size_t o = (((size_t)b * H_ + h) * S_ + s) * DH_ + dd;
        uint32_t lo, hi = packsplit_h(v0, v1, lo);
        *(uint32_t*)(g_q16h + o) = hi;
        *(uint32_t*)(g_q16l + o) = lo;
    }
    // K: single fp16 (rounded)
    for (int i2 = tid; i2 < KVD_ / 2; i2 += 256) {
        int i = i2 * 2;
        int h = i >> 7, dd = i & 127;
        int rj = (dd < 64) ? (i + 64) : (i - 64);
        float sgn = (dd < 64) ? -1.f : 1.f;
        float x0 = srow[D_ + i]   * kinv * k_scale[i];
        float x1 = srow[D_ + i+1] * kinv * k_scale[i+1];
        float r0 = srow[D_ + rj]   * kinv * k_scale[rj]   * sgn;
        float r1 = srow[D_ + rj+1] * kinv * k_scale[rj+1] * sgn;
        float v0 = x0 * cs[dd]   + r0 * sn[dd];
        float v1 = x1 * cs[dd+1] + r1 * sn[dd+1];
        size_t o = (((size_t)b * KVH_ + h) * S_ + s) * DH_ + dd;
        *(uint32_t*)(g_k16 + o) = pack_half2(v0, v1);
    }
    // V: single fp16 (rounded)
    for (int i2 = tid; i2 < KVD_ / 2; i2 += 256) {
        int i = i2 * 2;
        int h = i >> 7, dd = i & 127;
        size_t o = (((size_t)b * KVH_ + h) * S_ + s) * DH_ + dd;
        *(uint32_t*)(g_v16 + o) = pack_half2(srow[D_ + KVD_ + i], srow[D_ + KVD_ + i + 1]);
    }
}

// ---------------- tensor-core flash attention (causal, fp16 2-MMA) ----------------
// Q split fp16 (exact), K/V single fp16. QK: Qh*K + Ql*K. PV: Ph*V + Pl*V.
#define AT_QH   0
#define AT_QL   16384
#define AT_KV   32768
#define AKV_STG 32768                    // K @ +0 (16KB), V @ +16384 (16KB)
#define AT_SO   (AT_KV + 2*AKV_STG)      // 98304: fp32 [64][132]
#define SO_STRIDE 132
#define AT_RED  (AT_SO + 64*SO_STRIDE*4) // 132096
#define ATT_SMEM (AT_RED + 1024 + 128)

__global__ __launch_bounds__(256, 1) void attn_mma() {
    extern __shared__ char dsmem[];
    const int bh = blockIdx.x;
    const int b = bh / H_;
    const int h = bh % H_;
    const int kvh = h / (H_ / KVH_);
    const int qb = (S_ / 64 - 1) - blockIdx.y;   // heavy blocks first
    const int tid = threadIdx.x;
    const int lane = tid & 31;
    const int wid = tid >> 5;
    const int warp_m = wid >> 1;
    const int warp_n = wid & 1;

    uint32_t db = smem_u32(dsmem);
    uint32_t sbase = (db + 127u) & ~127u;
    float* sO   = (float*)(dsmem + (sbase - db) + AT_SO);
    float* redm = (float*)(dsmem + (sbase - db) + AT_RED);
    float* redl = redm + 128;

    const __half* QhG = g_q16h + (((size_t)b * H_ + h) * S_ + (size_t)qb * 64) * DH_;
    const __half* QlG = g_q16l + (((size_t)b * H_ + h) * S_ + (size_t)qb * 64) * DH_;
    const __half* KB  = g_k16  + ((size_t)b * KVH_ + kvh) * S_ * DH_;
    const __half* VB  = g_v16  + ((size_t)b * KVH_ + kvh) * S_ * DH_;

    #pragma unroll
    for (int i = 0; i < 4; i++) {
        int idx = tid + i * 256;
        int row = idx >> 4, ch = idx & 15;
        uint32_t sw = swz256(row, ch);
        size_t g = (size_t)row * DH_ + ch * 8;
        CP_ASYNC16(sbase + AT_QH + sw, QhG + g);
        CP_ASYNC16(sbase + AT_QL + sw, QlG + g);
    }
    auto load_kv = [&](int buf, int jt) {
        uint32_t sb = sbase + AT_KV + (uint32_t)buf * AKV_STG;
        size_t gb = (size_t)jt * 64 * DH_;
        #pragma unroll
        for (int i = 0; i < 4; i++) {
            int idx = tid + i * 256;
            int row = idx >> 4, ch = idx & 15;
            uint32_t sw = swz256(row, ch);
            size_t g = gb + (size_t)row * DH_ + ch * 8;
            CP_ASYNC16(sb +         sw, KB + g);
            CP_ASYNC16(sb + 16384 + sw, VB + g);
        }
    };
    load_kv(0, 0);
    CP_COMMIT();

    float oacc[16][4];
    #pragma unroll
    for (int nt = 0; nt < 16; nt++)
        #pragma unroll
        for (int j = 0; j < 4; j++) oacc[nt][j] = 0.f;
    float m0 = -1e30f, m1 = -1e30f, l0 = 0.f, l1 = 0.f;

    const int gr  = lane >> 2;
    const int rI0 = warp_m * 16 + gr;
    const int nj = qb + 1;

    for (int jt = 0; jt < nj; jt++) {
        const int buf = jt & 1;
        CP_WAIT(0);
        __syncthreads();
        if (jt + 1 < nj) { load_kv(buf ^ 1, jt + 1); CP_COMMIT(); }

        const uint32_t sQH = sbase + AT_QH, sQL = sbase + AT_QL;
        const uint32_t kb = sbase + AT_KV + (uint32_t)buf * AKV_STG;
        const uint32_t sK = kb, sV = kb + 16384;

        float sacc[4][4];
        #pragma unroll
        for (int nt = 0; nt < 4; nt++)
            #pragma unroll
            for (int j = 0; j < 4; j++) sacc[nt][j] = 0.f;

        #pragma unroll
        for (int kt = 0; kt < 8; kt++) {
            uint32_t qh4[4], ql4[4], kf[2][4];
            int qrow = warp_m * 16 + (lane & 15);
            int qch  = kt * 2 + (lane >> 4);
            ldsm_x4(qh4, sQH + swz256(qrow, qch));
            ldsm_x4(ql4, sQL + swz256(qrow, qch));
            #pragma unroll
            for (int ng = 0; ng < 2; ng++) {
                int krow = warp_n * 32 + ng * 16 + (lane & 7) + (lane >> 4) * 8;
                int kch  = kt * 2 + ((lane >> 3) & 1);
                ldsm_x4(kf[ng], sK + swz256(krow, kch));
            }
            #pragma unroll
            for (int ng = 0; ng < 2; ng++)
                #pragma unroll
                for (int s = 0; s < 2; s++) {
                    float* a = sacc[ng * 2 + s];
                    mma16816h(a, qh4, &kf[ng][s * 2]);
                    mma16816h(a, ql4, &kf[ng][s * 2]);
                }
        }

        #pragma unroll
        for (int nt = 0; nt < 4; nt++)
            #pragma unroll
            for (int j = 0; j < 4; j++) sacc[nt][j] *= SCALING_;
        if (jt == qb) {
            int r0g = qb * 64 + rI0;
            #pragma unroll
            for (int nt = 0; nt < 4; nt++) {
                int c = jt * 64 + warp_n * 32 + nt * 8 + (lane & 3) * 2;
                if (c     > r0g)     sacc[nt][0] = -1e30f;
                if (c + 1 > r0g)     sacc[nt][1] = -1e30f;
                if (c     > r0g + 8) sacc[nt][2] = -1e30f;
                if (c + 1 > r0g + 8) sacc[nt][3] = -1e30f;
            }
        }

        float pm0 = -1e30f, pm1 = -1e30f;
        #pragma unroll
        for (int nt = 0; nt < 4; nt++) {
            pm0 = fmaxf(pm0, fmaxf(sacc[nt][0], sacc[nt][1]));
            pm1 = fmaxf(pm1, fmaxf(sacc[nt][2], sacc[nt][3]));
        }
        pm0 = fmaxf(pm0, __shfl_xor_sync(0xFFFFFFFFu, pm0, 1));
        pm0 = fmaxf(pm0, __shfl_xor_sync(0xFFFFFFFFu, pm0, 2));
        pm1 = fmaxf(pm1, __shfl_xor_sync(0xFFFFFFFFu, pm1, 1));
        pm1 = fmaxf(pm1, __shfl_xor_sync(0xFFFFFFFFu, pm1, 2));
        if ((lane & 3) == 0) {
            redm[warp_n * 64 + rI0]     = pm0;
            redm[warp_n * 64 + rI0 + 8] = pm1;
        }
        __syncthreads();
        float mt0 = fmaxf(redm[rI0],     redm[64 + rI0]);
        float mt1 = fmaxf(redm[rI0 + 8], redm[64 + rI0 + 8]);

        float mn0 = fmaxf(m0, mt0), mn1 = fmaxf(m1, mt1);
        float c0 = __expf(m0 - mn0), c1 = __expf(m1 - mn1);

        float ps0 = 0.f, ps1 = 0.f;
        #pragma unroll
        for (int nt = 0; nt < 4; nt++) {
            sacc[nt][0] = __expf(sacc[nt][0] - mn0);
            sacc[nt][1] = __expf(sacc[nt][1] - mn0);
            sacc[nt][2] = __expf(sacc[nt][2] - mn1);
            sacc[nt][3] = __expf(sacc[nt][3] - mn1);
            ps0 += sacc[nt][0] + sacc[nt][1];
            ps1 += sacc[nt][2] + sacc[nt][3];
        }
        ps0 += __shfl_xor_sync(0xFFFFFFFFu, ps0, 1);
        ps0 += __shfl_xor_sync(0xFFFFFFFFu, ps0, 2);
        ps1 += __shfl_xor_sync(0xFFFFFFFFu, ps1, 1);
        ps1 += __shfl_xor_sync(0xFFFFFFFFu, ps1, 2);
        if ((lane & 3) == 0) {
            redl[warp_n * 64 + rI0]     = ps0;
            redl[warp_n * 64 + rI0 + 8] = ps1;
        }
        __syncthreads();
        l0 = l0 * c0 + redl[rI0]     + redl[64 + rI0];
        l1 = l1 * c1 + redl[rI0 + 8] + redl[64 + rI0 + 8];
        m0 = mn0; m1 = mn1;

        #pragma unroll
        for (int nt = 0; nt < 16; nt++) {
            oacc[nt][0] *= c0; oacc[nt][1] *= c0;
            oacc[nt][2] *= c1; oacc[nt][3] *= c1;
        }

        // P split to exact fp16 pair in registers
        uint32_t pah[2][4], pal[2][4];
        #pragma unroll
        for (int kt = 0; kt < 2; kt++) {
            pah[kt][0] = packsplit_h(sacc[2*kt][0],   sacc[2*kt][1],   pal[kt][0]);
            pah[kt][1] = packsplit_h(sacc[2*kt][2],   sacc[2*kt][3],   pal[kt][1]);
            pah[kt][2] = packsplit_h(sacc[2*kt+1][0], sacc[2*kt+1][1], pal[kt][2]);
            pah[kt][3] = packsplit_h(sacc[2*kt+1][2], sacc[2*kt+1][3], pal[kt][3]);
        }

        #pragma unroll
        for (int ndg = 0; ndg < 8; ndg++) {
            #pragma unroll
            for (int kt = 0; kt < 2; kt++) {
                uint32_t vf[4];
                int vrow = warp_n * 32 + kt * 16 + (lane & 15);
                int vch  = ndg * 2 + (lane >> 4);
                ldsm_x4_t(vf, sV + swz256(vrow, vch));
                #pragma unroll
                for (int hf = 0; hf < 2; hf++) {
                    float* o = oacc[ndg * 2 + hf];
                    mma16816h(o, pah[kt], &vf[hf * 2]);
                    mma16816h(o, pal[kt], &vf[hf * 2]);
                }
            }
        }
    }

    __syncthreads();
    if (warp_n == 0) {
        #pragma unroll
        for (int nt = 0; nt < 16; nt++) {
            int d = nt * 8 + (lane & 3) * 2;
            *(float2*)&sO[(size_t)rI0 * SO_STRIDE + d]       = make_float2(oacc[nt][0], oacc[nt][1]);
            *(float2*)&sO[(size_t)(rI0 + 8) * SO_STRIDE + d] = make_float2(oacc[nt][2], oacc[nt][3]);
        }
    }
    __syncthreads();
    if (warp_n == 1) {
        float inv0 = 1.0f / l0, inv1 = 1.0f / l1;
        size_t row0g = (size_t)b * S_ + qb * 64 + rI0;
        size_t row1g = row0g + 8;
        #pragma unroll
        for (int nt = 0; nt < 16; nt++) {
            int d = nt * 8 + (lane & 3) * 2;
            float2 t0 = *(float2*)&sO[(size_t)rI0 * SO_STRIDE + d];
            float2 t1 = *(float2*)&sO[(size_t)(rI0 + 8) * SO_STRIDE + d];
            size_t o0 = row0g * D_ + h * DH_ + d;
            size_t o1 = row1g * D_ + h * DH_ + d;
            *(uint32_t*)(g_a16 + o0) = pack_half2((t0.x + oacc[nt][0]) * inv0,
                                                  (t0.y + oacc[nt][1]) * inv0);
            *(uint32_t*)(g_a16 + o1) = pack_half2((t1.x + oacc[nt][2]) * inv1,
                                                  (t1.y + oacc[nt][3]) * inv1);
        }
    }
}

// ---------------- launch ----------------
extern "C" void kernel_launch(void* const* d_in, const int* in_sizes, int n_in,
                              void* d_out, int out_size) {
    const float* hidden  = (const float*)d_in[0];
    const float* w_qkv   = (const float*)d_in[1];
    const float* w_out   = (const float*)d_in[2];
    const float* q_scale = (const float*)d_in[3];
    const float* k_scale = (const float*)d_in[4];
    const float* cosc    = (const float*)d_in[5];
    const float* sinc    = (const float*)d_in[6];
    float* out = (float*)d_out;

    float* p_part;
    __half *p_a16, *p_wth, *p_wtl;
    cudaGetSymbolAddress((void**)&p_part, g_part);
    cudaGetSymbolAddress((void**)&p_a16,  g_a16);
    cudaGetSymbolAddress((void**)&p_wth,  g_wth);
    cudaGetSymbolAddress((void**)&p_wtl,  g_wtl);

    cudaFuncSetAttribute(gemm_mma_a16, cudaFuncAttributeMaxDynamicSharedMemorySize, HSMEM_SZ);
    cudaFuncSetAttribute(attn_mma,     cudaFuncAttributeMaxDynamicSharedMemorySize, ATT_SMEM);

    // 1) hidden -> fp16 ; w_qkv -> fp16 hi/lo transpose
    split_f16<<<(MROWS * (size_t)D_) / (256 * 4), 256>>>(hidden, p_a16);
    {
        dim3 g(QKVN / 32, D_ / 32);
        transpose_split_f16<<<g, dim3(32, 8)>>>(w_qkv, p_wth, p_wtl, D_, QKVN);
    }
    // 2) QKV projection (fp16 2-MMA), split-K=2 -> partials
    {
        dim3 g(QKVN / 256, MROWS / 128, 2);
        gemm_mma_a16<<<g, 256, HSMEM_SZ>>>(p_a16, p_wth, p_wtl, p_part, QKVN, D_);
    }
    // 3) fused reduce + RMSNorm + RoPE -> fp16 q(split)/k/v
    norm_rope_kernel<<<B_ * S_, 256>>>(p_part, q_scale, k_scale, cosc, sinc);
    // 4) attention (fp16 2-MMA) -> fp16 output g_a16
    {
        dim3 g(B_ * H_, S_ / 64);
        attn_mma<<<g, 256, ATT_SMEM>>>();
    }
    // 5) w_out -> fp16 hi/lo transpose (reuse weight buffers)
    {
        dim3 g(D_ / 32, D_ / 32);
        transpose_split_f16<<<g, dim3(32, 8)>>>(w_out, p_wth, p_wtl, D_, D_);
    }
    // 6) out-projection (fp16 2-MMA), split-K=2 -> partials ; reduce -> out
    {
        dim3 g(D_ / 256, MROWS / 128, 2);
        gemm_mma_a16<<<g, 256, HSMEM_SZ>>>(p_a16, p_wth, p_wtl, p_part, D_, D_);
    }
    reduce_add<<<(MROWS * (size_t)D_) / (256 * 4), 256>>>(p_part, out, (size_t)MROWS * D_);
}